// round 2
// baseline (speedup 1.0000x reference)
#include <cuda_runtime.h>
#include <math.h>

// Problem constants
#define BB   32
#define TT   256     // pred_len / d_model
#define FF   512     // feature dim (mamba seq len)
#define MMK  4       // time-mark feats
#define NV   508     // variates
#define T2K  512
#define ROWS (BB*FF) // 16384

// ---------------- scratch (device globals; no allocation) ----------------
__device__ float g_x    [ROWS*TT];
__device__ float g_xn   [ROWS*TT];
__device__ float g_xp   [ROWS*T2K];
__device__ float g_xc   [ROWS*T2K];
__device__ float g_xco  [ROWS*T2K];
__device__ float g_delta[ROWS*T2K];
__device__ float g_Bm   [ROWS*TT];
__device__ float g_Cm   [ROWS*TT];
__device__ float g_xres [ROWS*T2K];
__device__ float g_gbuf [ROWS*T2K];
__device__ float g_wk   [3*FF*FF];
__device__ float g_mean [BB*NV];
__device__ float g_std  [BB*NV];
__device__ float g_dec  [ROWS*TT];

// ---------------- activations ----------------
__device__ __forceinline__ float siluf(float x) { return x / (1.f + __expf(-x)); }
__device__ __forceinline__ float softplusf(float x) {
    return fmaxf(x, 0.f) + log1pf(__expf(-fabsf(x)));
}

// ---------------- GEMM: C[M,N] (+)= A[M,K] @ B[K,N] (+bias) (act) -------
// 128x128x8 tile, 256 threads, 8x8 per thread (2x2 of 4x4), float4 smem reads.
// bShift shifts the B column index (zero fill out of range) -> conv taps.
// ACT: 0 none, 1 silu, 2 softplus.  BIASMODE: 0 per-col, 1 per-row, 2 none.
template<int ACT, int BIASMODE, bool ACCUM>
__global__ void __launch_bounds__(256) mk_gemm(
    const float* __restrict__ A, long long sA,
    const float* __restrict__ Bmat, long long sB,
    const float* __restrict__ bias,
    float* __restrict__ C, long long sC,
    int Mrows, int K, int Ncols, int bShift)
{
    A    += (long long)blockIdx.z * sA;
    Bmat += (long long)blockIdx.z * sB;
    C    += (long long)blockIdx.z * sC;

    __shared__ __align__(16) float As[8][128];
    __shared__ __align__(16) float Bs[8][128];

    const int tid = threadIdx.x;
    const int m0  = blockIdx.y * 128;
    const int n0  = blockIdx.x * 128;
    const int tx  = tid & 15;      // col group
    const int ty  = tid >> 4;      // row group

    // A tile load: each thread one float4 (row = tid/2, kcol = (tid&1)*4)
    const int arow = tid >> 1;
    const int acol = (tid & 1) * 4;
    // B tile load: each thread 4 scalars (row = tid/32, col = (tid&31)*4)
    const int brow = tid >> 5;
    const int bcol = (tid & 31) * 4;

    float acc[2][2][4][4];
    #pragma unroll
    for (int p = 0; p < 2; p++)
        #pragma unroll
        for (int q = 0; q < 2; q++)
            #pragma unroll
            for (int i = 0; i < 4; i++)
                #pragma unroll
                for (int j = 0; j < 4; j++) acc[p][q][i][j] = 0.f;

    for (int k0 = 0; k0 < K; k0 += 8) {
        float4 av = *(const float4*)(A + (long long)(m0 + arow) * K + k0 + acol);
        As[acol + 0][arow] = av.x;
        As[acol + 1][arow] = av.y;
        As[acol + 2][arow] = av.z;
        As[acol + 3][arow] = av.w;
        #pragma unroll
        for (int j = 0; j < 4; j++) {
            int n = n0 + bcol + j + bShift;
            float v = 0.f;
            if (n >= 0 && n < Ncols)
                v = Bmat[(long long)(k0 + brow) * Ncols + n];
            Bs[brow][bcol + j] = v;
        }
        __syncthreads();

        #pragma unroll
        for (int kk = 0; kk < 8; kk++) {
            float a0[4], a1[4], b0[4], b1[4];
            *(float4*)a0 = *(const float4*)&As[kk][ty * 4];
            *(float4*)a1 = *(const float4*)&As[kk][64 + ty * 4];
            *(float4*)b0 = *(const float4*)&Bs[kk][tx * 4];
            *(float4*)b1 = *(const float4*)&Bs[kk][64 + tx * 4];
            #pragma unroll
            for (int i = 0; i < 4; i++)
                #pragma unroll
                for (int j = 0; j < 4; j++) {
                    acc[0][0][i][j] += a0[i] * b0[j];
                    acc[0][1][i][j] += a0[i] * b1[j];
                    acc[1][0][i][j] += a1[i] * b0[j];
                    acc[1][1][i][j] += a1[i] * b1[j];
                }
        }
        __syncthreads();
    }

    #pragma unroll
    for (int p = 0; p < 2; p++) {
        #pragma unroll
        for (int i = 0; i < 4; i++) {
            int m = m0 + p * 64 + ty * 4 + i;
            #pragma unroll
            for (int q = 0; q < 2; q++) {
                int nbase = n0 + q * 64 + tx * 4;
                float* crow = C + (long long)m * Ncols + nbase;
                #pragma unroll
                for (int j = 0; j < 4; j++) {
                    float c = acc[p][q][i][j];
                    if (ACCUM) c += crow[j];
                    if (BIASMODE == 0) c += bias[nbase + j];
                    if (BIASMODE == 1) c += bias[m];
                    if (ACT == 1) c = siluf(c);
                    if (ACT == 2) c = softplusf(c);
                    crow[j] = c;
                }
            }
        }
    }
}

// ---------------- input normalization + transpose to [B, F, T] ----------
__global__ void mk_norminput(const float* __restrict__ xe, const float* __restrict__ xm,
                             float* __restrict__ x, float* __restrict__ mean,
                             float* __restrict__ stdv)
{
    int idx = blockIdx.x * 256 + threadIdx.x;
    if (idx >= BB * FF) return;
    int f = idx % FF, b = idx / FF;
    float* xr = x + (long long)idx * TT;
    if (f < NV) {
        const float* src = xe + (long long)b * TT * NV + f;
        float s = 0.f, s2 = 0.f;
        for (int t = 0; t < TT; t++) {
            float v = src[(long long)t * NV];
            s += v; s2 += v * v;
        }
        float mu  = s / (float)TT;
        float var = s2 / (float)TT - mu * mu;
        float sd  = sqrtf(var + 1e-5f);
        mean[b * NV + f] = mu;
        stdv[b * NV + f] = sd;
        float inv = 1.f / sd;
        for (int t = 0; t < TT; t++)
            xr[t] = (src[(long long)t * NV] - mu) * inv;
    } else {
        const float* src = xm + (long long)b * TT * MMK + (f - NV);
        for (int t = 0; t < TT; t++)
            xr[t] = src[(long long)t * MMK];
    }
}

// ---------------- rmsnorm over last dim (T=256), one block per row ------
__global__ void mk_rmsnorm(const float* __restrict__ x, const float* __restrict__ w,
                           float* __restrict__ out)
{
    int r = blockIdx.x, t = threadIdx.x;
    __shared__ float red[256];
    float v = x[(long long)r * TT + t];
    red[t] = v * v;
    __syncthreads();
    for (int s = 128; s > 0; s >>= 1) {
        if (t < s) red[t] += red[t + s];
        __syncthreads();
    }
    float scale = rsqrtf(red[0] / (float)TT + 1e-5f);
    out[(long long)r * TT + t] = v * scale * w[t];
}

// ---------------- conv weight tap transpose: W[o][i][k] -> wk[k][o][i] ---
__global__ void mk_convw(const float* __restrict__ W, float* __restrict__ wk)
{
    int idx = blockIdx.x * 256 + threadIdx.x;
    if (idx >= FF * FF * 3) return;
    int k = idx % 3;
    int ii = (idx / 3) % FF;
    int o  = idx / (3 * FF);
    wk[(long long)k * FF * FF + (long long)o * FF + ii] = W[idx];
}

// ---------------- s6 combine: cb = <C,B>; g = silu(delta*x*cb)*xres -----
__global__ void mk_combine(const float* __restrict__ delta, const float* __restrict__ xco,
                           const float* __restrict__ Bm, const float* __restrict__ Cm,
                           const float* __restrict__ xres, float* __restrict__ g)
{
    int r = blockIdx.x, t = threadIdx.x;
    __shared__ float red[256];
    long long rb = (long long)r * TT;
    red[t] = Cm[rb + t] * Bm[rb + t];
    __syncthreads();
    for (int s = 128; s > 0; s >>= 1) {
        if (t < s) red[t] += red[t + s];
        __syncthreads();
    }
    float cb = red[0];
    long long r2 = (long long)r * T2K;
    for (int c = t; c < T2K; c += 256) {
        float xssm = delta[r2 + c] * xco[r2 + c] * cb;
        g[r2 + c] = siluf(xssm) * xres[r2 + c];
    }
}

// ---------------- output: de-normalize + transpose back -----------------
__global__ void mk_output(const float* __restrict__ dec, const float* __restrict__ mean,
                          const float* __restrict__ stdv, float* __restrict__ out)
{
    int idx = blockIdx.x * 256 + threadIdx.x;
    if (idx >= BB * TT * NV) return;
    int n = idx % NV;
    int t = (idx / NV) % TT;
    int b = idx / (NV * TT);
    out[idx] = dec[((long long)b * FF + n) * TT + t] * stdv[b * NV + n] + mean[b * NV + n];
}

// ---------------- host-side launch helpers ------------------------------
template<int ACT, int BIASMODE, bool ACCUM>
static void launch_gemm(const float* A, long long sA, const float* Bmat, long long sB,
                        const float* bias, float* C, long long sC,
                        int M, int K, int N, int shift, int batches)
{
    dim3 grid(N / 128, M / 128, batches);
    mk_gemm<ACT, BIASMODE, ACCUM><<<grid, 256>>>(A, sA, Bmat, sB, bias, C, sC, M, K, N, shift);
}

extern "C" void kernel_launch(void* const* d_in, const int* in_sizes, int n_in,
                              void* d_out, int out_size)
{
    const float* x_enc     = (const float*)d_in[0];
    const float* x_mark    = (const float*)d_in[1];
    const float* norm_w    = (const float*)d_in[4];
    const float* inp_W     = (const float*)d_in[5];
    const float* inp_b     = (const float*)d_in[6];
    const float* conv_W    = (const float*)d_in[7];
    const float* conv_b    = (const float*)d_in[8];
    const float* convlin_W = (const float*)d_in[9];
    const float* convlin_b = (const float*)d_in[10];
    const float* fc1_W     = (const float*)d_in[11];
    const float* fc1_b     = (const float*)d_in[12];
    const float* fc2_W     = (const float*)d_in[13];
    const float* fc2_b     = (const float*)d_in[14];
    const float* fc3_W     = (const float*)d_in[15];
    const float* fc3_b     = (const float*)d_in[16];
    const float* D_W       = (const float*)d_in[17];
    const float* D_b       = (const float*)d_in[18];
    const float* out_W     = (const float*)d_in[19];
    const float* out_b     = (const float*)d_in[20];
    const float* proj_W    = (const float*)d_in[21];
    const float* proj_b    = (const float*)d_in[22];

    float *px, *pxn, *pxp, *pxc, *pxco, *pdelta, *pBm, *pCm, *pxres, *pg, *pwk, *pmean, *pstd, *pdec;
    cudaGetSymbolAddress((void**)&px,    g_x);
    cudaGetSymbolAddress((void**)&pxn,   g_xn);
    cudaGetSymbolAddress((void**)&pxp,   g_xp);
    cudaGetSymbolAddress((void**)&pxc,   g_xc);
    cudaGetSymbolAddress((void**)&pxco,  g_xco);
    cudaGetSymbolAddress((void**)&pdelta,g_delta);
    cudaGetSymbolAddress((void**)&pBm,   g_Bm);
    cudaGetSymbolAddress((void**)&pCm,   g_Cm);
    cudaGetSymbolAddress((void**)&pxres, g_xres);
    cudaGetSymbolAddress((void**)&pg,    g_gbuf);
    cudaGetSymbolAddress((void**)&pwk,   g_wk);
    cudaGetSymbolAddress((void**)&pmean, g_mean);
    cudaGetSymbolAddress((void**)&pstd,  g_std);
    cudaGetSymbolAddress((void**)&pdec,  g_dec);

    const long long sFT2 = (long long)FF * T2K;   // per-batch stride for conv tensors

    mk_norminput<<<(BB * FF + 255) / 256, 256>>>(x_enc, x_mark, px, pmean, pstd);

    for (int i = 0; i < 3; i++) {
        // xn = rmsnorm(x) * w
        mk_rmsnorm<<<ROWS, 256>>>(px, norm_w + i * TT, pxn);
        // xp = xn @ inp_W + inp_b     [ROWS, 512]
        launch_gemm<0, 0, false>(pxn, 0, inp_W + (long long)i * TT * T2K, 0,
                                 inp_b + i * T2K, pxp, 0, ROWS, TT, T2K, 0, 1);
        // conv taps -> contiguous [F,F] matrices
        mk_convw<<<(FF * FF * 3 + 255) / 256, 256>>>(conv_W + (long long)i * FF * FF * 3, pwk);
        // xc = silu(conv1d(xp) + conv_b): 3 shifted batched GEMMs over channels
        launch_gemm<0, 2, false>(pwk + 0LL * FF * FF, 0, pxp, sFT2, nullptr,
                                 pxc, sFT2, FF, FF, T2K, -1, BB);
        launch_gemm<0, 2, true >(pwk + 1LL * FF * FF, 0, pxp, sFT2, nullptr,
                                 pxc, sFT2, FF, FF, T2K,  0, BB);
        launch_gemm<1, 1, true >(pwk + 2LL * FF * FF, 0, pxp, sFT2, conv_b + i * FF,
                                 pxc, sFT2, FF, FF, T2K, +1, BB);
        // xco = xc @ convlin_W + b
        launch_gemm<0, 0, false>(pxc, 0, convlin_W + (long long)i * T2K * T2K, 0,
                                 convlin_b + i * T2K, pxco, 0, ROWS, T2K, T2K, 0, 1);
        // delta = softplus(xco @ fc1_W + b)
        launch_gemm<2, 0, false>(pxco, 0, fc1_W + (long long)i * T2K * T2K, 0,
                                 fc1_b + i * T2K, pdelta, 0, ROWS, T2K, T2K, 0, 1);
        // Bmat / Cmat
        launch_gemm<0, 0, false>(pxco, 0, fc2_W + (long long)i * T2K * TT, 0,
                                 fc2_b + i * TT, pBm, 0, ROWS, T2K, TT, 0, 1);
        launch_gemm<0, 0, false>(pxco, 0, fc3_W + (long long)i * T2K * TT, 0,
                                 fc3_b + i * TT, pCm, 0, ROWS, T2K, TT, 0, 1);
        // xres = silu(xn @ D_W + D_b)
        launch_gemm<1, 0, false>(pxn, 0, D_W + (long long)i * TT * T2K, 0,
                                 D_b + i * T2K, pxres, 0, ROWS, TT, T2K, 0, 1);
        // g = silu(delta * xco * cb) * xres
        mk_combine<<<ROWS, 256>>>(pdelta, pxco, pBm, pCm, pxres, pg);
        // x = g @ out_W + out_b
        launch_gemm<0, 0, false>(pg, 0, out_W + (long long)i * T2K * TT, 0,
                                 out_b + i * TT, px, 0, ROWS, T2K, TT, 0, 1);
    }

    // dec = x @ proj_W + proj_b   [ROWS, 256]
    launch_gemm<0, 0, false>(px, 0, proj_W, 0, proj_b, pdec, 0, ROWS, TT, TT, 0, 1);
    // out[b,t,n] = dec[b,n,t] * std + mean
    mk_output<<<(BB * TT * NV + 255) / 256, 256>>>(pdec, pmean, pstd, (float*)d_out);
}

// round 6
// speedup vs baseline: 2.1353x; 2.1353x over previous
#include <cuda_runtime.h>
#include <cuda_bf16.h>
#include <math.h>
#include <stdint.h>

#define BB 32
#define TT 256
#define FF 512
#define MMK 4
#define NV 508
#define T2 512
#define ROWS (BB*FF)
typedef __nv_bfloat16 bf;
typedef long long ll;

// ---------------- scratch ----------------
__device__ float g_x32[ROWS*TT], g_xp32[ROWS*T2], g_xco32[ROWS*T2], g_dl32[ROWS*T2];
__device__ float g_Bm[ROWS*TT], g_Cm[ROWS*TT], g_xr32[ROWS*T2], g_dec[ROWS*TT];
__device__ float g_mean[BB*NV], g_std[BB*NV];
__device__ bf g_xnh[ROWS*TT], g_xnl[ROWS*TT];
__device__ bf g_xpTh[ROWS*T2], g_xpTl[ROWS*T2];
__device__ bf g_xch[ROWS*T2], g_xcl[ROWS*T2];
__device__ bf g_xcoh[ROWS*T2], g_xcol[ROWS*T2];
__device__ bf g_gh[ROWS*T2], g_gl[ROWS*T2];
__device__ bf g_xh[ROWS*TT], g_xl[ROWS*TT];
__device__ bf w_inph[3*512*256], w_inpl[3*512*256];
__device__ bf w_cvh[3*3*512*512], w_cvl_[3*3*512*512];
__device__ bf w_clh[3*512*512], w_cll[3*512*512];
__device__ bf w_f1h[3*512*512], w_f1l[3*512*512];
__device__ bf w_f2h[3*256*512], w_f2l[3*256*512];
__device__ bf w_f3h[3*256*512], w_f3l[3*256*512];
__device__ bf w_Dh[3*512*256], w_Dl[3*512*256];
__device__ bf w_oh[3*256*512], w_ol[3*256*512];
__device__ bf w_ph[256*256], w_pl[256*256];

// ---------------- helpers ----------------
__device__ __forceinline__ float siluf(float x){ return x/(1.f+__expf(-x)); }
__device__ __forceinline__ float softplusf(float x){ return fmaxf(x,0.f)+log1pf(__expf(-fabsf(x))); }
__device__ __forceinline__ void splitbf(float v, bf& h, bf& l){
    h = __float2bfloat16(v); l = __float2bfloat16(v - __bfloat162float(h));
}
__device__ __forceinline__ void st_split2(bf* Ch, bf* Cl, ll off, float v0, float v1){
    bf h0,l0,h1,l1; splitbf(v0,h0,l0); splitbf(v1,h1,l1);
    *(__nv_bfloat162*)(Ch+off) = __halves2bfloat162(h0,h1);
    *(__nv_bfloat162*)(Cl+off) = __halves2bfloat162(l0,l1);
}
__device__ __forceinline__ uint32_t s2u(const void* p){
    uint32_t a; asm("{.reg .u64 t; cvta.to.shared.u64 t,%1; cvt.u32.u64 %0,t;}":"=r"(a):"l"(p)); return a;
}
__device__ __forceinline__ void cp16(uint32_t s, const void* g, int sz){
    asm volatile("cp.async.cg.shared.global [%0], [%1], 16, %2;"::"r"(s),"l"(g),"r"(sz):"memory");
}
__device__ __forceinline__ void ldsm4(uint32_t* r, uint32_t a){
    asm volatile("ldmatrix.sync.aligned.m8n8.x4.shared.b16 {%0,%1,%2,%3}, [%4];"
        :"=r"(r[0]),"=r"(r[1]),"=r"(r[2]),"=r"(r[3]):"r"(a));
}
__device__ __forceinline__ void mma16816(float* d, const uint32_t* a, const uint32_t* b){
    asm volatile("mma.sync.aligned.m16n8k16.row.col.f32.bf16.bf16.f32 "
        "{%0,%1,%2,%3}, {%4,%5,%6,%7}, {%8,%9}, {%0,%1,%2,%3};"
        : "+f"(d[0]),"+f"(d[1]),"+f"(d[2]),"+f"(d[3])
        : "r"(a[0]),"r"(a[1]),"r"(a[2]),"r"(a[3]), "r"(b[0]),"r"(b[1]));
}

// smem: per stage: Ah[128][40] Al Bh Bl (bf16, 80B padded rows). stage=40960B, 2 stages.
#define ST_AL 10240
#define ST_BH 20480
#define ST_BL 30720
#define ST_SZ 40960
#define SMEMSZ (2*ST_SZ)

// ---------------- HMMA GEMM: D[128,128] = sum_k split(A)@split(B)^T ----------------
// A [M][K] row-major hi/lo, B [N][K] row-major hi/lo (so D = A@B^T).
// ACT: 0 none, 1 silu, 2 softplus.  OUTM: bit0 fp32, bit1 hi/lo.  CONV: 3-tap batched.
template<int ACT, int OUTM, int CONV>
__global__ void __launch_bounds__(256) tc_gemm(
    const bf* __restrict__ Ah, const bf* __restrict__ Al,
    const bf* __restrict__ Bh, const bf* __restrict__ Bl,
    const float* __restrict__ bias,
    float* __restrict__ C32, bf* __restrict__ Ch, bf* __restrict__ Cl,
    int Kd, int Nc)
{
    extern __shared__ __align__(128) char sm[];
    uint32_t sb = s2u(sm);
    const int tid = threadIdx.x, lane = tid & 31, wid = tid >> 5;
    const int n0 = blockIdx.x*128, m0 = blockIdx.y*128, z = blockIdx.z;
    const int wm = (wid >> 1) * 32, wn = (wid & 1) * 64;
    const int NC = CONV ? 48 : (Kd >> 5);

    float acc[2][8][4];
    #pragma unroll
    for (int a = 0; a < 2; a++)
        #pragma unroll
        for (int b = 0; b < 8; b++)
            #pragma unroll
            for (int c = 0; c < 4; c++) acc[a][b][c] = 0.f;

    auto DO_LOAD = [&](int c){
        int tap = CONV ? (c >> 4) : 0;
        int k0  = (CONV ? (c & 15) : c) << 5;
        uint32_t st = sb + (c & 1) * ST_SZ;
        const bf* A2h = Ah + (CONV ? (ll)tap * 262144 : 0);
        const bf* A2l = Al + (CONV ? (ll)tap * 262144 : 0);
        #pragma unroll
        for (int rep = 0; rep < 2; rep++){
            int idx = rep * 256 + tid;          // 0..511
            int row = idx >> 2, ck = idx & 3;
            uint32_t so = row * 80 + ck * 16;
            ll aoff = (ll)(m0 + row) * Kd + k0 + ck * 8;
            cp16(st + so,         A2h + aoff, 16);
            cp16(st + ST_AL + so, A2l + aoff, 16);
            if (!CONV){
                ll boff = (ll)(n0 + row) * Kd + k0 + ck * 8;
                cp16(st + ST_BH + so, Bh + boff, 16);
                cp16(st + ST_BL + so, Bl + boff, 16);
            } else {
                int lsrc = n0 + row + tap - 1;
                int ok = ((unsigned)lsrc < 512u) ? 16 : 0;
                ll boff = (ll)(z * 512 + lsrc) * 512 + k0 + ck * 8;
                cp16(st + ST_BH + so, Bh + boff, ok);
                cp16(st + ST_BL + so, Bl + boff, ok);
            }
        }
        asm volatile("cp.async.commit_group;":::"memory");
    };

    // ldmatrix lane patterns
    const int arow = (lane & 7) + ((lane >> 3) & 1) * 8;   // m-half on bit3
    const int acolq = ((lane >> 4) & 1) * 16;              // k-half on bit4
    const int brow = (lane & 7) + ((lane >> 4) & 1) * 8;   // n-half on bit4
    const int bcolq = ((lane >> 3) & 1) * 16;              // k-half on bit3

    DO_LOAD(0);
    for (int c = 0; c < NC; c++){
        if (c + 1 < NC){ DO_LOAD(c + 1); asm volatile("cp.async.wait_group 1;":::"memory"); }
        else           {                 asm volatile("cp.async.wait_group 0;":::"memory"); }
        __syncthreads();
        uint32_t st = sb + (c & 1) * ST_SZ;
        #pragma unroll
        for (int ks = 0; ks < 2; ks++){
            uint32_t ah[2][4], al_[2][4], bh[4][4], bl[4][4];
            #pragma unroll
            for (int mt = 0; mt < 2; mt++){
                uint32_t ad = st + (wm + mt*16 + arow) * 80 + ks*32 + acolq;
                ldsm4(ah[mt], ad);
                ldsm4(al_[mt], ad + ST_AL);
            }
            #pragma unroll
            for (int np = 0; np < 4; np++){
                uint32_t bd = st + ST_BH + (wn + np*16 + brow) * 80 + ks*32 + bcolq;
                ldsm4(bh[np], bd);
                ldsm4(bl[np], bd + (ST_BL - ST_BH));
            }
            #pragma unroll
            for (int mt = 0; mt < 2; mt++)
                #pragma unroll
                for (int nt = 0; nt < 8; nt++){
                    const uint32_t* ph = &bh[nt >> 1][(nt & 1) * 2];
                    const uint32_t* pl = &bl[nt >> 1][(nt & 1) * 2];
                    mma16816(acc[mt][nt], ah[mt],  ph);
                    mma16816(acc[mt][nt], al_[mt], ph);
                    mma16816(acc[mt][nt], ah[mt],  pl);
                }
        }
        __syncthreads();
    }

    // epilogue
    const int g = lane >> 2, qp = (lane & 3) * 2;
    #pragma unroll
    for (int mt = 0; mt < 2; mt++){
        #pragma unroll
        for (int half = 0; half < 2; half++){
            int m = m0 + wm + mt*16 + g + half*8;
            ll crow = CONV ? ((ll)z * 512 + m) : (ll)m;
            float bv = CONV ? bias[m] : 0.f;
            #pragma unroll
            for (int nt = 0; nt < 8; nt++){
                int n = n0 + wn + nt*8 + qp;
                float v0 = acc[mt][nt][half*2 + 0];
                float v1 = acc[mt][nt][half*2 + 1];
                if (CONV){ v0 += bv; v1 += bv; } else { v0 += bias[n]; v1 += bias[n+1]; }
                if (ACT == 1){ v0 = siluf(v0); v1 = siluf(v1); }
                if (ACT == 2){ v0 = softplusf(v0); v1 = softplusf(v1); }
                ll o = crow * Nc + n;
                if (OUTM & 1){ C32[o] = v0; C32[o+1] = v1; }
                if (OUTM & 2){ st_split2(Ch, Cl, o, v0, v1); }
            }
        }
    }
}

// ---------------- aux kernels ----------------
__global__ void k_norminput(const float* __restrict__ xe, const float* __restrict__ xm,
                            float* __restrict__ x, float* __restrict__ mean, float* __restrict__ stdv)
{
    int idx = blockIdx.x*256 + threadIdx.x;
    if (idx >= BB*FF) return;
    int f = idx % FF, b = idx / FF;
    float* xr = x + (ll)idx * TT;
    if (f < NV){
        const float* src = xe + (ll)b*TT*NV + f;
        float s = 0.f, s2 = 0.f;
        for (int t = 0; t < TT; t++){ float v = src[(ll)t*NV]; s += v; s2 += v*v; }
        float mu = s/(float)TT, var = s2/(float)TT - mu*mu, sd = sqrtf(var + 1e-5f);
        mean[b*NV+f] = mu; stdv[b*NV+f] = sd;
        float inv = 1.f/sd;
        for (int t = 0; t < TT; t++) xr[t] = (src[(ll)t*NV] - mu)*inv;
    } else {
        const float* src = xm + (ll)b*TT*MMK + (f - NV);
        for (int t = 0; t < TT; t++) xr[t] = src[(ll)t*MMK];
    }
}

__global__ void k_rms(const float* __restrict__ x, const float* __restrict__ w,
                      bf* __restrict__ oh, bf* __restrict__ ol)
{
    int r = blockIdx.x, t = threadIdx.x;
    __shared__ float red[256];
    float v = x[(ll)r*TT + t];
    red[t] = v*v; __syncthreads();
    for (int s = 128; s > 0; s >>= 1){ if (t < s) red[t] += red[t+s]; __syncthreads(); }
    float sc = rsqrtf(red[0]/(float)TT + 1e-5f);
    bf h,l; splitbf(v*sc*w[t], h, l);
    oh[(ll)r*TT+t] = h; ol[(ll)r*TT+t] = l;
}

__global__ void k_trans(const float* __restrict__ xp, bf* __restrict__ th, bf* __restrict__ tl)
{
    __shared__ float tsm[32][33];
    int b = blockIdx.z, l0 = blockIdx.x*32, f0 = blockIdx.y*32;
    int tx = threadIdx.x, ty = threadIdx.y;
    for (int i = ty; i < 32; i += 8)
        tsm[i][tx] = xp[((ll)(b*512 + f0 + i))*512 + l0 + tx];
    __syncthreads();
    for (int i = ty; i < 32; i += 8){
        bf h,l; splitbf(tsm[tx][i], h, l);
        ll o = ((ll)(b*512 + l0 + i))*512 + f0 + tx;
        th[o] = h; tl[o] = l;
    }
}

__global__ void k_combine(const float* __restrict__ dl, const float* __restrict__ xco,
                          const float* __restrict__ Bm, const float* __restrict__ Cm,
                          const float* __restrict__ xr, bf* __restrict__ gh, bf* __restrict__ gl)
{
    int r = blockIdx.x, t = threadIdx.x;
    __shared__ float red[256];
    ll rb = (ll)r*TT;
    red[t] = Cm[rb+t]*Bm[rb+t]; __syncthreads();
    for (int s = 128; s > 0; s >>= 1){ if (t < s) red[t] += red[t+s]; __syncthreads(); }
    float cb = red[0];
    ll r2 = (ll)r*T2;
    for (int c = t; c < T2; c += 256){
        float v = siluf(dl[r2+c]*xco[r2+c]*cb) * xr[r2+c];
        bf h,l; splitbf(v, h, l);
        gh[r2+c] = h; gl[r2+c] = l;
    }
}

__global__ void k_wprep(const float* __restrict__ W, bf* __restrict__ dh, bf* __restrict__ dl, int K, int N)
{
    int i = blockIdx.x*256 + threadIdx.x;
    if (i >= K*N) return;
    int k = i / N, n = i % N;
    ll zo = (ll)blockIdx.z * K * N;
    bf h,l; splitbf(W[zo + i], h, l);
    dh[zo + (ll)n*K + k] = h; dl[zo + (ll)n*K + k] = l;
}

__global__ void k_cprep(const float* __restrict__ W, bf* __restrict__ dh, bf* __restrict__ dl)
{
    int j = blockIdx.x*256 + threadIdx.x;
    if (j >= 786432) return;
    ll zo = (ll)blockIdx.z * 786432;
    int tap = j % 3, ii = (j/3) % 512, o = j / 1536;
    bf h,l; splitbf(W[zo + j], h, l);
    ll d = zo + (ll)tap*262144 + (ll)o*512 + ii;
    dh[d] = h; dl[d] = l;
}

__global__ void k_out(const float* __restrict__ dec, const float* __restrict__ mean,
                      const float* __restrict__ stdv, float* __restrict__ out)
{
    int idx = blockIdx.x*256 + threadIdx.x;
    if (idx >= BB*TT*NV) return;
    int n = idx % NV, t = (idx/NV) % TT, b = idx/(NV*TT);
    out[idx] = dec[((ll)b*FF + n)*TT + t] * stdv[b*NV+n] + mean[b*NV+n];
}

// ---------------- launcher ----------------
#define GA(p, s) cudaGetSymbolAddress((void**)&p, s)

template<int ACT, int OUTM, int CONV>
static void lg(dim3 grid, const bf* Ah, const bf* Al, const bf* Bh, const bf* Bl,
               const float* bias, float* C32, bf* Ch, bf* Cl, int Kd, int Nc)
{
    cudaFuncSetAttribute(tc_gemm<ACT,OUTM,CONV>, cudaFuncAttributeMaxDynamicSharedMemorySize, SMEMSZ);
    tc_gemm<ACT,OUTM,CONV><<<grid, 256, SMEMSZ>>>(Ah, Al, Bh, Bl, bias, C32, Ch, Cl, Kd, Nc);
}

extern "C" void kernel_launch(void* const* d_in, const int* in_sizes, int n_in,
                              void* d_out, int out_size)
{
    const float* x_enc  = (const float*)d_in[0];
    const float* x_mark = (const float*)d_in[1];
    const float* norm_w = (const float*)d_in[4];
    const float* inp_W  = (const float*)d_in[5];
    const float* inp_b  = (const float*)d_in[6];
    const float* conv_W = (const float*)d_in[7];
    const float* conv_b = (const float*)d_in[8];
    const float* cvl_W  = (const float*)d_in[9];
    const float* cvl_b  = (const float*)d_in[10];
    const float* fc1_W  = (const float*)d_in[11];
    const float* fc1_b  = (const float*)d_in[12];
    const float* fc2_W  = (const float*)d_in[13];
    const float* fc2_b  = (const float*)d_in[14];
    const float* fc3_W  = (const float*)d_in[15];
    const float* fc3_b  = (const float*)d_in[16];
    const float* D_W    = (const float*)d_in[17];
    const float* D_b    = (const float*)d_in[18];
    const float* out_W  = (const float*)d_in[19];
    const float* out_b  = (const float*)d_in[20];
    const float* proj_W = (const float*)d_in[21];
    const float* proj_b = (const float*)d_in[22];

    float *x32,*xp32,*xco32,*dl32,*Bm,*Cm,*xr32,*dec,*mean,*stdv;
    GA(x32,g_x32); GA(xp32,g_xp32); GA(xco32,g_xco32); GA(dl32,g_dl32);
    GA(Bm,g_Bm); GA(Cm,g_Cm); GA(xr32,g_xr32); GA(dec,g_dec); GA(mean,g_mean); GA(stdv,g_std);
    bf *xnh,*xnl,*xpTh,*xpTl,*xch,*xcl,*xcoh,*xcol,*gh,*gl,*xh,*xl;
    GA(xnh,g_xnh); GA(xnl,g_xnl); GA(xpTh,g_xpTh); GA(xpTl,g_xpTl);
    GA(xch,g_xch); GA(xcl,g_xcl); GA(xcoh,g_xcoh); GA(xcol,g_xcol);
    GA(gh,g_gh); GA(gl,g_gl); GA(xh,g_xh); GA(xl,g_xl);
    bf *inph,*inpl,*cvh,*cvl,*clh,*cll,*f1h,*f1l,*f2h,*f2l,*f3h,*f3l,*Dh,*Dl,*oh,*ol,*ph_,*pl_;
    GA(inph,w_inph); GA(inpl,w_inpl); GA(cvh,w_cvh); GA(cvl,w_cvl_);
    GA(clh,w_clh); GA(cll,w_cll); GA(f1h,w_f1h); GA(f1l,w_f1l);
    GA(f2h,w_f2h); GA(f2l,w_f2l); GA(f3h,w_f3h); GA(f3l,w_f3l);
    GA(Dh,w_Dh); GA(Dl,w_Dl); GA(oh,w_oh); GA(ol,w_ol); GA(ph_,w_ph); GA(pl_,w_pl);

    // weight prep (transpose to [N,K] + hi/lo split)
    k_wprep<<<dim3((256*512+255)/256,1,3),256>>>(inp_W, inph, inpl, 256, 512);
    k_wprep<<<dim3((512*512+255)/256,1,3),256>>>(cvl_W, clh, cll, 512, 512);
    k_wprep<<<dim3((512*512+255)/256,1,3),256>>>(fc1_W, f1h, f1l, 512, 512);
    k_wprep<<<dim3((512*256+255)/256,1,3),256>>>(fc2_W, f2h, f2l, 512, 256);
    k_wprep<<<dim3((512*256+255)/256,1,3),256>>>(fc3_W, f3h, f3l, 512, 256);
    k_wprep<<<dim3((256*512+255)/256,1,3),256>>>(D_W, Dh, Dl, 256, 512);
    k_wprep<<<dim3((512*256+255)/256,1,3),256>>>(out_W, oh, ol, 512, 256);
    k_wprep<<<dim3((256*256+255)/256,1,1),256>>>(proj_W, ph_, pl_, 256, 256);
    k_cprep<<<dim3((786432+255)/256,1,3),256>>>(conv_W, cvh, cvl);

    k_norminput<<<(BB*FF+255)/256,256>>>(x_enc, x_mark, x32, mean, stdv);

    for (int i = 0; i < 3; i++){
        ll w2 = (ll)i*512*512, w1 = (ll)i*256*512, wc = (ll)i*786432;
        k_rms<<<ROWS,256>>>(x32, norm_w + i*TT, xnh, xnl);
        // xp = xn @ inp_W + b                      [16384 x 512], K=256
        lg<0,1,0>(dim3(4,128), xnh, xnl, inph + w1, inpl + w1, inp_b + i*T2,
                  xp32, nullptr, nullptr, 256, 512);
        // xpT (L-major) hi/lo
        k_trans<<<dim3(16,16,BB),dim3(32,8)>>>(xp32, xpTh, xpTl);
        // xc = silu(conv1d(xp) + conv_b)            batched [512 x 512], 3 taps, K=512
        lg<1,2,1>(dim3(4,4,BB), cvh + wc, cvl + wc, xpTh, xpTl, conv_b + i*FF,
                  nullptr, xch, xcl, 512, 512);
        // xco = xc @ convlin_W + b  (fp32 + hi/lo)
        lg<0,3,0>(dim3(4,128), xch, xcl, clh + w2, cll + w2, cvl_b + i*T2,
                  xco32, xcoh, xcol, 512, 512);
        // delta = softplus(xco @ fc1_W + b)
        lg<2,1,0>(dim3(4,128), xcoh, xcol, f1h + w2, f1l + w2, fc1_b + i*T2,
                  dl32, nullptr, nullptr, 512, 512);
        // Bmat / Cmat
        lg<0,1,0>(dim3(2,128), xcoh, xcol, f2h + w2, f2l + w2, fc2_b + i*TT,
                  Bm, nullptr, nullptr, 512, 256);
        lg<0,1,0>(dim3(2,128), xcoh, xcol, f3h + w2, f3l + w2, fc3_b + i*TT,
                  Cm, nullptr, nullptr, 512, 256);
        // xres = silu(xn @ D_W + b)
        lg<1,1,0>(dim3(4,128), xnh, xnl, Dh + w1, Dl + w1, D_b + i*T2,
                  xr32, nullptr, nullptr, 256, 512);
        // g = silu(delta*xco*cb)*xres  -> hi/lo
        k_combine<<<ROWS,256>>>(dl32, xco32, Bm, Cm, xr32, gh, gl);
        // x = g @ out_W + b  (fp32 + hi/lo)
        lg<0,3,0>(dim3(2,128), gh, gl, oh + w2, ol + w2, out_b + i*TT,
                  x32, xh, xl, 512, 256);
    }
    // dec = x @ proj_W + b
    lg<0,1,0>(dim3(2,128), xh, xl, ph_, pl_, proj_b, dec, nullptr, nullptr, 256, 256);
    k_out<<<(BB*TT*NV+255)/256,256>>>(dec, mean, stdv, (float*)d_out);
}

// round 8
// speedup vs baseline: 2.7242x; 1.2758x over previous
#include <cuda_runtime.h>
#include <cuda_bf16.h>
#include <math.h>
#include <stdint.h>

#define BB 32
#define TT 256
#define FF 512
#define MMK 4
#define NV 508
#define T2 512
#define ROWS (BB*FF)
typedef __nv_bfloat16 bf;
typedef long long ll;

// ---------------- scratch ----------------
__device__ float g_x32[ROWS*TT], g_xp32[ROWS*T2], g_xco32[ROWS*T2], g_dl32[ROWS*T2];
__device__ float g_Bm[ROWS*TT], g_Cm[ROWS*TT], g_xr32[ROWS*T2], g_dec[ROWS*TT];
__device__ float g_mean[BB*NV], g_std[BB*NV];
__device__ bf g_xnh[ROWS*TT], g_xnl[ROWS*TT];
__device__ bf g_xpTh[ROWS*T2], g_xpTl[ROWS*T2];
__device__ bf g_xch[ROWS*T2], g_xcl[ROWS*T2];
__device__ bf g_xcoh[ROWS*T2], g_xcol[ROWS*T2];
__device__ bf g_gh[ROWS*T2], g_gl[ROWS*T2];
__device__ bf g_xh[ROWS*TT], g_xl[ROWS*TT];
__device__ bf w_inph[3*512*256], w_inpl[3*512*256];
__device__ bf w_cvh[3*3*512*512], w_cvl_[3*3*512*512];
__device__ bf w_clh[3*512*512], w_cll[3*512*512];
__device__ bf w_f1h[3*512*512], w_f1l[3*512*512];
__device__ bf w_f2h[3*256*512], w_f2l[3*256*512];
__device__ bf w_f3h[3*256*512], w_f3l[3*256*512];
__device__ bf w_Dh[3*512*256], w_Dl[3*512*256];
__device__ bf w_oh[3*256*512], w_ol[3*256*512];
__device__ bf w_ph[256*256], w_pl[256*256];

// ---------------- helpers ----------------
__device__ __forceinline__ float siluf(float x){ return x/(1.f+__expf(-x)); }
__device__ __forceinline__ float softplusf(float x){ return fmaxf(x,0.f)+log1pf(__expf(-fabsf(x))); }
__device__ __forceinline__ void splitbf(float v, bf& h, bf& l){
    h = __float2bfloat16(v); l = __float2bfloat16(v - __bfloat162float(h));
}
__device__ __forceinline__ void st_split2(bf* Ch, bf* Cl, ll off, float v0, float v1){
    bf h0,l0,h1,l1; splitbf(v0,h0,l0); splitbf(v1,h1,l1);
    *(__nv_bfloat162*)(Ch+off) = __halves2bfloat162(h0,h1);
    *(__nv_bfloat162*)(Cl+off) = __halves2bfloat162(l0,l1);
}
__device__ __forceinline__ uint32_t s2u(const void* p){
    uint32_t a; asm("{.reg .u64 t; cvta.to.shared.u64 t,%1; cvt.u32.u64 %0,t;}":"=r"(a):"l"(p)); return a;
}
__device__ __forceinline__ void cp16(uint32_t s, const void* g, int sz){
    asm volatile("cp.async.cg.shared.global [%0], [%1], 16, %2;"::"r"(s),"l"(g),"r"(sz):"memory");
}
__device__ __forceinline__ void ldsm4(uint32_t* r, uint32_t a){
    asm volatile("ldmatrix.sync.aligned.m8n8.x4.shared.b16 {%0,%1,%2,%3}, [%4];"
        :"=r"(r[0]),"=r"(r[1]),"=r"(r[2]),"=r"(r[3]):"r"(a));
}
__device__ __forceinline__ void mma16816(float* d, const uint32_t* a, const uint32_t* b){
    asm volatile("mma.sync.aligned.m16n8k16.row.col.f32.bf16.bf16.f32 "
        "{%0,%1,%2,%3}, {%4,%5,%6,%7}, {%8,%9}, {%0,%1,%2,%3};"
        : "+f"(d[0]),"+f"(d[1]),"+f"(d[2]),"+f"(d[3])
        : "r"(a[0]),"r"(a[1]),"r"(a[2]),"r"(a[3]), "r"(b[0]),"r"(b[1]));
}
#define SW(x) ((x) ^ (((x)>>3)&0x70))

// smem per stage: Ah[128][128B] Al Bh[256][128B] Bl ; stage = 96KB, 2 stages.
#define ST_AL 16384
#define ST_BH 32768
#define ST_BL 65536
#define ST_SZ 98304
#define SMEMSZ (2*ST_SZ)

// ---------------- HMMA GEMM: D[128,256] = sum_k split(A)@split(B)^T ----------------
// A [M][K] row-major hi/lo, B [N][K] row-major hi/lo. CTA tile 128x256, warp 64x64.
// K-chunk 64, SW128-swizzled smem. ACT: 0/1/2. OUTM: bit0 fp32, bit1 hi/lo. CONV: 3-tap.
template<int ACT, int OUTM, int CONV>
__global__ void __launch_bounds__(256, 1) tc_gemm(
    const bf* __restrict__ Ah, const bf* __restrict__ Al,
    const bf* __restrict__ Bh, const bf* __restrict__ Bl,
    const float* __restrict__ bias,
    float* __restrict__ C32, bf* __restrict__ Ch, bf* __restrict__ Cl,
    int Kd, int Nc)
{
    extern __shared__ __align__(1024) char sm[];
    uint32_t sb = s2u(sm);
    const int tid = threadIdx.x, lane = tid & 31, wid = tid >> 5;
    const int n0 = blockIdx.x*256, m0 = blockIdx.y*128, z = blockIdx.z;
    const int wm = (wid & 1) * 64, wn = (wid >> 1) * 64;
    const int NC = CONV ? 24 : (Kd >> 6);

    float acc[4][8][4];
    #pragma unroll
    for (int a = 0; a < 4; a++)
        #pragma unroll
        for (int b = 0; b < 8; b++)
            #pragma unroll
            for (int c = 0; c < 4; c++) acc[a][b][c] = 0.f;

    auto DO_LOAD = [&](int c){
        int tap = CONV ? (c >> 3) : 0;
        int k0  = (CONV ? (c & 7) : c) << 6;
        uint32_t st = sb + (c & 1) * ST_SZ;
        const bf* A2h = Ah + (CONV ? (ll)tap * 262144 : 0);
        const bf* A2l = Al + (CONV ? (ll)tap * 262144 : 0);
        #pragma unroll
        for (int rep = 0; rep < 4; rep++){
            int idx = rep * 256 + tid;            // 0..1023
            int row = idx >> 3, ck = idx & 7;
            uint32_t so = SW(row * 128 + ck * 16);
            ll aoff = (ll)(m0 + row) * Kd + k0 + ck * 8;
            cp16(st + so,         A2h + aoff, 16);
            cp16(st + ST_AL + so, A2l + aoff, 16);
        }
        #pragma unroll
        for (int rep = 0; rep < 8; rep++){
            int idx = rep * 256 + tid;            // 0..2047
            int row = idx >> 3, ck = idx & 7;
            uint32_t so = SW(row * 128 + ck * 16);
            if (!CONV){
                ll boff = (ll)(n0 + row) * Kd + k0 + ck * 8;
                cp16(st + ST_BH + so, Bh + boff, 16);
                cp16(st + ST_BL + so, Bl + boff, 16);
            } else {
                int lsrc = n0 + row + tap - 1;
                int ok = ((unsigned)lsrc < 512u) ? 16 : 0;
                ll boff = (ll)(z * 512 + lsrc) * 512 + k0 + ck * 8;
                cp16(st + ST_BH + so, Bh + boff, ok);
                cp16(st + ST_BL + so, Bl + boff, ok);
            }
        }
        asm volatile("cp.async.commit_group;":::"memory");
    };

    // ldmatrix lane patterns
    const int arow = (lane & 7) + ((lane >> 3) & 1) * 8;   // m-half on bit3
    const int acolq = ((lane >> 4) & 1) * 16;              // k-half on bit4
    const int brow = (lane & 7) + ((lane >> 4) & 1) * 8;   // n-half on bit4
    const int bcolq = ((lane >> 3) & 1) * 16;              // k-half on bit3

    DO_LOAD(0);
    for (int c = 0; c < NC; c++){
        if (c + 1 < NC){ DO_LOAD(c + 1); asm volatile("cp.async.wait_group 1;":::"memory"); }
        else           {                 asm volatile("cp.async.wait_group 0;":::"memory"); }
        __syncthreads();
        uint32_t st = sb + (c & 1) * ST_SZ;
        #pragma unroll
        for (int ks = 0; ks < 4; ks++){
            uint32_t ah[4][4], al_[4][4];
            #pragma unroll
            for (int mt = 0; mt < 4; mt++){
                uint32_t ad = st + SW((wm + mt*16 + arow) * 128 + ks*32 + acolq);
                ldsm4(ah[mt], ad);
                ldsm4(al_[mt], ad + ST_AL);
            }
            #pragma unroll
            for (int np = 0; np < 4; np++){
                uint32_t bh[4], bl[4];
                uint32_t bd = st + ST_BH + SW((wn + np*16 + brow) * 128 + ks*32 + bcolq);
                ldsm4(bh, bd);
                ldsm4(bl, bd + (ST_BL - ST_BH));
                #pragma unroll
                for (int half = 0; half < 2; half++){
                    const uint32_t* ph = &bh[half * 2];
                    const uint32_t* pl = &bl[half * 2];
                    #pragma unroll
                    for (int mt = 0; mt < 4; mt++){
                        float* d = acc[mt][np*2 + half];
                        mma16816(d, ah[mt],  ph);
                        mma16816(d, al_[mt], ph);
                        mma16816(d, ah[mt],  pl);
                    }
                }
            }
        }
        __syncthreads();
    }

    // epilogue
    const int g = lane >> 2, qp = (lane & 3) * 2;
    #pragma unroll
    for (int mt = 0; mt < 4; mt++){
        #pragma unroll
        for (int half = 0; half < 2; half++){
            int m = m0 + wm + mt*16 + g + half*8;
            ll crow = CONV ? ((ll)z * 512 + m) : (ll)m;
            float bv = CONV ? bias[m] : 0.f;
            #pragma unroll
            for (int nt = 0; nt < 8; nt++){
                int n = n0 + wn + nt*8 + qp;
                float v0 = acc[mt][nt][half*2 + 0];
                float v1 = acc[mt][nt][half*2 + 1];
                if (CONV){ v0 += bv; v1 += bv; } else { v0 += bias[n]; v1 += bias[n+1]; }
                if (ACT == 1){ v0 = siluf(v0); v1 = siluf(v1); }
                if (ACT == 2){ v0 = softplusf(v0); v1 = softplusf(v1); }
                ll o = crow * Nc + n;
                if (OUTM & 1){ C32[o] = v0; C32[o+1] = v1; }
                if (OUTM & 2){ st_split2(Ch, Cl, o, v0, v1); }
            }
        }
    }
}

// ---------------- aux kernels ----------------
__global__ void k_norminput(const float* __restrict__ xe, const float* __restrict__ xm,
                            float* __restrict__ x, float* __restrict__ mean, float* __restrict__ stdv)
{
    int idx = blockIdx.x*256 + threadIdx.x;
    if (idx >= BB*FF) return;
    int f = idx % FF, b = idx / FF;
    float* xr = x + (ll)idx * TT;
    if (f < NV){
        const float* src = xe + (ll)b*TT*NV + f;
        float s = 0.f, s2 = 0.f;
        for (int t = 0; t < TT; t++){ float v = src[(ll)t*NV]; s += v; s2 += v*v; }
        float mu = s/(float)TT, var = s2/(float)TT - mu*mu, sd = sqrtf(var + 1e-5f);
        mean[b*NV+f] = mu; stdv[b*NV+f] = sd;
        float inv = 1.f/sd;
        for (int t = 0; t < TT; t++) xr[t] = (src[(ll)t*NV] - mu)*inv;
    } else {
        const float* src = xm + (ll)b*TT*MMK + (f - NV);
        for (int t = 0; t < TT; t++) xr[t] = src[(ll)t*MMK];
    }
}

__global__ void k_rms(const float* __restrict__ x, const float* __restrict__ w,
                      bf* __restrict__ oh, bf* __restrict__ ol)
{
    int r = blockIdx.x, t = threadIdx.x;
    __shared__ float red[256];
    float v = x[(ll)r*TT + t];
    red[t] = v*v; __syncthreads();
    for (int s = 128; s > 0; s >>= 1){ if (t < s) red[t] += red[t+s]; __syncthreads(); }
    float sc = rsqrtf(red[0]/(float)TT + 1e-5f);
    bf h,l; splitbf(v*sc*w[t], h, l);
    oh[(ll)r*TT+t] = h; ol[(ll)r*TT+t] = l;
}

__global__ void k_trans(const float* __restrict__ xp, bf* __restrict__ th, bf* __restrict__ tl)
{
    __shared__ float tsm[32][33];
    int b = blockIdx.z, l0 = blockIdx.x*32, f0 = blockIdx.y*32;
    int tx = threadIdx.x, ty = threadIdx.y;
    for (int i = ty; i < 32; i += 8)
        tsm[i][tx] = xp[((ll)(b*512 + f0 + i))*512 + l0 + tx];
    __syncthreads();
    for (int i = ty; i < 32; i += 8){
        bf h,l; splitbf(tsm[tx][i], h, l);
        ll o = ((ll)(b*512 + l0 + i))*512 + f0 + tx;
        th[o] = h; tl[o] = l;
    }
}

__global__ void k_combine(const float* __restrict__ dl, const float* __restrict__ xco,
                          const float* __restrict__ Bm, const float* __restrict__ Cm,
                          const float* __restrict__ xr, bf* __restrict__ gh, bf* __restrict__ gl)
{
    int r = blockIdx.x, t = threadIdx.x;
    __shared__ float red[256];
    ll rb = (ll)r*TT;
    red[t] = Cm[rb+t]*Bm[rb+t]; __syncthreads();
    for (int s = 128; s > 0; s >>= 1){ if (t < s) red[t] += red[t+s]; __syncthreads(); }
    float cb = red[0];
    ll r2 = (ll)r*T2;
    for (int c = t; c < T2; c += 256){
        float v = siluf(dl[r2+c]*xco[r2+c]*cb) * xr[r2+c];
        bf h,l; splitbf(v, h, l);
        gh[r2+c] = h; gl[r2+c] = l;
    }
}

__global__ void k_wprep(const float* __restrict__ W, bf* __restrict__ dh, bf* __restrict__ dl, int K, int N)
{
    int i = blockIdx.x*256 + threadIdx.x;
    if (i >= K*N) return;
    int k = i / N, n = i % N;
    ll zo = (ll)blockIdx.z * K * N;
    bf h,l; splitbf(W[zo + i], h, l);
    dh[zo + (ll)n*K + k] = h; dl[zo + (ll)n*K + k] = l;
}

__global__ void k_cprep(const float* __restrict__ W, bf* __restrict__ dh, bf* __restrict__ dl)
{
    int j = blockIdx.x*256 + threadIdx.x;
    if (j >= 786432) return;
    ll zo = (ll)blockIdx.z * 786432;
    int tap = j % 3, ii = (j/3) % 512, o = j / 1536;
    bf h,l; splitbf(W[zo + j], h, l);
    ll d = zo + (ll)tap*262144 + (ll)o*512 + ii;
    dh[d] = h; dl[d] = l;
}

__global__ void k_out(const float* __restrict__ dec, const float* __restrict__ mean,
                      const float* __restrict__ stdv, float* __restrict__ out)
{
    int idx = blockIdx.x*256 + threadIdx.x;
    if (idx >= BB*TT*NV) return;
    int n = idx % NV, t = (idx/NV) % TT, b = idx/(NV*TT);
    out[idx] = dec[((ll)b*FF + n)*TT + t] * stdv[b*NV+n] + mean[b*NV+n];
}

// ---------------- launcher ----------------
#define GA(p, s) cudaGetSymbolAddress((void**)&p, s)

template<int ACT, int OUTM, int CONV>
static void lg(dim3 grid, const bf* Ah, const bf* Al, const bf* Bh, const bf* Bl,
               const float* bias, float* C32, bf* Ch, bf* Cl, int Kd, int Nc)
{
    cudaFuncSetAttribute(tc_gemm<ACT,OUTM,CONV>, cudaFuncAttributeMaxDynamicSharedMemorySize, SMEMSZ);
    tc_gemm<ACT,OUTM,CONV><<<grid, 256, SMEMSZ>>>(Ah, Al, Bh, Bl, bias, C32, Ch, Cl, Kd, Nc);
}

extern "C" void kernel_launch(void* const* d_in, const int* in_sizes, int n_in,
                              void* d_out, int out_size)
{
    const float* x_enc  = (const float*)d_in[0];
    const float* x_mark = (const float*)d_in[1];
    const float* norm_w = (const float*)d_in[4];
    const float* inp_W  = (const float*)d_in[5];
    const float* inp_b  = (const float*)d_in[6];
    const float* conv_W = (const float*)d_in[7];
    const float* conv_b = (const float*)d_in[8];
    const float* cvl_W  = (const float*)d_in[9];
    const float* cvl_b  = (const float*)d_in[10];
    const float* fc1_W  = (const float*)d_in[11];
    const float* fc1_b  = (const float*)d_in[12];
    const float* fc2_W  = (const float*)d_in[13];
    const float* fc2_b  = (const float*)d_in[14];
    const float* fc3_W  = (const float*)d_in[15];
    const float* fc3_b  = (const float*)d_in[16];
    const float* D_W    = (const float*)d_in[17];
    const float* D_b    = (const float*)d_in[18];
    const float* out_W  = (const float*)d_in[19];
    const float* out_b  = (const float*)d_in[20];
    const float* proj_W = (const float*)d_in[21];
    const float* proj_b = (const float*)d_in[22];

    float *x32,*xp32,*xco32,*dl32,*Bm,*Cm,*xr32,*dec,*mean,*stdv;
    GA(x32,g_x32); GA(xp32,g_xp32); GA(xco32,g_xco32); GA(dl32,g_dl32);
    GA(Bm,g_Bm); GA(Cm,g_Cm); GA(xr32,g_xr32); GA(dec,g_dec); GA(mean,g_mean); GA(stdv,g_std);
    bf *xnh,*xnl,*xpTh,*xpTl,*xch,*xcl,*xcoh,*xcol,*gh,*gl,*xh,*xl;
    GA(xnh,g_xnh); GA(xnl,g_xnl); GA(xpTh,g_xpTh); GA(xpTl,g_xpTl);
    GA(xch,g_xch); GA(xcl,g_xcl); GA(xcoh,g_xcoh); GA(xcol,g_xcol);
    GA(gh,g_gh); GA(gl,g_gl); GA(xh,g_xh); GA(xl,g_xl);
    bf *inph,*inpl,*cvh,*cvl,*clh,*cll,*f1h,*f1l,*f2h,*f2l,*f3h,*f3l,*Dh,*Dl,*oh,*ol,*ph_,*pl_;
    GA(inph,w_inph); GA(inpl,w_inpl); GA(cvh,w_cvh); GA(cvl,w_cvl_);
    GA(clh,w_clh); GA(cll,w_cll); GA(f1h,w_f1h); GA(f1l,w_f1l);
    GA(f2h,w_f2h); GA(f2l,w_f2l); GA(f3h,w_f3h); GA(f3l,w_f3l);
    GA(Dh,w_Dh); GA(Dl,w_Dl); GA(oh,w_oh); GA(ol,w_ol); GA(ph_,w_ph); GA(pl_,w_pl);

    // weight prep (transpose to [N,K] + hi/lo split)
    k_wprep<<<dim3((256*512+255)/256,1,3),256>>>(inp_W, inph, inpl, 256, 512);
    k_wprep<<<dim3((512*512+255)/256,1,3),256>>>(cvl_W, clh, cll, 512, 512);
    k_wprep<<<dim3((512*512+255)/256,1,3),256>>>(fc1_W, f1h, f1l, 512, 512);
    k_wprep<<<dim3((512*256+255)/256,1,3),256>>>(fc2_W, f2h, f2l, 512, 256);
    k_wprep<<<dim3((512*256+255)/256,1,3),256>>>(fc3_W, f3h, f3l, 512, 256);
    k_wprep<<<dim3((256*512+255)/256,1,3),256>>>(D_W, Dh, Dl, 256, 512);
    k_wprep<<<dim3((512*256+255)/256,1,3),256>>>(out_W, oh, ol, 512, 256);
    k_wprep<<<dim3((256*256+255)/256,1,1),256>>>(proj_W, ph_, pl_, 256, 256);
    k_cprep<<<dim3((786432+255)/256,1,3),256>>>(conv_W, cvh, cvl);

    k_norminput<<<(BB*FF+255)/256,256>>>(x_enc, x_mark, x32, mean, stdv);

    for (int i = 0; i < 3; i++){
        ll w2 = (ll)i*512*512, w1 = (ll)i*256*512, wc = (ll)i*786432;
        k_rms<<<ROWS,256>>>(x32, norm_w + i*TT, xnh, xnl);
        // xp = xn @ inp_W + b                      [16384 x 512], K=256
        lg<0,1,0>(dim3(2,128), xnh, xnl, inph + w1, inpl + w1, inp_b + i*T2,
                  xp32, nullptr, nullptr, 256, 512);
        // xpT (L-major) hi/lo
        k_trans<<<dim3(16,16,BB),dim3(32,8)>>>(xp32, xpTh, xpTl);
        // xc = silu(conv1d(xp) + conv_b)            batched [512 x 512], 3 taps, K=512
        lg<1,2,1>(dim3(2,4,BB), cvh + wc, cvl + wc, xpTh, xpTl, conv_b + i*FF,
                  nullptr, xch, xcl, 512, 512);
        // xco = xc @ convlin_W + b  (fp32 + hi/lo)
        lg<0,3,0>(dim3(2,128), xch, xcl, clh + w2, cll + w2, cvl_b + i*T2,
                  xco32, xcoh, xcol, 512, 512);
        // delta = softplus(xco @ fc1_W + b)
        lg<2,1,0>(dim3(2,128), xcoh, xcol, f1h + w2, f1l + w2, fc1_b + i*T2,
                  dl32, nullptr, nullptr, 512, 512);
        // Bmat / Cmat
        lg<0,1,0>(dim3(1,128), xcoh, xcol, f2h + w2, f2l + w2, fc2_b + i*TT,
                  Bm, nullptr, nullptr, 512, 256);
        lg<0,1,0>(dim3(1,128), xcoh, xcol, f3h + w2, f3l + w2, fc3_b + i*TT,
                  Cm, nullptr, nullptr, 512, 256);
        // xres = silu(xn @ D_W + b)
        lg<1,1,0>(dim3(2,128), xnh, xnl, Dh + w1, Dl + w1, D_b + i*T2,
                  xr32, nullptr, nullptr, 256, 512);
        // g = silu(delta*xco*cb)*xres  -> hi/lo
        k_combine<<<ROWS,256>>>(dl32, xco32, Bm, Cm, xr32, gh, gl);
        // x = g @ out_W + b  (fp32 + hi/lo)
        lg<0,3,0>(dim3(1,128), gh, gl, oh + w2, ol + w2, out_b + i*TT,
                  x32, xh, xl, 512, 256);
    }
    // dec = x @ proj_W + b
    lg<0,1,0>(dim3(1,128), xh, xl, ph_, pl_, proj_b, dec, nullptr, nullptr, 256, 256);
    k_out<<<(BB*TT*NV+255)/256,256>>>(dec, mean, stdv, (float*)d_out);
}

// round 9
// speedup vs baseline: 2.7582x; 1.0125x over previous
#include <cuda_runtime.h>
#include <cuda_bf16.h>
#include <math.h>
#include <stdint.h>

#define BB 32
#define TT 256
#define FF 512
#define MMK 4
#define NV 508
#define T2 512
#define ROWS (BB*FF)
typedef __nv_bfloat16 bf;
typedef long long ll;

// ---------------- scratch ----------------
__device__ float g_x32[ROWS*TT], g_xp32[ROWS*T2];
__device__ float g_BmCm[ROWS*T2], g_xr32[ROWS*T2], g_dec[ROWS*TT];
__device__ float g_cb[ROWS];
__device__ float g_mean[BB*NV], g_std[BB*NV];
__device__ float g_b23[3*T2];
__device__ bf g_xnh[ROWS*TT], g_xnl[ROWS*TT];
__device__ bf g_xpTh[ROWS*T2], g_xpTl[ROWS*T2];
__device__ bf g_xch[ROWS*T2], g_xcl[ROWS*T2];
__device__ bf g_xcoh[ROWS*T2], g_xcol[ROWS*T2];
__device__ bf g_gh[ROWS*T2], g_gl[ROWS*T2];
__device__ bf g_xh[ROWS*TT], g_xl[ROWS*TT];
__device__ bf w_inph[3*512*256], w_inpl[3*512*256];
__device__ bf w_cvh[3*3*512*512], w_cvl_[3*3*512*512];
__device__ bf w_clh[3*512*512], w_cll[3*512*512];
__device__ bf w_f1h[3*512*512], w_f1l[3*512*512];
__device__ bf w_f23h[3*512*512], w_f23l[3*512*512];
__device__ bf w_Dh[3*512*256], w_Dl[3*512*256];
__device__ bf w_oh[3*256*512], w_ol[3*256*512];
__device__ bf w_ph[256*256], w_pl[256*256];

// ---------------- helpers ----------------
__device__ __forceinline__ float siluf(float x){ return x/(1.f+__expf(-x)); }
__device__ __forceinline__ float softplusf(float x){ return fmaxf(x,0.f)+log1pf(__expf(-fabsf(x))); }
__device__ __forceinline__ void splitbf(float v, bf& h, bf& l){
    h = __float2bfloat16(v); l = __float2bfloat16(v - __bfloat162float(h));
}
__device__ __forceinline__ void st_split2(bf* Ch, bf* Cl, ll off, float v0, float v1){
    bf h0,l0,h1,l1; splitbf(v0,h0,l0); splitbf(v1,h1,l1);
    *(__nv_bfloat162*)(Ch+off) = __halves2bfloat162(h0,h1);
    *(__nv_bfloat162*)(Cl+off) = __halves2bfloat162(l0,l1);
}
__device__ __forceinline__ uint32_t s2u(const void* p){
    uint32_t a; asm("{.reg .u64 t; cvta.to.shared.u64 t,%1; cvt.u32.u64 %0,t;}":"=r"(a):"l"(p)); return a;
}
__device__ __forceinline__ void cp16(uint32_t s, const void* g, int sz){
    asm volatile("cp.async.cg.shared.global [%0], [%1], 16, %2;"::"r"(s),"l"(g),"r"(sz):"memory");
}
__device__ __forceinline__ void ldsm4(uint32_t* r, uint32_t a){
    asm volatile("ldmatrix.sync.aligned.m8n8.x4.shared.b16 {%0,%1,%2,%3}, [%4];"
        :"=r"(r[0]),"=r"(r[1]),"=r"(r[2]),"=r"(r[3]):"r"(a));
}
__device__ __forceinline__ void mma16816(float* d, const uint32_t* a, const uint32_t* b){
    asm volatile("mma.sync.aligned.m16n8k16.row.col.f32.bf16.bf16.f32 "
        "{%0,%1,%2,%3}, {%4,%5,%6,%7}, {%8,%9}, {%0,%1,%2,%3};"
        : "+f"(d[0]),"+f"(d[1]),"+f"(d[2]),"+f"(d[3])
        : "r"(a[0]),"r"(a[1]),"r"(a[2]),"r"(a[3]), "r"(b[0]),"r"(b[1]));
}
#define SW(x) ((x) ^ (((x)>>3)&0x70))

// smem per stage: Ah[128][128B] Al Bh[256][128B] Bl ; stage = 96KB, 2 stages.
#define ST_AL 16384
#define ST_BH 32768
#define ST_BL 65536
#define ST_SZ 98304
#define SMEMSZ (2*ST_SZ)

// ---------------- HMMA GEMM ----------------
// A [M][K] row-major hi/lo, B [N][K] row-major hi/lo. CTA tile 128x256, warp 64x64.
// ACT: 0 none, 1 silu, 2 softplus.
// OUTM: 1 fp32 -> C32 ; 2 hi/lo split -> Ch/Cl ; 8 fused-rmsnorm -> Ch/Cl via nw ;
//       16 fused s6-combine (reads Xh/Xl=xco pair, Xf=xres, cbv) -> Ch/Cl.
template<int ACT, int OUTM, int CONV>
__global__ void __launch_bounds__(256, 1) tc_gemm(
    const bf* __restrict__ Ah, const bf* __restrict__ Al,
    const bf* __restrict__ Bh, const bf* __restrict__ Bl,
    const float* __restrict__ bias,
    float* __restrict__ C32, bf* __restrict__ Ch, bf* __restrict__ Cl,
    const bf* __restrict__ Xh, const bf* __restrict__ Xl,
    const float* __restrict__ Xf, const float* __restrict__ cbv,
    const float* __restrict__ nw,
    int Kd, int Nc)
{
    extern __shared__ __align__(1024) char sm[];
    uint32_t sb = s2u(sm);
    const int tid = threadIdx.x, lane = tid & 31, wid = tid >> 5;
    const int n0 = blockIdx.x*256, m0 = blockIdx.y*128, z = blockIdx.z;
    const int wm = (wid & 1) * 64, wn = (wid >> 1) * 64;
    const int NC = CONV ? 24 : (Kd >> 6);

    float acc[4][8][4];
    #pragma unroll
    for (int a = 0; a < 4; a++)
        #pragma unroll
        for (int b = 0; b < 8; b++)
            #pragma unroll
            for (int c = 0; c < 4; c++) acc[a][b][c] = 0.f;

    auto DO_LOAD = [&](int c){
        int tap = CONV ? (c >> 3) : 0;
        int k0  = (CONV ? (c & 7) : c) << 6;
        uint32_t st = sb + (c & 1) * ST_SZ;
        const bf* A2h = Ah + (CONV ? (ll)tap * 262144 : 0);
        const bf* A2l = Al + (CONV ? (ll)tap * 262144 : 0);
        #pragma unroll
        for (int rep = 0; rep < 4; rep++){
            int idx = rep * 256 + tid;
            int row = idx >> 3, ck = idx & 7;
            uint32_t so = SW(row * 128 + ck * 16);
            ll aoff = (ll)(m0 + row) * Kd + k0 + ck * 8;
            cp16(st + so,         A2h + aoff, 16);
            cp16(st + ST_AL + so, A2l + aoff, 16);
        }
        #pragma unroll
        for (int rep = 0; rep < 8; rep++){
            int idx = rep * 256 + tid;
            int row = idx >> 3, ck = idx & 7;
            uint32_t so = SW(row * 128 + ck * 16);
            if (!CONV){
                ll boff = (ll)(n0 + row) * Kd + k0 + ck * 8;
                cp16(st + ST_BH + so, Bh + boff, 16);
                cp16(st + ST_BL + so, Bl + boff, 16);
            } else {
                int lsrc = n0 + row + tap - 1;
                int ok = ((unsigned)lsrc < 512u) ? 16 : 0;
                ll boff = (ll)(z * 512 + lsrc) * 512 + k0 + ck * 8;
                cp16(st + ST_BH + so, Bh + boff, ok);
                cp16(st + ST_BL + so, Bl + boff, ok);
            }
        }
        asm volatile("cp.async.commit_group;":::"memory");
    };

    const int arow = (lane & 7) + ((lane >> 3) & 1) * 8;
    const int acolq = ((lane >> 4) & 1) * 16;
    const int brow = (lane & 7) + ((lane >> 4) & 1) * 8;
    const int bcolq = ((lane >> 3) & 1) * 16;

    DO_LOAD(0);
    for (int c = 0; c < NC; c++){
        if (c + 1 < NC){ DO_LOAD(c + 1); asm volatile("cp.async.wait_group 1;":::"memory"); }
        else           {                 asm volatile("cp.async.wait_group 0;":::"memory"); }
        __syncthreads();
        uint32_t st = sb + (c & 1) * ST_SZ;
        #pragma unroll
        for (int ks = 0; ks < 4; ks++){
            uint32_t ah[4][4], al_[4][4];
            #pragma unroll
            for (int mt = 0; mt < 4; mt++){
                uint32_t ad = st + SW((wm + mt*16 + arow) * 128 + ks*32 + acolq);
                ldsm4(ah[mt], ad);
                ldsm4(al_[mt], ad + ST_AL);
            }
            #pragma unroll
            for (int np = 0; np < 4; np++){
                uint32_t bh[4], bl[4];
                uint32_t bd = st + ST_BH + SW((wn + np*16 + brow) * 128 + ks*32 + bcolq);
                ldsm4(bh, bd);
                ldsm4(bl, bd + (ST_BL - ST_BH));
                #pragma unroll
                for (int half = 0; half < 2; half++){
                    const uint32_t* ph = &bh[half * 2];
                    const uint32_t* pl = &bl[half * 2];
                    #pragma unroll
                    for (int mt = 0; mt < 4; mt++){
                        float* d = acc[mt][np*2 + half];
                        mma16816(d, ah[mt],  ph);
                        mma16816(d, al_[mt], ph);
                        mma16816(d, ah[mt],  pl);
                    }
                }
            }
        }
        __syncthreads();
    }

    // ---------------- epilogue ----------------
    const int g = lane >> 2, qp = (lane & 3) * 2;

    if (OUTM == 8){
        // fused rmsnorm: Nc==256, grid.x==1, CTA owns full rows.
        float* part   = (float*)sm;          // [128][16]
        float* rscale = part + 2048;         // [128]
        const int nidx = wid >> 1, qi = lane & 3;
        // phase 1: bias-add, accumulate row sum-of-squares (deterministic partials)
        #pragma unroll
        for (int mt = 0; mt < 4; mt++)
            #pragma unroll
            for (int half = 0; half < 2; half++){
                int rl = wm + mt*16 + g + half*8;
                float lsq = 0.f;
                #pragma unroll
                for (int nt = 0; nt < 8; nt++){
                    int n = wn + nt*8 + qp;
                    float v0 = acc[mt][nt][half*2 + 0] + bias[n];
                    float v1 = acc[mt][nt][half*2 + 1] + bias[n+1];
                    acc[mt][nt][half*2 + 0] = v0;
                    acc[mt][nt][half*2 + 1] = v1;
                    lsq += v0*v0 + v1*v1;
                }
                part[rl*16 + nidx*4 + qi] = lsq;
            }
        __syncthreads();
        if (tid < 128){
            float s = 0.f;
            #pragma unroll
            for (int j = 0; j < 16; j++) s += part[tid*16 + j];
            rscale[tid] = rsqrtf(s * (1.f/256.f) + 1e-5f);
        }
        __syncthreads();
        #pragma unroll
        for (int mt = 0; mt < 4; mt++)
            #pragma unroll
            for (int half = 0; half < 2; half++){
                int rl = wm + mt*16 + g + half*8;
                int m = m0 + rl;
                float sc = rscale[rl];
                #pragma unroll
                for (int nt = 0; nt < 8; nt++){
                    int n = wn + nt*8 + qp;
                    float v0 = acc[mt][nt][half*2 + 0] * sc * nw[n];
                    float v1 = acc[mt][nt][half*2 + 1] * sc * nw[n+1];
                    st_split2(Ch, Cl, (ll)m * Nc + n, v0, v1);
                }
            }
        return;
    }

    #pragma unroll
    for (int mt = 0; mt < 4; mt++){
        #pragma unroll
        for (int half = 0; half < 2; half++){
            int m = m0 + wm + mt*16 + g + half*8;
            ll crow = CONV ? ((ll)z * 512 + m) : (ll)m;
            float bv = CONV ? bias[m] : 0.f;
            float cbrow = (OUTM == 16) ? cbv[crow] : 0.f;
            #pragma unroll
            for (int nt = 0; nt < 8; nt++){
                int n = n0 + wn + nt*8 + qp;
                float v0 = acc[mt][nt][half*2 + 0];
                float v1 = acc[mt][nt][half*2 + 1];
                if (CONV){ v0 += bv; v1 += bv; } else { v0 += bias[n]; v1 += bias[n+1]; }
                if (ACT == 1){ v0 = siluf(v0); v1 = siluf(v1); }
                if (ACT == 2){ v0 = softplusf(v0); v1 = softplusf(v1); }
                ll o = crow * Nc + n;
                if (OUTM == 16){
                    float xc0 = __bfloat162float(Xh[o])   + __bfloat162float(Xl[o]);
                    float xc1 = __bfloat162float(Xh[o+1]) + __bfloat162float(Xl[o+1]);
                    v0 = siluf(v0 * xc0 * cbrow) * Xf[o];
                    v1 = siluf(v1 * xc1 * cbrow) * Xf[o+1];
                    st_split2(Ch, Cl, o, v0, v1);
                } else {
                    if (OUTM & 1){ C32[o] = v0; C32[o+1] = v1; }
                    if (OUTM & 2){ st_split2(Ch, Cl, o, v0, v1); }
                }
            }
        }
    }
}

// ---------------- aux kernels ----------------
__global__ void k_norminput(const float* __restrict__ xe, const float* __restrict__ xm,
                            float* __restrict__ x, float* __restrict__ mean, float* __restrict__ stdv)
{
    int idx = blockIdx.x*256 + threadIdx.x;
    if (idx >= BB*FF) return;
    int f = idx % FF, b = idx / FF;
    float* xr = x + (ll)idx * TT;
    if (f < NV){
        const float* src = xe + (ll)b*TT*NV + f;
        float s = 0.f, s2 = 0.f;
        for (int t = 0; t < TT; t++){ float v = src[(ll)t*NV]; s += v; s2 += v*v; }
        float mu = s/(float)TT, var = s2/(float)TT - mu*mu, sd = sqrtf(var + 1e-5f);
        mean[b*NV+f] = mu; stdv[b*NV+f] = sd;
        float inv = 1.f/sd;
        for (int t = 0; t < TT; t++) xr[t] = (src[(ll)t*NV] - mu)*inv;
    } else {
        const float* src = xm + (ll)b*TT*MMK + (f - NV);
        for (int t = 0; t < TT; t++) xr[t] = src[(ll)t*MMK];
    }
}

__global__ void k_rms(const float* __restrict__ x, const float* __restrict__ w,
                      bf* __restrict__ oh, bf* __restrict__ ol)
{
    int r = blockIdx.x, t = threadIdx.x;
    __shared__ float red[256];
    float v = x[(ll)r*TT + t];
    red[t] = v*v; __syncthreads();
    for (int s = 128; s > 0; s >>= 1){ if (t < s) red[t] += red[t+s]; __syncthreads(); }
    float sc = rsqrtf(red[0]/(float)TT + 1e-5f);
    bf h,l; splitbf(v*sc*w[t], h, l);
    oh[(ll)r*TT+t] = h; ol[(ll)r*TT+t] = l;
}

__global__ void k_trans(const float* __restrict__ xp, bf* __restrict__ th, bf* __restrict__ tl)
{
    __shared__ float tsm[32][33];
    int b = blockIdx.z, l0 = blockIdx.x*32, f0 = blockIdx.y*32;
    int tx = threadIdx.x, ty = threadIdx.y;
    for (int i = ty; i < 32; i += 8)
        tsm[i][tx] = xp[((ll)(b*512 + f0 + i))*512 + l0 + tx];
    __syncthreads();
    for (int i = ty; i < 32; i += 8){
        bf h,l; splitbf(tsm[tx][i], h, l);
        ll o = ((ll)(b*512 + l0 + i))*512 + f0 + tx;
        th[o] = h; tl[o] = l;
    }
}

// cb[r] = dot(BmCm[r][0:256], BmCm[r][256:512]); warp per row
__global__ void k_cb(const float* __restrict__ BC, float* __restrict__ cb)
{
    int r = blockIdx.x*8 + (threadIdx.x >> 5), lane = threadIdx.x & 31;
    const float* p = BC + (ll)r*512;
    float s = 0.f;
    #pragma unroll
    for (int j = 0; j < 8; j++){
        int c = lane*8 + j;
        s += p[c] * p[c+256];
    }
    #pragma unroll
    for (int o = 16; o; o >>= 1) s += __shfl_xor_sync(0xFFFFFFFFu, s, o);
    if (lane == 0) cb[r] = s;
}

// one-launch weight prep: transpose [K][N]->[N][K] + hi/lo split, 8 segments
struct Seg { const float* src; bf* dh; bf* dl; int K, Nsrc, Ndst, colOff, nbat; };
struct PrepArgs { Seg s[8]; int cum[9]; };
__global__ void k_prep(PrepArgs a, int total)
{
    int i = blockIdx.x*256 + threadIdx.x;
    if (i >= total) return;
    int si = 0;
    #pragma unroll
    for (int q = 0; q < 7; q++) si += (i >= a.cum[q+1]);
    Seg sg = a.s[si];
    int r = i - a.cum[si];
    int per = sg.K * sg.Nsrc;
    int z = r / per, j = r % per;
    int k = j / sg.Nsrc, n = j % sg.Nsrc;
    float w = sg.src[(ll)z * per + j];
    bf h, l; splitbf(w, h, l);
    ll d = (ll)z * sg.K * sg.Ndst + (ll)(sg.colOff + n) * sg.K + k;
    sg.dh[d] = h; sg.dl[d] = l;
}

__global__ void k_cprep(const float* __restrict__ W, bf* __restrict__ dh, bf* __restrict__ dl)
{
    int j = blockIdx.x*256 + threadIdx.x;
    if (j >= 786432) return;
    ll zo = (ll)blockIdx.z * 786432;
    int tap = j % 3, ii = (j/3) % 512, o = j / 1536;
    bf h,l; splitbf(W[zo + j], h, l);
    ll d = zo + (ll)tap*262144 + (ll)o*512 + ii;
    dh[d] = h; dl[d] = l;
}

__global__ void k_bias23(const float* __restrict__ b2, const float* __restrict__ b3,
                         float* __restrict__ b23)
{
    int i = blockIdx.x*256 + threadIdx.x;
    if (i >= 3*T2) return;
    int z = i / T2, n = i % T2;
    b23[i] = (n < 256) ? b2[z*256 + n] : b3[z*256 + n - 256];
}

__global__ void k_out(const float* __restrict__ dec, const float* __restrict__ mean,
                      const float* __restrict__ stdv, float* __restrict__ out)
{
    int idx = blockIdx.x*256 + threadIdx.x;
    if (idx >= BB*TT*NV) return;
    int n = idx % NV, t = (idx/NV) % TT, b = idx/(NV*TT);
    out[idx] = dec[((ll)b*FF + n)*TT + t] * stdv[b*NV+n] + mean[b*NV+n];
}

// ---------------- launcher ----------------
#define GA(p, s) cudaGetSymbolAddress((void**)&p, s)

template<int ACT, int OUTM, int CONV>
static void lg(dim3 grid, const bf* Ah, const bf* Al, const bf* Bh, const bf* Bl,
               const float* bias, float* C32, bf* Ch, bf* Cl,
               const bf* Xh, const bf* Xl, const float* Xf, const float* cbv,
               const float* nw, int Kd, int Nc)
{
    cudaFuncSetAttribute(tc_gemm<ACT,OUTM,CONV>, cudaFuncAttributeMaxDynamicSharedMemorySize, SMEMSZ);
    tc_gemm<ACT,OUTM,CONV><<<grid, 256, SMEMSZ>>>(Ah, Al, Bh, Bl, bias, C32, Ch, Cl,
                                                  Xh, Xl, Xf, cbv, nw, Kd, Nc);
}

extern "C" void kernel_launch(void* const* d_in, const int* in_sizes, int n_in,
                              void* d_out, int out_size)
{
    const float* x_enc  = (const float*)d_in[0];
    const float* x_mark = (const float*)d_in[1];
    const float* norm_w = (const float*)d_in[4];
    const float* inp_W  = (const float*)d_in[5];
    const float* inp_b  = (const float*)d_in[6];
    const float* conv_W = (const float*)d_in[7];
    const float* conv_b = (const float*)d_in[8];
    const float* cvl_W  = (const float*)d_in[9];
    const float* cvl_b  = (const float*)d_in[10];
    const float* fc1_W  = (const float*)d_in[11];
    const float* fc1_b  = (const float*)d_in[12];
    const float* fc2_W  = (const float*)d_in[13];
    const float* fc2_b  = (const float*)d_in[14];
    const float* fc3_W  = (const float*)d_in[15];
    const float* fc3_b  = (const float*)d_in[16];
    const float* D_W    = (const float*)d_in[17];
    const float* D_b    = (const float*)d_in[18];
    const float* out_W  = (const float*)d_in[19];
    const float* out_b  = (const float*)d_in[20];
    const float* proj_W = (const float*)d_in[21];
    const float* proj_b = (const float*)d_in[22];

    float *x32,*xp32,*BmCm,*xr32,*dec,*mean,*stdv,*cb,*b23;
    GA(x32,g_x32); GA(xp32,g_xp32); GA(BmCm,g_BmCm); GA(xr32,g_xr32);
    GA(dec,g_dec); GA(mean,g_mean); GA(stdv,g_std); GA(cb,g_cb); GA(b23,g_b23);
    bf *xnh,*xnl,*xpTh,*xpTl,*xch,*xcl,*xcoh,*xcol,*gh,*gl,*xh,*xl;
    GA(xnh,g_xnh); GA(xnl,g_xnl); GA(xpTh,g_xpTh); GA(xpTl,g_xpTl);
    GA(xch,g_xch); GA(xcl,g_xcl); GA(xcoh,g_xcoh); GA(xcol,g_xcol);
    GA(gh,g_gh); GA(gl,g_gl); GA(xh,g_xh); GA(xl,g_xl);
    bf *inph,*inpl,*cvh,*cvl,*clh,*cll,*f1h,*f1l,*f23h,*f23l,*Dh,*Dl,*oh,*ol,*ph_,*pl_;
    GA(inph,w_inph); GA(inpl,w_inpl); GA(cvh,w_cvh); GA(cvl,w_cvl_);
    GA(clh,w_clh); GA(cll,w_cll); GA(f1h,w_f1h); GA(f1l,w_f1l);
    GA(f23h,w_f23h); GA(f23l,w_f23l);
    GA(Dh,w_Dh); GA(Dl,w_Dl); GA(oh,w_oh); GA(ol,w_ol); GA(ph_,w_ph); GA(pl_,w_pl);

    // --- one-launch weight prep ---
    PrepArgs pa;
    pa.s[0] = { inp_W,  inph, inpl, 256, 512, 512, 0,   3 };
    pa.s[1] = { cvl_W,  clh,  cll,  512, 512, 512, 0,   3 };
    pa.s[2] = { fc1_W,  f1h,  f1l,  512, 512, 512, 0,   3 };
    pa.s[3] = { fc2_W,  f23h, f23l, 512, 256, 512, 0,   3 };
    pa.s[4] = { fc3_W,  f23h, f23l, 512, 256, 512, 256, 3 };
    pa.s[5] = { D_W,    Dh,   Dl,   256, 512, 512, 0,   3 };
    pa.s[6] = { out_W,  oh,   ol,   512, 256, 256, 0,   3 };
    pa.s[7] = { proj_W, ph_,  pl_,  256, 256, 256, 0,   1 };
    pa.cum[0] = 0;
    for (int q = 0; q < 8; q++)
        pa.cum[q+1] = pa.cum[q] + pa.s[q].K * pa.s[q].Nsrc * pa.s[q].nbat;
    int total = pa.cum[8];
    k_prep<<<(total + 255)/256, 256>>>(pa, total);
    k_cprep<<<dim3((786432+255)/256,1,3),256>>>(conv_W, cvh, cvl);
    k_bias23<<<(3*T2+255)/256,256>>>(fc2_b, fc3_b, b23);

    k_norminput<<<(BB*FF+255)/256,256>>>(x_enc, x_mark, x32, mean, stdv);
    k_rms<<<ROWS,256>>>(x32, norm_w, xnh, xnl);

    for (int i = 0; i < 3; i++){
        ll w2 = (ll)i*512*512, w1 = (ll)i*256*512, wc = (ll)i*786432;
        // xp = xn @ inp_W + b  -> fp32
        lg<0,1,0>(dim3(2,128), xnh, xnl, inph + w1, inpl + w1, inp_b + i*T2,
                  xp32, nullptr, nullptr, nullptr, nullptr, nullptr, nullptr, nullptr, 256, 512);
        // xres = silu(xn @ D_W + b) -> fp32
        lg<1,1,0>(dim3(2,128), xnh, xnl, Dh + w1, Dl + w1, D_b + i*T2,
                  xr32, nullptr, nullptr, nullptr, nullptr, nullptr, nullptr, nullptr, 256, 512);
        // xpT (L-major) hi/lo
        k_trans<<<dim3(16,16,BB),dim3(32,8)>>>(xp32, xpTh, xpTl);
        // xc = silu(conv1d(xp) + conv_b) -> hi/lo
        lg<1,2,1>(dim3(2,4,BB), cvh + wc, cvl + wc, xpTh, xpTl, conv_b + i*FF,
                  nullptr, xch, xcl, nullptr, nullptr, nullptr, nullptr, nullptr, 512, 512);
        // xco = xc @ convlin_W + b -> hi/lo only
        lg<0,2,0>(dim3(2,128), xch, xcl, clh + w2, cll + w2, cvl_b + i*T2,
                  nullptr, xcoh, xcol, nullptr, nullptr, nullptr, nullptr, nullptr, 512, 512);
        // [Bm|Cm] = xco @ [fc2|fc3] + [b2|b3] -> fp32
        lg<0,1,0>(dim3(2,128), xcoh, xcol, f23h + w2, f23l + w2, b23 + i*T2,
                  BmCm, nullptr, nullptr, nullptr, nullptr, nullptr, nullptr, nullptr, 512, 512);
        // cb = rowwise dot
        k_cb<<<ROWS/8,256>>>(BmCm, cb);
        // g = silu(softplus(xco@fc1+b) * xco * cb) * xres -> hi/lo (fused combine)
        lg<2,16,0>(dim3(2,128), xcoh, xcol, f1h + w2, f1l + w2, fc1_b + i*T2,
                  nullptr, gh, gl, xcoh, xcol, xr32, cb, nullptr, 512, 512);
        // x = g @ out_W + b ; blocks 0,1: fused rmsnorm -> xn hi/lo ; block 2: raw split
        if (i < 2){
            lg<0,8,0>(dim3(1,128), gh, gl, oh + w1, ol + w1, out_b + i*TT,
                      nullptr, xnh, xnl, nullptr, nullptr, nullptr, nullptr,
                      norm_w + (i+1)*TT, 512, 256);
        } else {
            lg<0,2,0>(dim3(1,128), gh, gl, oh + w1, ol + w1, out_b + i*TT,
                      nullptr, xh, xl, nullptr, nullptr, nullptr, nullptr, nullptr, 512, 256);
        }
    }
    // dec = x @ proj_W + b
    lg<0,1,0>(dim3(1,128), xh, xl, ph_, pl_, proj_b,
              dec, nullptr, nullptr, nullptr, nullptr, nullptr, nullptr, nullptr, 256, 256);
    k_out<<<(BB*TT*NV+255)/256,256>>>(dec, mean, stdv, (float*)d_out);
}

// round 11
// speedup vs baseline: 2.7990x; 1.0148x over previous
#include <cuda_runtime.h>
#include <cuda_bf16.h>
#include <math.h>
#include <stdint.h>

#define BB 32
#define TT 256
#define FF 512
#define MMK 4
#define NV 508
#define T2 512
#define ROWS (BB*FF)
typedef __nv_bfloat16 bf;
typedef long long ll;

// ---------------- scratch ----------------
__device__ float g_x32[ROWS*TT], g_xp32[ROWS*T2];
__device__ float g_BmCm[ROWS*T2], g_xr32[ROWS*T2], g_dec[ROWS*TT];
__device__ float g_cb[ROWS];
__device__ float g_mean[BB*NV], g_std[BB*NV];
__device__ float g_b23[3*T2];
__device__ bf g_xnh[ROWS*TT], g_xnl[ROWS*TT];
__device__ bf g_xpTh[ROWS*T2], g_xpTl[ROWS*T2];
__device__ bf g_xch[ROWS*T2], g_xcl[ROWS*T2];
__device__ bf g_xcoh[ROWS*T2], g_xcol[ROWS*T2];
__device__ bf g_gh[ROWS*T2], g_gl[ROWS*T2];
__device__ bf g_xh[ROWS*TT], g_xl[ROWS*TT];
__device__ bf w_inph[3*512*256], w_inpl[3*512*256];
__device__ bf w_cvh[3*3*512*512], w_cvl_[3*3*512*512];
__device__ bf w_clh[3*512*512], w_cll[3*512*512];
__device__ bf w_f1h[3*512*512], w_f1l[3*512*512];
__device__ bf w_f23h[3*512*512], w_f23l[3*512*512];
__device__ bf w_Dh[3*512*256], w_Dl[3*512*256];
__device__ bf w_oh[3*256*512], w_ol[3*256*512];
__device__ bf w_ph[256*256], w_pl[256*256];

// ---------------- helpers ----------------
__device__ __forceinline__ float siluf(float x){ return x/(1.f+__expf(-x)); }
__device__ __forceinline__ float softplusf(float x){ return fmaxf(x,0.f)+log1pf(__expf(-fabsf(x))); }
__device__ __forceinline__ void splitbf(float v, bf& h, bf& l){
    h = __float2bfloat16(v); l = __float2bfloat16(v - __bfloat162float(h));
}
__device__ __forceinline__ void st_split2(bf* Ch, bf* Cl, ll off, float v0, float v1){
    bf h0,l0,h1,l1; splitbf(v0,h0,l0); splitbf(v1,h1,l1);
    *(__nv_bfloat162*)(Ch+off) = __halves2bfloat162(h0,h1);
    *(__nv_bfloat162*)(Cl+off) = __halves2bfloat162(l0,l1);
}
__device__ __forceinline__ uint32_t s2u(const void* p){
    uint32_t a; asm("{.reg .u64 t; cvta.to.shared.u64 t,%1; cvt.u32.u64 %0,t;}":"=r"(a):"l"(p)); return a;
}
__device__ __forceinline__ void cp16(uint32_t s, const void* g, int sz){
    asm volatile("cp.async.cg.shared.global [%0], [%1], 16, %2;"::"r"(s),"l"(g),"r"(sz):"memory");
}
__device__ __forceinline__ void ldsm4(uint32_t* r, uint32_t a){
    asm volatile("ldmatrix.sync.aligned.m8n8.x4.shared.b16 {%0,%1,%2,%3}, [%4];"
        :"=r"(r[0]),"=r"(r[1]),"=r"(r[2]),"=r"(r[3]):"r"(a));
}
__device__ __forceinline__ void mma16816(float* d, const uint32_t* a, const uint32_t* b){
    asm volatile("mma.sync.aligned.m16n8k16.row.col.f32.bf16.bf16.f32 "
        "{%0,%1,%2,%3}, {%4,%5,%6,%7}, {%8,%9}, {%0,%1,%2,%3};"
        : "+f"(d[0]),"+f"(d[1]),"+f"(d[2]),"+f"(d[3])
        : "r"(a[0]),"r"(a[1]),"r"(a[2]),"r"(a[3]), "r"(b[0]),"r"(b[1]));
}
// 64B-row swizzle: 16B slot XOR'd by (row>>1)&3 — conflict-free for cp.async stores
// and every 8-lane ldmatrix phase (verified: 8 rows -> 8 distinct bank quads).
#define SW32(r,c) ((uint32_t)((r)*64 + (((c) ^ ((((r)>>1)&3)<<4)))))

// smem per stage: Ah[128][64B] Al Bh[128][64B] Bl = 32KB; 2 stages = 64KB -> 2 CTAs/SM.
#define ST_AL 8192
#define ST_BH 16384
#define ST_BL 24576
#define ST_SZ 32768
#define SMEMSZ (2*ST_SZ)

// ---------------- 3-term HMMA GEMM: D = (Ah+Al)@(Bh+Bl)^T (drop Al*Bl) ----------------
// A [M][K] row-major hi/lo, B [N][K] row-major hi/lo. CTA 128x128, 4 warps, K-chunk 32.
// ACT: 0 none, 1 silu, 2 softplus. OUTM: 1 fp32 ; 2 hi/lo split ; 16 fused s6-combine.
template<int ACT, int OUTM, int CONV>
__global__ void __launch_bounds__(128, 2) tc_gemm(
    const bf* __restrict__ Ah, const bf* __restrict__ Al,
    const bf* __restrict__ Bh, const bf* __restrict__ Bl,
    const float* __restrict__ bias,
    float* __restrict__ C32, bf* __restrict__ Ch, bf* __restrict__ Cl,
    const bf* __restrict__ Xh, const bf* __restrict__ Xl,
    const float* __restrict__ Xf, const float* __restrict__ cbv,
    int Kd, int Nc)
{
    extern __shared__ __align__(1024) char sm[];
    uint32_t sb = s2u(sm);
    const int tid = threadIdx.x, lane = tid & 31, wid = tid >> 5;
    const int n0 = blockIdx.x*128, m0 = blockIdx.y*128, z = blockIdx.z;
    const int wm = (wid & 1) * 64, wn = (wid >> 1) * 64;
    const int NC = CONV ? 48 : (Kd >> 5);

    float acc[4][8][4];
    #pragma unroll
    for (int a = 0; a < 4; a++)
        #pragma unroll
        for (int b = 0; b < 8; b++)
            #pragma unroll
            for (int c = 0; c < 4; c++) acc[a][b][c] = 0.f;

    auto DO_LOAD = [&](int c){
        int tap = CONV ? (c >> 4) : 0;
        int k0  = (CONV ? (c & 15) : c) << 5;
        uint32_t st = sb + (c & 1) * ST_SZ;
        const bf* A2h = Ah + (CONV ? (ll)tap * 262144 : 0);
        const bf* A2l = Al + (CONV ? (ll)tap * 262144 : 0);
        #pragma unroll
        for (int rep = 0; rep < 4; rep++){
            int idx = rep * 128 + tid;            // 0..511
            int row = idx >> 2, ck = idx & 3;
            uint32_t so = SW32(row, ck * 16);
            ll aoff = (ll)(m0 + row) * Kd + k0 + ck * 8;
            cp16(st + so,         A2h + aoff, 16);
            cp16(st + ST_AL + so, A2l + aoff, 16);
            if (!CONV){
                ll boff = (ll)(n0 + row) * Kd + k0 + ck * 8;
                cp16(st + ST_BH + so, Bh + boff, 16);
                cp16(st + ST_BL + so, Bl + boff, 16);
            } else {
                int lsrc = n0 + row + tap - 1;
                int ok = ((unsigned)lsrc < 512u) ? 16 : 0;
                ll boff = (ll)(z * 512 + lsrc) * 512 + k0 + ck * 8;
                cp16(st + ST_BH + so, Bh + boff, ok);
                cp16(st + ST_BL + so, Bl + boff, ok);
            }
        }
        asm volatile("cp.async.commit_group;":::"memory");
    };

    const int arow = (lane & 7) + ((lane >> 3) & 1) * 8;
    const int acolq = ((lane >> 4) & 1) * 16;
    const int brow = (lane & 7) + ((lane >> 4) & 1) * 8;
    const int bcolq = ((lane >> 3) & 1) * 16;

    DO_LOAD(0);
    for (int c = 0; c < NC; c++){
        if (c + 1 < NC){ DO_LOAD(c + 1); asm volatile("cp.async.wait_group 1;":::"memory"); }
        else           {                 asm volatile("cp.async.wait_group 0;":::"memory"); }
        __syncthreads();
        uint32_t st = sb + (c & 1) * ST_SZ;
        #pragma unroll
        for (int ks = 0; ks < 2; ks++){
            uint32_t ah[4][4], al_[4][4];
            #pragma unroll
            for (int mt = 0; mt < 4; mt++){
                int r = wm + mt*16 + arow;
                ldsm4(ah[mt],  st + SW32(r, ks*32 + acolq));
                ldsm4(al_[mt], st + ST_AL + SW32(r, ks*32 + acolq));
            }
            #pragma unroll
            for (int np = 0; np < 4; np++){
                uint32_t bh[4], bl[4];
                int r = wn + np*16 + brow;
                ldsm4(bh, st + ST_BH + SW32(r, ks*32 + bcolq));
                ldsm4(bl, st + ST_BL + SW32(r, ks*32 + bcolq));
                #pragma unroll
                for (int half = 0; half < 2; half++){
                    const uint32_t* ph = &bh[half * 2];
                    const uint32_t* pl = &bl[half * 2];
                    #pragma unroll
                    for (int mt = 0; mt < 4; mt++){
                        float* d = acc[mt][np*2 + half];
                        mma16816(d, ah[mt],  ph);
                        mma16816(d, al_[mt], ph);
                        mma16816(d, ah[mt],  pl);
                    }
                }
            }
        }
        __syncthreads();
    }

    // ---------------- epilogue ----------------
    const int g = lane >> 2, qp = (lane & 3) * 2;
    #pragma unroll
    for (int mt = 0; mt < 4; mt++){
        #pragma unroll
        for (int half = 0; half < 2; half++){
            int m = m0 + wm + mt*16 + g + half*8;
            ll crow = CONV ? ((ll)z * 512 + m) : (ll)m;
            float bv = CONV ? bias[m] : 0.f;
            float cbrow = (OUTM == 16) ? cbv[crow] : 0.f;
            #pragma unroll
            for (int nt = 0; nt < 8; nt++){
                int n = n0 + wn + nt*8 + qp;
                float v0 = acc[mt][nt][half*2 + 0];
                float v1 = acc[mt][nt][half*2 + 1];
                if (CONV){ v0 += bv; v1 += bv; } else { v0 += bias[n]; v1 += bias[n+1]; }
                if (ACT == 1){ v0 = siluf(v0); v1 = siluf(v1); }
                if (ACT == 2){ v0 = softplusf(v0); v1 = softplusf(v1); }
                ll o = crow * Nc + n;
                if (OUTM == 16){
                    float xc0 = __bfloat162float(Xh[o])   + __bfloat162float(Xl[o]);
                    float xc1 = __bfloat162float(Xh[o+1]) + __bfloat162float(Xl[o+1]);
                    v0 = siluf(v0 * xc0 * cbrow) * Xf[o];
                    v1 = siluf(v1 * xc1 * cbrow) * Xf[o+1];
                    st_split2(Ch, Cl, o, v0, v1);
                } else if (OUTM == 2){
                    st_split2(Ch, Cl, o, v0, v1);
                } else {
                    C32[o] = v0; C32[o+1] = v1;
                }
            }
        }
    }
}

// ---------------- aux kernels ----------------
// fused: per-variate standardization + block-0 rmsnorm (analytic) + hi/lo split
__global__ void k_norm(const float* __restrict__ xe, const float* __restrict__ xm,
                       const float* __restrict__ nw, bf* __restrict__ xnh, bf* __restrict__ xnl,
                       float* __restrict__ mean, float* __restrict__ stdv)
{
    int b = blockIdx.y, f0 = blockIdx.x*64;
    int tid = threadIdx.x, f = tid & 63, tg = tid >> 6;
    int gf = f0 + f;
    __shared__ float ss[64][4], ss2[64][4];
    __shared__ float smu[64], sinv[64], ssc[64];
    bool ismark = (gf >= NV);
    const float* src = ismark ? (xm + (ll)b*TT*MMK + (gf-NV)) : (xe + (ll)b*TT*NV + gf);
    int stride = ismark ? MMK : NV;
    float s = 0.f, s2 = 0.f;
    for (int t = tg; t < TT; t += 4){ float v = src[(ll)t*stride]; s += v; s2 += v*v; }
    ss[f][tg] = s; ss2[f][tg] = s2;
    __syncthreads();
    if (tg == 0){
        float S = 0.f, S2 = 0.f;
        #pragma unroll
        for (int q = 0; q < 4; q++){ S += ss[f][q]; S2 += ss2[f][q]; }
        float mu, inv, m2;
        if (!ismark){
            mu = S * (1.f/256.f);
            float var = S2 * (1.f/256.f) - mu*mu;
            float sd = sqrtf(var + 1e-5f);
            inv = 1.f/sd;
            m2 = var / (var + 1e-5f);
            mean[b*NV+gf] = mu; stdv[b*NV+gf] = sd;
        } else { mu = 0.f; inv = 1.f; m2 = S2 * (1.f/256.f); }
        smu[f] = mu; sinv[f] = inv; ssc[f] = rsqrtf(m2 + 1e-5f);
    }
    __syncthreads();
    float mu = smu[f], inv = sinv[f], sc = ssc[f];
    ll rb = ((ll)b*512 + gf) * TT;
    for (int t = tg; t < TT; t += 4){
        float v = (src[(ll)t*stride] - mu) * inv * sc * nw[t];
        bf h,l; splitbf(v,h,l);
        xnh[rb + t] = h; xnl[rb + t] = l;
    }
}

__global__ void k_rms(const float* __restrict__ x, const float* __restrict__ w,
                      bf* __restrict__ oh, bf* __restrict__ ol)
{
    int r = blockIdx.x, t = threadIdx.x;
    __shared__ float red[256];
    float v = x[(ll)r*TT + t];
    red[t] = v*v; __syncthreads();
    for (int s = 128; s > 0; s >>= 1){ if (t < s) red[t] += red[t+s]; __syncthreads(); }
    float sc = rsqrtf(red[0]*(1.f/256.f) + 1e-5f);
    bf h,l; splitbf(v*sc*w[t], h, l);
    oh[(ll)r*TT+t] = h; ol[(ll)r*TT+t] = l;
}

__global__ void k_trans(const float* __restrict__ xp, bf* __restrict__ th, bf* __restrict__ tl)
{
    __shared__ float tsm[32][33];
    int b = blockIdx.z, l0 = blockIdx.x*32, f0 = blockIdx.y*32;
    int tx = threadIdx.x, ty = threadIdx.y;
    for (int i = ty; i < 32; i += 8)
        tsm[i][tx] = xp[((ll)(b*512 + f0 + i))*512 + l0 + tx];
    __syncthreads();
    for (int i = ty; i < 32; i += 8){
        bf h,l; splitbf(tsm[tx][i], h, l);
        ll o = ((ll)(b*512 + l0 + i))*512 + f0 + tx;
        th[o] = h; tl[o] = l;
    }
}

__global__ void k_cb(const float* __restrict__ BC, float* __restrict__ cb)
{
    int r = blockIdx.x*8 + (threadIdx.x >> 5), lane = threadIdx.x & 31;
    const float* p = BC + (ll)r*512;
    float s = 0.f;
    #pragma unroll
    for (int j = 0; j < 8; j++){ int c = lane*8 + j; s += p[c] * p[c+256]; }
    #pragma unroll
    for (int o = 16; o; o >>= 1) s += __shfl_xor_sync(0xFFFFFFFFu, s, o);
    if (lane == 0) cb[r] = s;
}

struct Seg { const float* src; bf* dh; bf* dl; int K, Nsrc, Ndst, colOff, nbat; };
struct PrepArgs { Seg s[8]; int cum[9]; };
__global__ void k_prep(PrepArgs a, int total)
{
    int i = blockIdx.x*256 + threadIdx.x;
    if (i >= total) return;
    int si = 0;
    #pragma unroll
    for (int q = 0; q < 7; q++) si += (i >= a.cum[q+1]);
    Seg sg = a.s[si];
    int r = i - a.cum[si];
    int per = sg.K * sg.Nsrc;
    int z = r / per, j = r % per;
    int k = j / sg.Nsrc, n = j % sg.Nsrc;
    bf h, l; splitbf(sg.src[(ll)z * per + j], h, l);
    ll d = (ll)z * sg.K * sg.Ndst + (ll)(sg.colOff + n) * sg.K + k;
    sg.dh[d] = h; sg.dl[d] = l;
}

__global__ void k_cprep(const float* __restrict__ W, bf* __restrict__ dh, bf* __restrict__ dl)
{
    int j = blockIdx.x*256 + threadIdx.x;
    if (j >= 786432) return;
    ll zo = (ll)blockIdx.z * 786432;
    int tap = j % 3, ii = (j/3) % 512, o = j / 1536;
    bf h,l; splitbf(W[zo + j], h, l);
    ll d = zo + (ll)tap*262144 + (ll)o*512 + ii;
    dh[d] = h; dl[d] = l;
}

__global__ void k_bias23(const float* __restrict__ b2, const float* __restrict__ b3,
                         float* __restrict__ b23)
{
    int i = blockIdx.x*256 + threadIdx.x;
    if (i >= 3*T2) return;
    int z = i / T2, n = i % T2;
    b23[i] = (n < 256) ? b2[z*256 + n] : b3[z*256 + n - 256];
}

__global__ void k_out(const float* __restrict__ dec, const float* __restrict__ mean,
                      const float* __restrict__ stdv, float* __restrict__ out)
{
    int idx = blockIdx.x*256 + threadIdx.x;
    if (idx >= BB*TT*NV) return;
    int n = idx % NV, t = (idx/NV) % TT, b = idx/(NV*TT);
    out[idx] = dec[((ll)b*FF + n)*TT + t] * stdv[b*NV+n] + mean[b*NV+n];
}

// ---------------- launcher ----------------
#define GA(p, s) cudaGetSymbolAddress((void**)&p, s)

template<int ACT, int OUTM, int CONV>
static void lg(dim3 grid, const bf* Ah, const bf* Al, const bf* Bh, const bf* Bl,
               const float* bias, float* C32, bf* Ch, bf* Cl,
               const bf* Xh, const bf* Xl, const float* Xf, const float* cbv,
               int Kd, int Nc)
{
    cudaFuncSetAttribute(tc_gemm<ACT,OUTM,CONV>, cudaFuncAttributeMaxDynamicSharedMemorySize, SMEMSZ);
    tc_gemm<ACT,OUTM,CONV><<<grid, 128, SMEMSZ>>>(Ah, Al, Bh, Bl, bias, C32, Ch, Cl,
                                                  Xh, Xl, Xf, cbv, Kd, Nc);
}

extern "C" void kernel_launch(void* const* d_in, const int* in_sizes, int n_in,
                              void* d_out, int out_size)
{
    const float* x_enc  = (const float*)d_in[0];
    const float* x_mark = (const float*)d_in[1];
    const float* norm_w = (const float*)d_in[4];
    const float* inp_W  = (const float*)d_in[5];
    const float* inp_b  = (const float*)d_in[6];
    const float* conv_W = (const float*)d_in[7];
    const float* conv_b = (const float*)d_in[8];
    const float* cvl_W  = (const float*)d_in[9];
    const float* cvl_b  = (const float*)d_in[10];
    const float* fc1_W  = (const float*)d_in[11];
    const float* fc1_b  = (const float*)d_in[12];
    const float* fc2_W  = (const float*)d_in[13];
    const float* fc2_b  = (const float*)d_in[14];
    const float* fc3_W  = (const float*)d_in[15];
    const float* fc3_b  = (const float*)d_in[16];
    const float* D_W    = (const float*)d_in[17];
    const float* D_b    = (const float*)d_in[18];
    const float* out_W  = (const float*)d_in[19];
    const float* out_b  = (const float*)d_in[20];
    const float* proj_W = (const float*)d_in[21];
    const float* proj_b = (const float*)d_in[22];

    float *x32,*xp32,*BmCm,*xr32,*dec,*mean,*stdv,*cb,*b23;
    GA(x32,g_x32); GA(xp32,g_xp32); GA(BmCm,g_BmCm); GA(xr32,g_xr32);
    GA(dec,g_dec); GA(mean,g_mean); GA(stdv,g_std); GA(cb,g_cb); GA(b23,g_b23);
    bf *xnh,*xnl,*xpTh,*xpTl,*xch,*xcl,*xcoh,*xcol,*gh,*gl,*xh,*xl;
    GA(xnh,g_xnh); GA(xnl,g_xnl); GA(xpTh,g_xpTh); GA(xpTl,g_xpTl);
    GA(xch,g_xch); GA(xcl,g_xcl); GA(xcoh,g_xcoh); GA(xcol,g_xcol);
    GA(gh,g_gh); GA(gl,g_gl); GA(xh,g_xh); GA(xl,g_xl);
    bf *inph,*inpl,*cvh,*cvl,*clh,*cll,*f1h,*f1l,*f23h,*f23l,*Dh,*Dl,*oh,*ol,*ph_,*pl_;
    GA(inph,w_inph); GA(inpl,w_inpl); GA(cvh,w_cvh); GA(cvl,w_cvl_);
    GA(clh,w_clh); GA(cll,w_cll); GA(f1h,w_f1h); GA(f1l,w_f1l);
    GA(f23h,w_f23h); GA(f23l,w_f23l);
    GA(Dh,w_Dh); GA(Dl,w_Dl); GA(oh,w_oh); GA(ol,w_ol); GA(ph_,w_ph); GA(pl_,w_pl);

    PrepArgs pa;
    pa.s[0] = { inp_W,  inph, inpl, 256, 512, 512, 0,   3 };
    pa.s[1] = { cvl_W,  clh,  cll,  512, 512, 512, 0,   3 };
    pa.s[2] = { fc1_W,  f1h,  f1l,  512, 512, 512, 0,   3 };
    pa.s[3] = { fc2_W,  f23h, f23l, 512, 256, 512, 0,   3 };
    pa.s[4] = { fc3_W,  f23h, f23l, 512, 256, 512, 256, 3 };
    pa.s[5] = { D_W,    Dh,   Dl,   256, 512, 512, 0,   3 };
    pa.s[6] = { out_W,  oh,   ol,   512, 256, 256, 0,   3 };
    pa.s[7] = { proj_W, ph_,  pl_,  256, 256, 256, 0,   1 };
    pa.cum[0] = 0;
    for (int q = 0; q < 8; q++)
        pa.cum[q+1] = pa.cum[q] + pa.s[q].K * pa.s[q].Nsrc * pa.s[q].nbat;
    int total = pa.cum[8];
    k_prep<<<(total + 255)/256, 256>>>(pa, total);
    k_cprep<<<dim3((786432+255)/256,1,3),256>>>(conv_W, cvh, cvl);
    k_bias23<<<(3*T2+255)/256,256>>>(fc2_b, fc3_b, b23);

    // fused input standardization + block-0 rmsnorm -> xn hi/lo
    k_norm<<<dim3(8,BB),256>>>(x_enc, x_mark, norm_w, xnh, xnl, mean, stdv);

    for (int i = 0; i < 3; i++){
        ll w2 = (ll)i*512*512, w1 = (ll)i*256*512, wc = (ll)i*786432;
        // xp = xn @ inp_W + b -> fp32
        lg<0,1,0>(dim3(4,128), xnh, xnl, inph + w1, inpl + w1, inp_b + i*T2,
                  xp32, nullptr, nullptr, nullptr, nullptr, nullptr, nullptr, 256, 512);
        // xres = silu(xn @ D_W + b) -> fp32
        lg<1,1,0>(dim3(4,128), xnh, xnl, Dh + w1, Dl + w1, D_b + i*T2,
                  xr32, nullptr, nullptr, nullptr, nullptr, nullptr, nullptr, 256, 512);
        // xp^T hi/lo
        k_trans<<<dim3(16,16,BB),dim3(32,8)>>>(xp32, xpTh, xpTl);
        // xc = silu(conv1d(xp) + conv_b) -> hi/lo
        lg<1,2,1>(dim3(4,4,BB), cvh + wc, cvl + wc, xpTh, xpTl, conv_b + i*FF,
                  nullptr, xch, xcl, nullptr, nullptr, nullptr, nullptr, 512, 512);
        // xco = xc @ convlin_W + b -> hi/lo
        lg<0,2,0>(dim3(4,128), xch, xcl, clh + w2, cll + w2, cvl_b + i*T2,
                  nullptr, xcoh, xcol, nullptr, nullptr, nullptr, nullptr, 512, 512);
        // [Bm|Cm] = xco @ [fc2|fc3] + [b2|b3] -> fp32
        lg<0,1,0>(dim3(4,128), xcoh, xcol, f23h + w2, f23l + w2, b23 + i*T2,
                  BmCm, nullptr, nullptr, nullptr, nullptr, nullptr, nullptr, 512, 512);
        k_cb<<<ROWS/8,256>>>(BmCm, cb);
        // g = silu(softplus(xco@fc1+b) * xco * cb) * xres -> hi/lo (fused)
        lg<2,16,0>(dim3(4,128), xcoh, xcol, f1h + w2, f1l + w2, fc1_b + i*T2,
                  nullptr, gh, gl, xcoh, xcol, xr32, cb, 512, 512);
        // x = g @ out_W + b
        if (i < 2){
            lg<0,1,0>(dim3(2,128), gh, gl, oh + w1, ol + w1, out_b + i*TT,
                      x32, nullptr, nullptr, nullptr, nullptr, nullptr, nullptr, 512, 256);
            k_rms<<<ROWS,256>>>(x32, norm_w + (i+1)*TT, xnh, xnl);
        } else {
            lg<0,2,0>(dim3(2,128), gh, gl, oh + w1, ol + w1, out_b + i*TT,
                      nullptr, xh, xl, nullptr, nullptr, nullptr, nullptr, 512, 256);
        }
    }
    // dec = x @ proj_W + b
    lg<0,1,0>(dim3(2,128), xh, xl, ph_, pl_, proj_b,
              dec, nullptr, nullptr, nullptr, nullptr, nullptr, nullptr, 256, 256);
    k_out<<<(BB*TT*NV+255)/256,256>>>(dec, mean, stdv, (float*)d_out);
}

// round 12
// speedup vs baseline: 3.6760x; 1.3133x over previous
#include <cuda_runtime.h>
#include <cuda_fp16.h>
#include <math.h>
#include <stdint.h>

#define BB 32
#define TT 256
#define FF 512
#define MMK 4
#define NV 508
#define T2 512
#define ROWS (BB*FF)
typedef __half hf;
typedef long long ll;

// ---------------- scratch ----------------
__device__ float g_x32[ROWS*TT], g_xp32[ROWS*T2];
__device__ float g_BmCm[ROWS*T2], g_xr32[ROWS*T2], g_dec[ROWS*TT];
__device__ float g_cb[ROWS];
__device__ float g_mean[BB*NV], g_std[BB*NV];
__device__ float g_b23[3*T2];
__device__ hf g_xnh[ROWS*TT], g_xnl[ROWS*TT];
__device__ hf g_xpTh[ROWS*T2], g_xpTl[ROWS*T2];
__device__ hf g_xch[ROWS*T2], g_xcl[ROWS*T2];
__device__ hf g_xcoh[ROWS*T2], g_xcol[ROWS*T2];
__device__ hf g_gh[ROWS*T2], g_gl[ROWS*T2];
__device__ hf g_xh[ROWS*TT], g_xl[ROWS*TT];
__device__ hf w_inp[3*512*256];
__device__ hf w_cv [3*3*512*512];
__device__ hf w_cl [3*512*512];
__device__ hf w_f1 [3*512*512];
__device__ hf w_f23[3*512*512];
__device__ hf w_D  [3*512*256];
__device__ hf w_o  [3*256*512];
__device__ hf w_p  [256*256];

// ---------------- helpers ----------------
__device__ __forceinline__ float siluf(float x){ return x/(1.f+__expf(-x)); }
__device__ __forceinline__ float softplusf(float x){ return fmaxf(x,0.f)+log1pf(__expf(-fabsf(x))); }
__device__ __forceinline__ void splithf(float v, hf& h, hf& l){
    h = __float2half(v); l = __float2half(v - __half2float(h));
}
__device__ __forceinline__ void st_split2(hf* Ch, hf* Cl, ll off, float v0, float v1){
    hf h0,l0,h1,l1; splithf(v0,h0,l0); splithf(v1,h1,l1);
    *(__half2*)(Ch+off) = __halves2half2(h0,h1);
    *(__half2*)(Cl+off) = __halves2half2(l0,l1);
}
__device__ __forceinline__ uint32_t s2u(const void* p){
    uint32_t a; asm("{.reg .u64 t; cvta.to.shared.u64 t,%1; cvt.u32.u64 %0,t;}":"=r"(a):"l"(p)); return a;
}
__device__ __forceinline__ void cp16(uint32_t s, const void* g, int sz){
    asm volatile("cp.async.cg.shared.global [%0], [%1], 16, %2;"::"r"(s),"l"(g),"r"(sz):"memory");
}
__device__ __forceinline__ void ldsm4(uint32_t* r, uint32_t a){
    asm volatile("ldmatrix.sync.aligned.m8n8.x4.shared.b16 {%0,%1,%2,%3}, [%4];"
        :"=r"(r[0]),"=r"(r[1]),"=r"(r[2]),"=r"(r[3]):"r"(a));
}
__device__ __forceinline__ void mma16816(float* d, const uint32_t* a, const uint32_t* b){
    asm volatile("mma.sync.aligned.m16n8k16.row.col.f32.f16.f16.f32 "
        "{%0,%1,%2,%3}, {%4,%5,%6,%7}, {%8,%9}, {%0,%1,%2,%3};"
        : "+f"(d[0]),"+f"(d[1]),"+f"(d[2]),"+f"(d[3])
        : "r"(a[0]),"r"(a[1]),"r"(a[2]),"r"(a[3]), "r"(b[0]),"r"(b[1]));
}
// 64B-row swizzle, conflict-free for cp.async stores and all ldmatrix phases.
#define SW32(r,c) ((uint32_t)((r)*64 + (((c) ^ ((((r)>>1)&3)<<4)))))

// smem per stage: P0[128][64B] P1 P2 = 24KB; 2 stages = 48KB -> 2 CTAs/SM.
// P0 = A-hi (or conv weights); P1 = A-lo (or conv B-lo); P2 = B-hi.
#define ST_P1 8192
#define ST_P2 16384
#define ST_SZ 24576
#define SMEMSZ (2*ST_SZ)

// ---------------- 2-term fp16 HMMA GEMM ----------------
// Non-conv: D = (Ah+Al) @ W^T   (A activations 2-term, W weights 1-term)
// Conv:     D = W @ (Bh+Bl)^T   (A weights 1-term, B activations 2-term, 3-tap)
// CTA 128x128, 4 warps (64x64), K-chunk 32.
// ACT: 0 none, 1 silu, 2 softplus. OUTM: 1 fp32 ; 2 hi/lo split ; 16 fused s6-combine.
template<int ACT, int OUTM, int CONV>
__global__ void __launch_bounds__(128, 2) tc_gemm(
    const hf* __restrict__ A0, const hf* __restrict__ A1,
    const hf* __restrict__ B0, const hf* __restrict__ B1,
    const float* __restrict__ bias,
    float* __restrict__ C32, hf* __restrict__ Ch, hf* __restrict__ Cl,
    const hf* __restrict__ Xh, const hf* __restrict__ Xl,
    const float* __restrict__ Xf, const float* __restrict__ cbv,
    int Kd, int Nc)
{
    extern __shared__ __align__(1024) char sm[];
    uint32_t sb = s2u(sm);
    const int tid = threadIdx.x, lane = tid & 31, wid = tid >> 5;
    const int n0 = blockIdx.x*128, m0 = blockIdx.y*128, z = blockIdx.z;
    const int wm = (wid & 1) * 64, wn = (wid >> 1) * 64;
    const int NC = CONV ? 48 : (Kd >> 5);

    float acc[4][8][4];
    #pragma unroll
    for (int a = 0; a < 4; a++)
        #pragma unroll
        for (int b = 0; b < 8; b++)
            #pragma unroll
            for (int c = 0; c < 4; c++) acc[a][b][c] = 0.f;

    auto DO_LOAD = [&](int c){
        int tap = CONV ? (c >> 4) : 0;
        int k0  = (CONV ? (c & 15) : c) << 5;
        uint32_t st = sb + (c & 1) * ST_SZ;
        const hf* Aw = A0 + (CONV ? (ll)tap * 262144 : 0);
        #pragma unroll
        for (int rep = 0; rep < 4; rep++){
            int idx = rep * 128 + tid;            // 0..511
            int row = idx >> 2, ck = idx & 3;
            uint32_t so = SW32(row, ck * 16);
            ll aoff = (ll)(m0 + row) * Kd + k0 + ck * 8;
            cp16(st + so, Aw + aoff, 16);
            if (!CONV){
                cp16(st + ST_P1 + so, A1 + aoff, 16);
                ll boff = (ll)(n0 + row) * Kd + k0 + ck * 8;
                cp16(st + ST_P2 + so, B0 + boff, 16);
            } else {
                int lsrc = n0 + row + tap - 1;
                int ok = ((unsigned)lsrc < 512u) ? 16 : 0;
                ll boff = (ll)(z * 512 + lsrc) * 512 + k0 + ck * 8;
                cp16(st + ST_P1 + so, B1 + boff, ok);   // B-lo
                cp16(st + ST_P2 + so, B0 + boff, ok);   // B-hi
            }
        }
        asm volatile("cp.async.commit_group;":::"memory");
    };

    const int arow = (lane & 7) + ((lane >> 3) & 1) * 8;
    const int acolq = ((lane >> 4) & 1) * 16;
    const int brow = (lane & 7) + ((lane >> 4) & 1) * 8;
    const int bcolq = ((lane >> 3) & 1) * 16;

    DO_LOAD(0);
    for (int c = 0; c < NC; c++){
        if (c + 1 < NC){ DO_LOAD(c + 1); asm volatile("cp.async.wait_group 1;":::"memory"); }
        else           {                 asm volatile("cp.async.wait_group 0;":::"memory"); }
        __syncthreads();
        uint32_t st = sb + (c & 1) * ST_SZ;
        #pragma unroll
        for (int ks = 0; ks < 2; ks++){
            uint32_t a0[4][4], a1[4][4];
            #pragma unroll
            for (int mt = 0; mt < 4; mt++){
                int r = wm + mt*16 + arow;
                ldsm4(a0[mt], st + SW32(r, ks*32 + acolq));
                if (!CONV) ldsm4(a1[mt], st + ST_P1 + SW32(r, ks*32 + acolq));
            }
            #pragma unroll
            for (int np = 0; np < 4; np++){
                uint32_t b0[4], b1[4];
                int r = wn + np*16 + brow;
                ldsm4(b0, st + ST_P2 + SW32(r, ks*32 + bcolq));
                if (CONV) ldsm4(b1, st + ST_P1 + SW32(r, ks*32 + bcolq));
                #pragma unroll
                for (int half = 0; half < 2; half++){
                    #pragma unroll
                    for (int mt = 0; mt < 4; mt++){
                        float* d = acc[mt][np*2 + half];
                        mma16816(d, a0[mt], &b0[half*2]);
                        if (!CONV) mma16816(d, a1[mt], &b0[half*2]);
                        else       mma16816(d, a0[mt], &b1[half*2]);
                    }
                }
            }
        }
        __syncthreads();
    }

    // ---------------- epilogue ----------------
    const int g = lane >> 2, qp = (lane & 3) * 2;
    #pragma unroll
    for (int mt = 0; mt < 4; mt++){
        #pragma unroll
        for (int half = 0; half < 2; half++){
            int m = m0 + wm + mt*16 + g + half*8;
            ll crow = CONV ? ((ll)z * 512 + m) : (ll)m;
            float bv = CONV ? bias[m] : 0.f;
            float cbrow = (OUTM == 16) ? cbv[crow] : 0.f;
            #pragma unroll
            for (int nt = 0; nt < 8; nt++){
                int n = n0 + wn + nt*8 + qp;
                float v0 = acc[mt][nt][half*2 + 0];
                float v1 = acc[mt][nt][half*2 + 1];
                if (CONV){ v0 += bv; v1 += bv; } else { v0 += bias[n]; v1 += bias[n+1]; }
                if (ACT == 1){ v0 = siluf(v0); v1 = siluf(v1); }
                if (ACT == 2){ v0 = softplusf(v0); v1 = softplusf(v1); }
                ll o = crow * Nc + n;
                if (OUTM == 16){
                    float xc0 = __half2float(Xh[o])   + __half2float(Xl[o]);
                    float xc1 = __half2float(Xh[o+1]) + __half2float(Xl[o+1]);
                    v0 = siluf(v0 * xc0 * cbrow) * Xf[o];
                    v1 = siluf(v1 * xc1 * cbrow) * Xf[o+1];
                    st_split2(Ch, Cl, o, v0, v1);
                } else if (OUTM == 2){
                    st_split2(Ch, Cl, o, v0, v1);
                } else {
                    C32[o] = v0; C32[o+1] = v1;
                }
            }
        }
    }
}

// ---------------- aux kernels ----------------
// fused standardization + block-0 rmsnorm, smem-staged for coalesced writes
__global__ void k_norm(const float* __restrict__ xe, const float* __restrict__ xm,
                       const float* __restrict__ nw, hf* __restrict__ xnh, hf* __restrict__ xnl,
                       float* __restrict__ mean, float* __restrict__ stdv)
{
    extern __shared__ float tile[];                 // [64][257]
    __shared__ float ss[64][4], ss2[64][4];
    __shared__ float smu[64], sinv[64], ssc[64];
    int b = blockIdx.y, f0 = blockIdx.x*64;
    int tid = threadIdx.x, f = tid & 63, tg = tid >> 6;
    int gf = f0 + f;
    bool ismark = (gf >= NV);
    const float* src = ismark ? (xm + (ll)b*TT*MMK + (gf-NV)) : (xe + (ll)b*TT*NV + gf);
    int stride = ismark ? MMK : NV;
    float s = 0.f, s2 = 0.f;
    for (int t = tg; t < TT; t += 4){
        float v = src[(ll)t*stride];
        tile[f*257 + t] = v;
        s += v; s2 += v*v;
    }
    ss[f][tg] = s; ss2[f][tg] = s2;
    __syncthreads();
    if (tg == 0){
        float S = 0.f, S2 = 0.f;
        #pragma unroll
        for (int q = 0; q < 4; q++){ S += ss[f][q]; S2 += ss2[f][q]; }
        float mu, inv, m2;
        if (!ismark){
            mu = S * (1.f/256.f);
            float var = S2 * (1.f/256.f) - mu*mu;
            float sd = sqrtf(var + 1e-5f);
            inv = 1.f/sd;
            m2 = var / (var + 1e-5f);
            mean[b*NV+gf] = mu; stdv[b*NV+gf] = sd;
        } else { mu = 0.f; inv = 1.f; m2 = S2 * (1.f/256.f); }
        smu[f] = mu; sinv[f] = inv; ssc[f] = rsqrtf(m2 + 1e-5f);
    }
    __syncthreads();
    float wv = nw[tid];
    for (int fr = 0; fr < 64; fr++){
        float v = (tile[fr*257 + tid] - smu[fr]) * sinv[fr] * ssc[fr] * wv;
        hf h,l; splithf(v,h,l);
        ll o = ((ll)b*512 + f0 + fr) * TT + tid;
        xnh[o] = h; xnl[o] = l;
    }
}

__global__ void k_rms(const float* __restrict__ x, const float* __restrict__ w,
                      hf* __restrict__ oh, hf* __restrict__ ol)
{
    int r = blockIdx.x, t = threadIdx.x;
    __shared__ float red[256];
    float v = x[(ll)r*TT + t];
    red[t] = v*v; __syncthreads();
    for (int s = 128; s > 0; s >>= 1){ if (t < s) red[t] += red[t+s]; __syncthreads(); }
    float sc = rsqrtf(red[0]*(1.f/256.f) + 1e-5f);
    hf h,l; splithf(v*sc*w[t], h, l);
    oh[(ll)r*TT+t] = h; ol[(ll)r*TT+t] = l;
}

__global__ void k_trans(const float* __restrict__ xp, hf* __restrict__ th, hf* __restrict__ tl)
{
    __shared__ float tsm[32][33];
    int b = blockIdx.z, l0 = blockIdx.x*32, f0 = blockIdx.y*32;
    int tx = threadIdx.x, ty = threadIdx.y;
    for (int i = ty; i < 32; i += 8)
        tsm[i][tx] = xp[((ll)(b*512 + f0 + i))*512 + l0 + tx];
    __syncthreads();
    for (int i = ty; i < 32; i += 8){
        hf h,l; splithf(tsm[tx][i], h, l);
        ll o = ((ll)(b*512 + l0 + i))*512 + f0 + tx;
        th[o] = h; tl[o] = l;
    }
}

__global__ void k_cb(const float* __restrict__ BC, float* __restrict__ cb)
{
    int r = blockIdx.x*8 + (threadIdx.x >> 5), lane = threadIdx.x & 31;
    const float* p = BC + (ll)r*512;
    float s = 0.f;
    #pragma unroll
    for (int j = 0; j < 8; j++){ int c = lane*8 + j; s += p[c] * p[c+256]; }
    #pragma unroll
    for (int o = 16; o; o >>= 1) s += __shfl_xor_sync(0xFFFFFFFFu, s, o);
    if (lane == 0) cb[r] = s;
}

struct Seg { const float* src; hf* dst; int K, Nsrc, Ndst, colOff, nbat; };
struct PrepArgs { Seg s[8]; int cum[9]; };
__global__ void k_prep(PrepArgs a, int total)
{
    int i = blockIdx.x*256 + threadIdx.x;
    if (i >= total) return;
    int si = 0;
    #pragma unroll
    for (int q = 0; q < 7; q++) si += (i >= a.cum[q+1]);
    Seg sg = a.s[si];
    int r = i - a.cum[si];
    int per = sg.K * sg.Nsrc;
    int z = r / per, j = r % per;
    int k = j / sg.Nsrc, n = j % sg.Nsrc;
    ll d = (ll)z * sg.K * sg.Ndst + (ll)(sg.colOff + n) * sg.K + k;
    sg.dst[d] = __float2half(sg.src[(ll)z * per + j]);
}

__global__ void k_cprep(const float* __restrict__ W, hf* __restrict__ dst)
{
    int j = blockIdx.x*256 + threadIdx.x;
    if (j >= 786432) return;
    ll zo = (ll)blockIdx.z * 786432;
    int tap = j % 3, ii = (j/3) % 512, o = j / 1536;
    ll d = zo + (ll)tap*262144 + (ll)o*512 + ii;
    dst[d] = __float2half(W[zo + j]);
}

__global__ void k_bias23(const float* __restrict__ b2, const float* __restrict__ b3,
                         float* __restrict__ b23)
{
    int i = blockIdx.x*256 + threadIdx.x;
    if (i >= 3*T2) return;
    int z = i / T2, n = i % T2;
    b23[i] = (n < 256) ? b2[z*256 + n] : b3[z*256 + n - 256];
}

__global__ void k_out(const float* __restrict__ dec, const float* __restrict__ mean,
                      const float* __restrict__ stdv, float* __restrict__ out)
{
    int idx = blockIdx.x*256 + threadIdx.x;
    if (idx >= BB*TT*NV) return;
    int n = idx % NV, t = (idx/NV) % TT, b = idx/(NV*TT);
    out[idx] = dec[((ll)b*FF + n)*TT + t] * stdv[b*NV+n] + mean[b*NV+n];
}

// ---------------- launcher ----------------
#define GA(p, s) cudaGetSymbolAddress((void**)&p, s)

template<int ACT, int OUTM, int CONV>
static void lg(dim3 grid, const hf* A0, const hf* A1, const hf* B0, const hf* B1,
               const float* bias, float* C32, hf* Ch, hf* Cl,
               const hf* Xh, const hf* Xl, const float* Xf, const float* cbv,
               int Kd, int Nc)
{
    cudaFuncSetAttribute(tc_gemm<ACT,OUTM,CONV>, cudaFuncAttributeMaxDynamicSharedMemorySize, SMEMSZ);
    tc_gemm<ACT,OUTM,CONV><<<grid, 128, SMEMSZ>>>(A0, A1, B0, B1, bias, C32, Ch, Cl,
                                                  Xh, Xl, Xf, cbv, Kd, Nc);
}

extern "C" void kernel_launch(void* const* d_in, const int* in_sizes, int n_in,
                              void* d_out, int out_size)
{
    const float* x_enc  = (const float*)d_in[0];
    const float* x_mark = (const float*)d_in[1];
    const float* norm_w = (const float*)d_in[4];
    const float* inp_W  = (const float*)d_in[5];
    const float* inp_b  = (const float*)d_in[6];
    const float* conv_W = (const float*)d_in[7];
    const float* conv_b = (const float*)d_in[8];
    const float* cvl_W  = (const float*)d_in[9];
    const float* cvl_b  = (const float*)d_in[10];
    const float* fc1_W  = (const float*)d_in[11];
    const float* fc1_b  = (const float*)d_in[12];
    const float* fc2_W  = (const float*)d_in[13];
    const float* fc2_b  = (const float*)d_in[14];
    const float* fc3_W  = (const float*)d_in[15];
    const float* fc3_b  = (const float*)d_in[16];
    const float* D_W    = (const float*)d_in[17];
    const float* D_b    = (const float*)d_in[18];
    const float* out_W  = (const float*)d_in[19];
    const float* out_b  = (const float*)d_in[20];
    const float* proj_W = (const float*)d_in[21];
    const float* proj_b = (const float*)d_in[22];

    float *x32,*xp32,*BmCm,*xr32,*dec,*mean,*stdv,*cb,*b23;
    GA(x32,g_x32); GA(xp32,g_xp32); GA(BmCm,g_BmCm); GA(xr32,g_xr32);
    GA(dec,g_dec); GA(mean,g_mean); GA(stdv,g_std); GA(cb,g_cb); GA(b23,g_b23);
    hf *xnh,*xnl,*xpTh,*xpTl,*xch,*xcl,*xcoh,*xcol,*gh,*gl,*xh,*xl;
    GA(xnh,g_xnh); GA(xnl,g_xnl); GA(xpTh,g_xpTh); GA(xpTl,g_xpTl);
    GA(xch,g_xch); GA(xcl,g_xcl); GA(xcoh,g_xcoh); GA(xcol,g_xcol);
    GA(gh,g_gh); GA(gl,g_gl); GA(xh,g_xh); GA(xl,g_xl);
    hf *winp,*wcv,*wcl,*wf1,*wf23,*wD,*wo,*wp;
    GA(winp,w_inp); GA(wcv,w_cv); GA(wcl,w_cl); GA(wf1,w_f1);
    GA(wf23,w_f23); GA(wD,w_D); GA(wo,w_o); GA(wp,w_p);

    PrepArgs pa;
    pa.s[0] = { inp_W,  winp, 256, 512, 512, 0,   3 };
    pa.s[1] = { cvl_W,  wcl,  512, 512, 512, 0,   3 };
    pa.s[2] = { fc1_W,  wf1,  512, 512, 512, 0,   3 };
    pa.s[3] = { fc2_W,  wf23, 512, 256, 512, 0,   3 };
    pa.s[4] = { fc3_W,  wf23, 512, 256, 512, 256, 3 };
    pa.s[5] = { D_W,    wD,   256, 512, 512, 0,   3 };
    pa.s[6] = { out_W,  wo,   512, 256, 256, 0,   3 };
    pa.s[7] = { proj_W, wp,   256, 256, 256, 0,   1 };
    pa.cum[0] = 0;
    for (int q = 0; q < 8; q++)
        pa.cum[q+1] = pa.cum[q] + pa.s[q].K * pa.s[q].Nsrc * pa.s[q].nbat;
    int total = pa.cum[8];
    k_prep<<<(total + 255)/256, 256>>>(pa, total);
    k_cprep<<<dim3((786432+255)/256,1,3),256>>>(conv_W, wcv);
    k_bias23<<<(3*T2+255)/256,256>>>(fc2_b, fc3_b, b23);

    // fused input standardization + block-0 rmsnorm -> xn hi/lo (smem-staged)
    cudaFuncSetAttribute(k_norm, cudaFuncAttributeMaxDynamicSharedMemorySize, 64*257*4);
    k_norm<<<dim3(8,BB),256,64*257*4>>>(x_enc, x_mark, norm_w, xnh, xnl, mean, stdv);

    for (int i = 0; i < 3; i++){
        ll w2 = (ll)i*512*512, w1 = (ll)i*256*512, wc = (ll)i*786432, wo1 = (ll)i*512*256;
        // xp = xn @ inp_W + b -> fp32
        lg<0,1,0>(dim3(4,128), xnh, xnl, winp + w1, nullptr, inp_b + i*T2,
                  xp32, nullptr, nullptr, nullptr, nullptr, nullptr, nullptr, 256, 512);
        // xres = silu(xn @ D_W + b) -> fp32
        lg<1,1,0>(dim3(4,128), xnh, xnl, wD + w1, nullptr, D_b + i*T2,
                  xr32, nullptr, nullptr, nullptr, nullptr, nullptr, nullptr, 256, 512);
        // xp^T hi/lo
        k_trans<<<dim3(16,16,BB),dim3(32,8)>>>(xp32, xpTh, xpTl);
        // xc = silu(conv1d(xp) + conv_b) -> hi/lo   (A=weights 1-term, B=xpT 2-term)
        lg<1,2,1>(dim3(4,4,BB), wcv + wc, nullptr, xpTh, xpTl, conv_b + i*FF,
                  nullptr, xch, xcl, nullptr, nullptr, nullptr, nullptr, 512, 512);
        // xco = xc @ convlin_W + b -> hi/lo
        lg<0,2,0>(dim3(4,128), xch, xcl, wcl + w2, nullptr, cvl_b + i*T2,
                  nullptr, xcoh, xcol, nullptr, nullptr, nullptr, nullptr, 512, 512);
        // [Bm|Cm] = xco @ [fc2|fc3] + [b2|b3] -> fp32
        lg<0,1,0>(dim3(4,128), xcoh, xcol, wf23 + w2, nullptr, b23 + i*T2,
                  BmCm, nullptr, nullptr, nullptr, nullptr, nullptr, nullptr, 512, 512);
        k_cb<<<ROWS/8,256>>>(BmCm, cb);
        // g = silu(softplus(xco@fc1+b) * xco * cb) * xres -> hi/lo (fused)
        lg<2,16,0>(dim3(4,128), xcoh, xcol, wf1 + w2, nullptr, fc1_b + i*T2,
                  nullptr, gh, gl, xcoh, xcol, xr32, cb, 512, 512);
        // x = g @ out_W + b
        if (i < 2){
            lg<0,1,0>(dim3(2,128), gh, gl, wo + wo1, nullptr, out_b + i*TT,
                      x32, nullptr, nullptr, nullptr, nullptr, nullptr, nullptr, 512, 256);
            k_rms<<<ROWS,256>>>(x32, norm_w + (i+1)*TT, xnh, xnl);
        } else {
            lg<0,2,0>(dim3(2,128), gh, gl, wo + wo1, nullptr, out_b + i*TT,
                      nullptr, xh, xl, nullptr, nullptr, nullptr, nullptr, 512, 256);
        }
    }
    // dec = x @ proj_W + b
    lg<0,1,0>(dim3(2,128), xh, xl, wp, nullptr, proj_b,
              dec, nullptr, nullptr, nullptr, nullptr, nullptr, nullptr, 256, 256);
    k_out<<<(BB*TT*NV+255)/256,256>>>(dec, mean, stdv, (float*)d_out);
}

// round 14
// speedup vs baseline: 3.9722x; 1.0806x over previous
#include <cuda_runtime.h>
#include <cuda_fp16.h>
#include <math.h>
#include <stdint.h>

#define BB 32
#define TT 256
#define FF 512
#define MMK 4
#define NV 508
#define T2 512
#define ROWS (BB*FF)
typedef __half hf;
typedef long long ll;

// ---------------- scratch ----------------
__device__ float g_x32[ROWS*TT];
__device__ float g_xr32[ROWS*T2], g_dec[ROWS*TT];
__device__ float g_cb[ROWS], g_cbp[ROWS*4];
__device__ float g_mean[BB*NV], g_std[BB*NV];
__device__ float g_b23[3*T2];
__device__ hf g_xnh[ROWS*TT], g_xnl[ROWS*TT];
__device__ hf g_xpTh[ROWS*T2], g_xpTl[ROWS*T2];
__device__ hf g_xch[ROWS*T2], g_xcl[ROWS*T2];
__device__ hf g_xcoh[ROWS*T2], g_xcol[ROWS*T2];
__device__ hf g_gh[ROWS*T2], g_gl[ROWS*T2];
__device__ hf g_xh[ROWS*TT], g_xl[ROWS*TT];
__device__ hf w_inp[3*512*256];
__device__ hf w_cv [3*3*512*512];
__device__ hf w_cl [3*512*512];
__device__ hf w_f1 [3*512*512];
__device__ hf w_f23[3*512*512];
__device__ hf w_D  [3*512*256];
__device__ hf w_o  [3*256*512];
__device__ hf w_p  [256*256];

// ---------------- helpers ----------------
__device__ __forceinline__ float siluf(float x){ return x/(1.f+__expf(-x)); }
__device__ __forceinline__ float softplusf(float x){ return fmaxf(x,0.f)+log1pf(__expf(-fabsf(x))); }
__device__ __forceinline__ void splithf(float v, hf& h, hf& l){
    h = __float2half(v); l = __float2half(v - __half2float(h));
}
__device__ __forceinline__ void st_split2(hf* Ch, hf* Cl, ll off, float v0, float v1){
    hf h0,l0,h1,l1; splithf(v0,h0,l0); splithf(v1,h1,l1);
    *(__half2*)(Ch+off) = __halves2half2(h0,h1);
    *(__half2*)(Cl+off) = __halves2half2(l0,l1);
}
__device__ __forceinline__ uint32_t s2u(const void* p){
    uint32_t a; asm("{.reg .u64 t; cvta.to.shared.u64 t,%1; cvt.u32.u64 %0,t;}":"=r"(a):"l"(p)); return a;
}
__device__ __forceinline__ void cp16(uint32_t s, const void* g, int sz){
    asm volatile("cp.async.cg.shared.global [%0], [%1], 16, %2;"::"r"(s),"l"(g),"r"(sz):"memory");
}
__device__ __forceinline__ void ldsm4(uint32_t* r, uint32_t a){
    asm volatile("ldmatrix.sync.aligned.m8n8.x4.shared.b16 {%0,%1,%2,%3}, [%4];"
        :"=r"(r[0]),"=r"(r[1]),"=r"(r[2]),"=r"(r[3]):"r"(a));
}
__device__ __forceinline__ void mma16816(float* d, const uint32_t* a, const uint32_t* b){
    asm volatile("mma.sync.aligned.m16n8k16.row.col.f32.f16.f16.f32 "
        "{%0,%1,%2,%3}, {%4,%5,%6,%7}, {%8,%9}, {%0,%1,%2,%3};"
        : "+f"(d[0]),"+f"(d[1]),"+f"(d[2]),"+f"(d[3])
        : "r"(a[0]),"r"(a[1]),"r"(a[2]),"r"(a[3]), "r"(b[0]),"r"(b[1]));
}
// 64B-row swizzle, conflict-free for cp.async stores and all ldmatrix phases.
#define SW32(r,c) ((uint32_t)((r)*64 + (((c) ^ ((((r)>>1)&3)<<4)))))

// smem per stage: P0[128][64B] P1 P2 = 24KB; 2 stages = 48KB -> 2 CTAs/SM.
// Non-conv: P0=A-hi, P1=A-lo, P2=B(weights). CONV: P0=A(weights), P1=B-lo, P2=B-hi.
#define ST_P1 8192
#define ST_P2 16384
#define ST_SZ 24576
#define SMEMSZ (2*ST_SZ)

// ---------------- 2-term fp16 HMMA GEMM ----------------
// Non-conv: D = (Ah+Al) @ W^T.  CONV: D = W @ (Bh+Bl)^T, B batched by z, row bias;
// SHIFT adds 3-tap shifted accumulation over B rows.
// ACT: 0 none, 1 silu, 2 softplus.
// OUTM: 1 fp32 ; 2 hi/lo split ; 16 fused s6-combine ; 32 cb partial-dot (interleaved f23).
template<int ACT, int OUTM, int CONV, int SHIFT>
__global__ void __launch_bounds__(128, 2) tc_gemm(
    const hf* __restrict__ A0, const hf* __restrict__ A1,
    const hf* __restrict__ B0, const hf* __restrict__ B1,
    const float* __restrict__ bias,
    float* __restrict__ C32, hf* __restrict__ Ch, hf* __restrict__ Cl,
    const hf* __restrict__ Xh, const hf* __restrict__ Xl,
    const float* __restrict__ Xf, const float* __restrict__ cbv,
    int Kd, int Nc)
{
    extern __shared__ __align__(1024) char sm[];
    uint32_t sb = s2u(sm);
    const int tid = threadIdx.x, lane = tid & 31, wid = tid >> 5;
    const int n0 = blockIdx.x*128, m0 = blockIdx.y*128, z = blockIdx.z;
    const int wm = (wid & 1) * 64, wn = (wid >> 1) * 64;
    const int NC = SHIFT ? 48 : (Kd >> 5);

    float acc[4][8][4];
    #pragma unroll
    for (int a = 0; a < 4; a++)
        #pragma unroll
        for (int b = 0; b < 8; b++)
            #pragma unroll
            for (int c = 0; c < 4; c++) acc[a][b][c] = 0.f;

    auto DO_LOAD = [&](int c){
        int tap = SHIFT ? (c >> 4) : 0;
        int k0  = (SHIFT ? (c & 15) : c) << 5;
        uint32_t st = sb + (c & 1) * ST_SZ;
        const hf* Aw = A0 + (SHIFT ? (ll)tap * 262144 : 0);
        #pragma unroll
        for (int rep = 0; rep < 4; rep++){
            int idx = rep * 128 + tid;            // 0..511
            int row = idx >> 2, ck = idx & 3;
            uint32_t so = SW32(row, ck * 16);
            ll aoff = (ll)(m0 + row) * Kd + k0 + ck * 8;
            cp16(st + so, Aw + aoff, 16);
            if (!CONV){
                cp16(st + ST_P1 + so, A1 + aoff, 16);
                ll boff = (ll)(n0 + row) * Kd + k0 + ck * 8;
                cp16(st + ST_P2 + so, B0 + boff, 16);
            } else {
                int lsrc = n0 + row + (SHIFT ? (tap - 1) : 0);
                int ok = (!SHIFT || (unsigned)lsrc < 512u) ? 16 : 0;
                ll boff = (ll)(z * 512 + lsrc) * Kd + k0 + ck * 8;
                cp16(st + ST_P1 + so, B1 + boff, ok);   // B-lo
                cp16(st + ST_P2 + so, B0 + boff, ok);   // B-hi
            }
        }
        asm volatile("cp.async.commit_group;":::"memory");
    };

    const int arow = (lane & 7) + ((lane >> 3) & 1) * 8;
    const int acolq = ((lane >> 4) & 1) * 16;
    const int brow = (lane & 7) + ((lane >> 4) & 1) * 8;
    const int bcolq = ((lane >> 3) & 1) * 16;

    DO_LOAD(0);
    for (int c = 0; c < NC; c++){
        if (c + 1 < NC){ DO_LOAD(c + 1); asm volatile("cp.async.wait_group 1;":::"memory"); }
        else           {                 asm volatile("cp.async.wait_group 0;":::"memory"); }
        __syncthreads();
        uint32_t st = sb + (c & 1) * ST_SZ;
        #pragma unroll
        for (int ks = 0; ks < 2; ks++){
            uint32_t a0[4][4], a1[4][4];
            #pragma unroll
            for (int mt = 0; mt < 4; mt++){
                int r = wm + mt*16 + arow;
                ldsm4(a0[mt], st + SW32(r, ks*32 + acolq));
                if (!CONV) ldsm4(a1[mt], st + ST_P1 + SW32(r, ks*32 + acolq));
            }
            #pragma unroll
            for (int np = 0; np < 4; np++){
                uint32_t b0[4], b1[4];
                int r = wn + np*16 + brow;
                ldsm4(b0, st + ST_P2 + SW32(r, ks*32 + bcolq));
                if (CONV) ldsm4(b1, st + ST_P1 + SW32(r, ks*32 + bcolq));
                #pragma unroll
                for (int half = 0; half < 2; half++){
                    #pragma unroll
                    for (int mt = 0; mt < 4; mt++){
                        float* d = acc[mt][np*2 + half];
                        mma16816(d, a0[mt], &b0[half*2]);
                        if (!CONV) mma16816(d, a1[mt], &b0[half*2]);
                        else       mma16816(d, a0[mt], &b1[half*2]);
                    }
                }
            }
        }
        __syncthreads();
    }

    // ---------------- epilogue ----------------
    const int g = lane >> 2, qp = (lane & 3) * 2;

    if (OUTM == 32){
        // interleaved f23: (v0,v1) = (Bm_j, Cm_j); deterministic partial dot per CTA.
        float* part = (float*)sm;     // [128][2]
        #pragma unroll
        for (int mt = 0; mt < 4; mt++){
            #pragma unroll
            for (int half = 0; half < 2; half++){
                float s = 0.f;
                #pragma unroll
                for (int nt = 0; nt < 8; nt++){
                    int n = n0 + wn + nt*8 + qp;
                    float v0 = acc[mt][nt][half*2 + 0] + bias[n];
                    float v1 = acc[mt][nt][half*2 + 1] + bias[n+1];
                    s += v0 * v1;
                }
                s += __shfl_xor_sync(0xFFFFFFFFu, s, 1);
                s += __shfl_xor_sync(0xFFFFFFFFu, s, 2);
                if ((lane & 3) == 0)
                    part[(wm + mt*16 + g + half*8)*2 + (wid >> 1)] = s;
            }
        }
        __syncthreads();
        if (tid < 128)
            C32[((ll)m0 + tid)*4 + blockIdx.x] = part[tid*2] + part[tid*2 + 1];
        return;
    }

    #pragma unroll
    for (int mt = 0; mt < 4; mt++){
        #pragma unroll
        for (int half = 0; half < 2; half++){
            int m = m0 + wm + mt*16 + g + half*8;
            ll crow = CONV ? ((ll)z * 512 + m) : (ll)m;
            float bv = CONV ? bias[m] : 0.f;
            float cbrow = (OUTM == 16) ? cbv[crow] : 0.f;
            #pragma unroll
            for (int nt = 0; nt < 8; nt++){
                int n = n0 + wn + nt*8 + qp;
                float v0 = acc[mt][nt][half*2 + 0];
                float v1 = acc[mt][nt][half*2 + 1];
                if (CONV){ v0 += bv; v1 += bv; } else { v0 += bias[n]; v1 += bias[n+1]; }
                if (ACT == 1){ v0 = siluf(v0); v1 = siluf(v1); }
                if (ACT == 2){ v0 = softplusf(v0); v1 = softplusf(v1); }
                ll o = crow * Nc + n;
                if (OUTM == 16){
                    float xc0 = __half2float(Xh[o])   + __half2float(Xl[o]);
                    float xc1 = __half2float(Xh[o+1]) + __half2float(Xl[o+1]);
                    v0 = siluf(v0 * xc0 * cbrow) * Xf[o];
                    v1 = siluf(v1 * xc1 * cbrow) * Xf[o+1];
                    st_split2(Ch, Cl, o, v0, v1);
                } else if (OUTM == 2){
                    st_split2(Ch, Cl, o, v0, v1);
                } else {
                    C32[o] = v0; C32[o+1] = v1;
                }
            }
        }
    }
}

// ---------------- aux kernels ----------------
// fused standardization + block-0 rmsnorm; 32 features/block for occupancy
__global__ void k_norm(const float* __restrict__ xe, const float* __restrict__ xm,
                       const float* __restrict__ nw, hf* __restrict__ xnh, hf* __restrict__ xnl,
                       float* __restrict__ mean, float* __restrict__ stdv)
{
    extern __shared__ float tile[];                 // [32][257]
    __shared__ float ss[32][8], ss2[32][8];
    __shared__ float smu[32], sinv[32], ssc[32];
    int b = blockIdx.y, f0 = blockIdx.x*32;
    int tid = threadIdx.x, f = tid & 31, tg = tid >> 5;
    int gf = f0 + f;
    bool ismark = (gf >= NV);
    const float* src = ismark ? (xm + (ll)b*TT*MMK + (gf-NV)) : (xe + (ll)b*TT*NV + gf);
    int stride = ismark ? MMK : NV;
    float s = 0.f, s2 = 0.f;
    for (int t = tg; t < TT; t += 8){
        float v = src[(ll)t*stride];
        tile[f*257 + t] = v;
        s += v; s2 += v*v;
    }
    ss[f][tg] = s; ss2[f][tg] = s2;
    __syncthreads();
    if (tg == 0){
        float S = 0.f, S2 = 0.f;
        #pragma unroll
        for (int q = 0; q < 8; q++){ S += ss[f][q]; S2 += ss2[f][q]; }
        float mu, inv, m2;
        if (!ismark){
            mu = S * (1.f/256.f);
            float var = S2 * (1.f/256.f) - mu*mu;
            float sd = sqrtf(var + 1e-5f);
            inv = 1.f/sd;
            m2 = var / (var + 1e-5f);
            mean[b*NV+gf] = mu; stdv[b*NV+gf] = sd;
        } else { mu = 0.f; inv = 1.f; m2 = S2 * (1.f/256.f); }
        smu[f] = mu; sinv[f] = inv; ssc[f] = rsqrtf(m2 + 1e-5f);
    }
    __syncthreads();
    float wv = nw[tid];
    #pragma unroll 4
    for (int fr = 0; fr < 32; fr++){
        float v = (tile[fr*257 + tid] - smu[fr]) * sinv[fr] * ssc[fr] * wv;
        hf h,l; splithf(v,h,l);
        ll o = ((ll)b*512 + f0 + fr) * TT + tid;
        xnh[o] = h; xnl[o] = l;
    }
}

__global__ void k_rms(const float* __restrict__ x, const float* __restrict__ w,
                      hf* __restrict__ oh, hf* __restrict__ ol)
{
    int r = blockIdx.x, t = threadIdx.x;
    __shared__ float red[256];
    float v = x[(ll)r*TT + t];
    red[t] = v*v; __syncthreads();
    for (int s = 128; s > 0; s >>= 1){ if (t < s) red[t] += red[t+s]; __syncthreads(); }
    float sc = rsqrtf(red[0]*(1.f/256.f) + 1e-5f);
    hf h,l; splithf(v*sc*w[t], h, l);
    oh[(ll)r*TT+t] = h; ol[(ll)r*TT+t] = l;
}

__global__ void k_cb2(const float* __restrict__ cbp, float* __restrict__ cb)
{
    int r = blockIdx.x*256 + threadIdx.x;
    if (r < ROWS)
        cb[r] = (cbp[r*4+0] + cbp[r*4+1]) + (cbp[r*4+2] + cbp[r*4+3]);
}

struct Seg { const float* src; hf* dst; int K, Nsrc, Ndst, colOff, colStride, nbat; };
struct PrepArgs { Seg s[8]; int cum[9]; };
__global__ void k_prep(PrepArgs a, int total)
{
    int i = blockIdx.x*256 + threadIdx.x;
    if (i >= total) return;
    int si = 0;
    #pragma unroll
    for (int q = 0; q < 7; q++) si += (i >= a.cum[q+1]);
    Seg sg = a.s[si];
    int r = i - a.cum[si];
    int per = sg.K * sg.Nsrc;
    int z = r / per, j = r % per;
    int k = j / sg.Nsrc, n = j % sg.Nsrc;
    ll d = (ll)z * sg.K * sg.Ndst + (ll)(sg.colOff + n * sg.colStride) * sg.K + k;
    sg.dst[d] = __float2half(sg.src[(ll)z * per + j]);
}

__global__ void k_cprep(const float* __restrict__ W, hf* __restrict__ dst)
{
    int j = blockIdx.x*256 + threadIdx.x;
    if (j >= 786432) return;
    ll zo = (ll)blockIdx.z * 786432;
    int tap = j % 3, ii = (j/3) % 512, o = j / 1536;
    ll d = zo + (ll)tap*262144 + (ll)o*512 + ii;
    dst[d] = __float2half(W[zo + j]);
}

__global__ void k_bias23(const float* __restrict__ b2, const float* __restrict__ b3,
                         float* __restrict__ b23)
{
    int i = blockIdx.x*256 + threadIdx.x;
    if (i >= 3*T2) return;
    int z = i / T2, n = i % T2;
    b23[i] = (n & 1) ? b3[z*256 + (n>>1)] : b2[z*256 + (n>>1)];
}

__global__ void k_out(const float* __restrict__ dec, const float* __restrict__ mean,
                      const float* __restrict__ stdv, float* __restrict__ out)
{
    int idx = blockIdx.x*256 + threadIdx.x;
    if (idx >= BB*TT*NV) return;
    int n = idx % NV, t = (idx/NV) % TT, b = idx/(NV*TT);
    out[idx] = dec[((ll)b*FF + n)*TT + t] * stdv[b*NV+n] + mean[b*NV+n];
}

// ---------------- launcher ----------------
#define GA(p, s) cudaGetSymbolAddress((void**)&p, s)

template<int ACT, int OUTM, int CONV, int SHIFT>
static void lg(dim3 grid, const hf* A0, const hf* A1, const hf* B0, const hf* B1,
               const float* bias, float* C32, hf* Ch, hf* Cl,
               const hf* Xh, const hf* Xl, const float* Xf, const float* cbv,
               int Kd, int Nc)
{
    cudaFuncSetAttribute(tc_gemm<ACT,OUTM,CONV,SHIFT>, cudaFuncAttributeMaxDynamicSharedMemorySize, SMEMSZ);
    tc_gemm<ACT,OUTM,CONV,SHIFT><<<grid, 128, SMEMSZ>>>(A0, A1, B0, B1, bias, C32, Ch, Cl,
                                                        Xh, Xl, Xf, cbv, Kd, Nc);
}

extern "C" void kernel_launch(void* const* d_in, const int* in_sizes, int n_in,
                              void* d_out, int out_size)
{
    const float* x_enc  = (const float*)d_in[0];
    const float* x_mark = (const float*)d_in[1];
    const float* norm_w = (const float*)d_in[4];
    const float* inp_W  = (const float*)d_in[5];
    const float* inp_b  = (const float*)d_in[6];
    const float* conv_W = (const float*)d_in[7];
    const float* conv_b = (const float*)d_in[8];
    const float* cvl_W  = (const float*)d_in[9];
    const float* cvl_b  = (const float*)d_in[10];
    const float* fc1_W  = (const float*)d_in[11];
    const float* fc1_b  = (const float*)d_in[12];
    const float* fc2_W  = (const float*)d_in[13];
    const float* fc2_b  = (const float*)d_in[14];
    const float* fc3_W  = (const float*)d_in[15];
    const float* fc3_b  = (const float*)d_in[16];
    const float* D_W    = (const float*)d_in[17];
    const float* D_b    = (const float*)d_in[18];
    const float* out_W  = (const float*)d_in[19];
    const float* out_b  = (const float*)d_in[20];
    const float* proj_W = (const float*)d_in[21];
    const float* proj_b = (const float*)d_in[22];

    float *x32,*xr32,*dec,*mean,*stdv,*cb,*cbp,*b23;
    GA(x32,g_x32); GA(xr32,g_xr32); GA(dec,g_dec); GA(mean,g_mean); GA(stdv,g_std);
    GA(cb,g_cb); GA(cbp,g_cbp); GA(b23,g_b23);
    hf *xnh,*xnl,*xpTh,*xpTl,*xch,*xcl,*xcoh,*xcol,*gh,*gl,*xh,*xl;
    GA(xnh,g_xnh); GA(xnl,g_xnl); GA(xpTh,g_xpTh); GA(xpTl,g_xpTl);
    GA(xch,g_xch); GA(xcl,g_xcl); GA(xcoh,g_xcoh); GA(xcol,g_xcol);
    GA(gh,g_gh); GA(gl,g_gl); GA(xh,g_xh); GA(xl,g_xl);
    hf *winp,*wcv,*wcl,*wf1,*wf23,*wD,*wo,*wp;
    GA(winp,w_inp); GA(wcv,w_cv); GA(wcl,w_cl); GA(wf1,w_f1);
    GA(wf23,w_f23); GA(wD,w_D); GA(wo,w_o); GA(wp,w_p);

    PrepArgs pa;
    pa.s[0] = { inp_W,  winp, 256, 512, 512, 0, 1, 3 };
    pa.s[1] = { cvl_W,  wcl,  512, 512, 512, 0, 1, 3 };
    pa.s[2] = { fc1_W,  wf1,  512, 512, 512, 0, 1, 3 };
    pa.s[3] = { fc2_W,  wf23, 512, 256, 512, 0, 2, 3 };   // even cols
    pa.s[4] = { fc3_W,  wf23, 512, 256, 512, 1, 2, 3 };   // odd cols
    pa.s[5] = { D_W,    wD,   256, 512, 512, 0, 1, 3 };
    pa.s[6] = { out_W,  wo,   512, 256, 256, 0, 1, 3 };
    pa.s[7] = { proj_W, wp,   256, 256, 256, 0, 1, 1 };
    pa.cum[0] = 0;
    for (int q = 0; q < 8; q++)
        pa.cum[q+1] = pa.cum[q] + pa.s[q].K * pa.s[q].Nsrc * pa.s[q].nbat;
    int total = pa.cum[8];
    k_prep<<<(total + 255)/256, 256>>>(pa, total);
    k_cprep<<<dim3((786432+255)/256,1,3),256>>>(conv_W, wcv);
    k_bias23<<<(3*T2+255)/256,256>>>(fc2_b, fc3_b, b23);

    // fused input standardization + block-0 rmsnorm -> xn hi/lo
    cudaFuncSetAttribute(k_norm, cudaFuncAttributeMaxDynamicSharedMemorySize, 32*257*4);
    k_norm<<<dim3(16,BB),256,32*257*4>>>(x_enc, x_mark, norm_w, xnh, xnl, mean, stdv);

    for (int i = 0; i < 3; i++){
        ll w2 = (ll)i*512*512, w1 = (ll)i*256*512, wc = (ll)i*786432, wo1 = (ll)i*512*256;
        // xpT[(b,l)][f] = W^T @ xn_b^T + b[l]  (batched, no shift) -> hi/lo
        lg<0,2,1,0>(dim3(4,4,BB), winp + w1, nullptr, xnh, xnl, inp_b + i*T2,
                  nullptr, xpTh, xpTl, nullptr, nullptr, nullptr, nullptr, 256, 512);
        // xres = silu(xn @ D_W + b) -> fp32
        lg<1,1,0,0>(dim3(4,128), xnh, xnl, wD + w1, nullptr, D_b + i*T2,
                  xr32, nullptr, nullptr, nullptr, nullptr, nullptr, nullptr, 256, 512);
        // xc = silu(conv1d(xp) + conv_b) -> hi/lo  (3-tap shifted batched)
        lg<1,2,1,1>(dim3(4,4,BB), wcv + wc, nullptr, xpTh, xpTl, conv_b + i*FF,
                  nullptr, xch, xcl, nullptr, nullptr, nullptr, nullptr, 512, 512);
        // xco = xc @ convlin_W + b -> hi/lo
        lg<0,2,0,0>(dim3(4,128), xch, xcl, wcl + w2, nullptr, cvl_b + i*T2,
                  nullptr, xcoh, xcol, nullptr, nullptr, nullptr, nullptr, 512, 512);
        // interleaved [Bm|Cm] GEMM with fused partial row-dot -> cbp
        lg<0,32,0,0>(dim3(4,128), xcoh, xcol, wf23 + w2, nullptr, b23 + i*T2,
                  cbp, nullptr, nullptr, nullptr, nullptr, nullptr, nullptr, 512, 512);
        k_cb2<<<ROWS/256,256>>>(cbp, cb);
        // g = silu(softplus(xco@fc1+b) * xco * cb) * xres -> hi/lo (fused)
        lg<2,16,0,0>(dim3(4,128), xcoh, xcol, wf1 + w2, nullptr, fc1_b + i*T2,
                  nullptr, gh, gl, xcoh, xcol, xr32, cb, 512, 512);
        // x = g @ out_W + b
        if (i < 2){
            lg<0,1,0,0>(dim3(2,128), gh, gl, wo + wo1, nullptr, out_b + i*TT,
                      x32, nullptr, nullptr, nullptr, nullptr, nullptr, nullptr, 512, 256);
            k_rms<<<ROWS,256>>>(x32, norm_w + (i+1)*TT, xnh, xnl);
        } else {
            lg<0,2,0,0>(dim3(2,128), gh, gl, wo + wo1, nullptr, out_b + i*TT,
                      nullptr, xh, xl, nullptr, nullptr, nullptr, nullptr, 512, 256);
        }
    }
    // dec = x @ proj_W + b
    lg<0,1,0,0>(dim3(2,128), xh, xl, wp, nullptr, proj_b,
              dec, nullptr, nullptr, nullptr, nullptr, nullptr, nullptr, 256, 256);
    k_out<<<(BB*TT*NV+255)/256,256>>>(dec, mean, stdv, (float*)d_out);
}

// round 16
// speedup vs baseline: 5.4480x; 1.3715x over previous
#include <cuda_runtime.h>
#include <cuda_fp16.h>
#include <math.h>
#include <stdint.h>

#define BB 32
#define TT 256
#define FF 512
#define MMK 4
#define NV 508
#define T2 512
#define ROWS (BB*FF)
typedef __half hf;
typedef long long ll;

// ---------------- scratch (single fp16 activation planes) ----------------
__device__ float g_x32[ROWS*TT];
__device__ float g_xr32[ROWS*T2], g_dec[ROWS*TT];
__device__ float g_cb[ROWS], g_cbp[ROWS*4];
__device__ float g_mean[BB*NV], g_std[BB*NV];
__device__ float g_b23[3*T2];
__device__ hf g_xn [ROWS*TT];
__device__ hf g_xpT[ROWS*T2];
__device__ hf g_xc [ROWS*T2];
__device__ hf g_xco[ROWS*T2];
__device__ hf g_g  [ROWS*T2];
__device__ hf g_x  [ROWS*TT];
__device__ hf w_inp[3*512*256];
__device__ hf w_cv [3*3*512*512];
__device__ hf w_cl [3*512*512];
__device__ hf w_f1 [3*512*512];
__device__ hf w_f23[3*512*512];
__device__ hf w_D  [3*512*256];
__device__ hf w_o  [3*256*512];
__device__ hf w_p  [256*256];

// ---------------- helpers ----------------
__device__ __forceinline__ float siluf(float x){ return x/(1.f+__expf(-x)); }
__device__ __forceinline__ float softplusf(float x){ return fmaxf(x,0.f)+log1pf(__expf(-fabsf(x))); }
__device__ __forceinline__ void st_h2(hf* C, ll off, float v0, float v1){
    *(__half2*)(C+off) = __floats2half2_rn(v0, v1);
}
__device__ __forceinline__ uint32_t s2u(const void* p){
    uint32_t a; asm("{.reg .u64 t; cvta.to.shared.u64 t,%1; cvt.u32.u64 %0,t;}":"=r"(a):"l"(p)); return a;
}
__device__ __forceinline__ void cp16(uint32_t s, const void* g, int sz){
    asm volatile("cp.async.cg.shared.global [%0], [%1], 16, %2;"::"r"(s),"l"(g),"r"(sz):"memory");
}
__device__ __forceinline__ void ldsm4(uint32_t* r, uint32_t a){
    asm volatile("ldmatrix.sync.aligned.m8n8.x4.shared.b16 {%0,%1,%2,%3}, [%4];"
        :"=r"(r[0]),"=r"(r[1]),"=r"(r[2]),"=r"(r[3]):"r"(a));
}
__device__ __forceinline__ void mma16816(float* d, const uint32_t* a, const uint32_t* b){
    asm volatile("mma.sync.aligned.m16n8k16.row.col.f32.f16.f16.f32 "
        "{%0,%1,%2,%3}, {%4,%5,%6,%7}, {%8,%9}, {%0,%1,%2,%3};"
        : "+f"(d[0]),"+f"(d[1]),"+f"(d[2]),"+f"(d[3])
        : "r"(a[0]),"r"(a[1]),"r"(a[2]),"r"(a[3]), "r"(b[0]),"r"(b[1]));
}
// 64B-row swizzle, conflict-free for cp.async stores and all ldmatrix phases.
#define SW32(r,c) ((uint32_t)((r)*64 + (((c) ^ ((((r)>>1)&3)<<4)))))

// smem per stage: A[128][64B] + B[128][64B] = 16KB; 2 stages = 32KB -> 2 CTAs/SM.
#define ST_P1 8192
#define ST_SZ 16384
#define SMEMSZ (2*ST_SZ)

// ---------------- 1-term fp16 HMMA GEMM ----------------
// Non-conv: D = A @ W^T (A activation rows, W weight rows, bias per col).
// CONV: D = W @ B^T, B batched by z, bias per row; SHIFT adds 3-tap shifted accumulation.
// ACT: 0 none, 1 silu, 2 softplus.
// OUTM: 1 fp32 ; 2 fp16 ; 16 fused s6-combine ; 32 cb partial-dot (interleaved f23).
template<int ACT, int OUTM, int CONV, int SHIFT>
__global__ void __launch_bounds__(128, 2) tc_gemm(
    const hf* __restrict__ A, const hf* __restrict__ B,
    const float* __restrict__ bias,
    float* __restrict__ C32, hf* __restrict__ Cf,
    const hf* __restrict__ Xp, const float* __restrict__ Xf,
    const float* __restrict__ cbv,
    int Kd, int Nc)
{
    extern __shared__ __align__(1024) char sm[];
    uint32_t sb = s2u(sm);
    const int tid = threadIdx.x, lane = tid & 31, wid = tid >> 5;
    const int n0 = blockIdx.x*128, m0 = blockIdx.y*128, z = blockIdx.z;
    const int wm = (wid & 1) * 64, wn = (wid >> 1) * 64;
    const int NC = SHIFT ? 48 : (Kd >> 5);

    float acc[4][8][4];
    #pragma unroll
    for (int a = 0; a < 4; a++)
        #pragma unroll
        for (int b = 0; b < 8; b++)
            #pragma unroll
            for (int c = 0; c < 4; c++) acc[a][b][c] = 0.f;

    auto DO_LOAD = [&](int c){
        int tap = SHIFT ? (c >> 4) : 0;
        int k0  = (SHIFT ? (c & 15) : c) << 5;
        uint32_t st = sb + (c & 1) * ST_SZ;
        const hf* Aw = A + (SHIFT ? (ll)tap * 262144 : 0);
        #pragma unroll
        for (int rep = 0; rep < 4; rep++){
            int idx = rep * 128 + tid;            // 0..511
            int row = idx >> 2, ck = idx & 3;
            uint32_t so = SW32(row, ck * 16);
            cp16(st + so, Aw + (ll)(m0 + row) * Kd + k0 + ck * 8, 16);
            if (!CONV){
                cp16(st + ST_P1 + so, B + (ll)(n0 + row) * Kd + k0 + ck * 8, 16);
            } else {
                int lsrc = n0 + row + (SHIFT ? (tap - 1) : 0);
                int ok = (!SHIFT || (unsigned)lsrc < 512u) ? 16 : 0;
                cp16(st + ST_P1 + so, B + (ll)(z * 512 + lsrc) * Kd + k0 + ck * 8, ok);
            }
        }
        asm volatile("cp.async.commit_group;":::"memory");
    };

    const int arow = (lane & 7) + ((lane >> 3) & 1) * 8;
    const int acolq = ((lane >> 4) & 1) * 16;
    const int brow = (lane & 7) + ((lane >> 4) & 1) * 8;
    const int bcolq = ((lane >> 3) & 1) * 16;

    DO_LOAD(0);
    for (int c = 0; c < NC; c++){
        if (c + 1 < NC){ DO_LOAD(c + 1); asm volatile("cp.async.wait_group 1;":::"memory"); }
        else           {                 asm volatile("cp.async.wait_group 0;":::"memory"); }
        __syncthreads();
        uint32_t st = sb + (c & 1) * ST_SZ;
        #pragma unroll
        for (int ks = 0; ks < 2; ks++){
            uint32_t a0[4][4];
            #pragma unroll
            for (int mt = 0; mt < 4; mt++)
                ldsm4(a0[mt], st + SW32(wm + mt*16 + arow, ks*32 + acolq));
            #pragma unroll
            for (int np = 0; np < 4; np++){
                uint32_t b0[4];
                ldsm4(b0, st + ST_P1 + SW32(wn + np*16 + brow, ks*32 + bcolq));
                #pragma unroll
                for (int half = 0; half < 2; half++)
                    #pragma unroll
                    for (int mt = 0; mt < 4; mt++)
                        mma16816(acc[mt][np*2 + half], a0[mt], &b0[half*2]);
            }
        }
        __syncthreads();
    }

    // ---------------- epilogue ----------------
    const int g = lane >> 2, qp = (lane & 3) * 2;

    if (OUTM == 32){
        // interleaved f23: (v0,v1) = (Bm_j, Cm_j); deterministic partial dot per CTA.
        float* part = (float*)sm;     // [128][2]
        #pragma unroll
        for (int mt = 0; mt < 4; mt++){
            #pragma unroll
            for (int half = 0; half < 2; half++){
                float s = 0.f;
                #pragma unroll
                for (int nt = 0; nt < 8; nt++){
                    int n = n0 + wn + nt*8 + qp;
                    float v0 = acc[mt][nt][half*2 + 0] + bias[n];
                    float v1 = acc[mt][nt][half*2 + 1] + bias[n+1];
                    s += v0 * v1;
                }
                s += __shfl_xor_sync(0xFFFFFFFFu, s, 1);
                s += __shfl_xor_sync(0xFFFFFFFFu, s, 2);
                if ((lane & 3) == 0)
                    part[(wm + mt*16 + g + half*8)*2 + (wid >> 1)] = s;
            }
        }
        __syncthreads();
        if (tid < 128)
            C32[((ll)m0 + tid)*4 + blockIdx.x] = part[tid*2] + part[tid*2 + 1];
        return;
    }

    #pragma unroll
    for (int mt = 0; mt < 4; mt++){
        #pragma unroll
        for (int half = 0; half < 2; half++){
            int m = m0 + wm + mt*16 + g + half*8;
            ll crow = CONV ? ((ll)z * 512 + m) : (ll)m;
            float bv = CONV ? bias[m] : 0.f;
            float cbrow = (OUTM == 16) ? cbv[crow] : 0.f;
            #pragma unroll
            for (int nt = 0; nt < 8; nt++){
                int n = n0 + wn + nt*8 + qp;
                float v0 = acc[mt][nt][half*2 + 0];
                float v1 = acc[mt][nt][half*2 + 1];
                if (CONV){ v0 += bv; v1 += bv; } else { v0 += bias[n]; v1 += bias[n+1]; }
                if (ACT == 1){ v0 = siluf(v0); v1 = siluf(v1); }
                if (ACT == 2){ v0 = softplusf(v0); v1 = softplusf(v1); }
                ll o = crow * Nc + n;
                if (OUTM == 16){
                    float xc0 = __half2float(Xp[o]);
                    float xc1 = __half2float(Xp[o+1]);
                    v0 = siluf(v0 * xc0 * cbrow) * Xf[o];
                    v1 = siluf(v1 * xc1 * cbrow) * Xf[o+1];
                    st_h2(Cf, o, v0, v1);
                } else if (OUTM == 2){
                    st_h2(Cf, o, v0, v1);
                } else {
                    C32[o] = v0; C32[o+1] = v1;
                }
            }
        }
    }
}

// ---------------- aux kernels ----------------
// fused standardization + block-0 rmsnorm; 32 features/block
__global__ void k_norm(const float* __restrict__ xe, const float* __restrict__ xm,
                       const float* __restrict__ nw, hf* __restrict__ xn,
                       float* __restrict__ mean, float* __restrict__ stdv)
{
    extern __shared__ float tile[];                 // [32][257]
    __shared__ float ss[32][8], ss2[32][8];
    __shared__ float smu[32], sinv[32], ssc[32];
    int b = blockIdx.y, f0 = blockIdx.x*32;
    int tid = threadIdx.x, f = tid & 31, tg = tid >> 5;
    int gf = f0 + f;
    bool ismark = (gf >= NV);
    const float* src = ismark ? (xm + (ll)b*TT*MMK + (gf-NV)) : (xe + (ll)b*TT*NV + gf);
    int stride = ismark ? MMK : NV;
    float s = 0.f, s2 = 0.f;
    for (int t = tg; t < TT; t += 8){
        float v = src[(ll)t*stride];
        tile[f*257 + t] = v;
        s += v; s2 += v*v;
    }
    ss[f][tg] = s; ss2[f][tg] = s2;
    __syncthreads();
    if (tg == 0){
        float S = 0.f, S2 = 0.f;
        #pragma unroll
        for (int q = 0; q < 8; q++){ S += ss[f][q]; S2 += ss2[f][q]; }
        float mu, inv, m2;
        if (!ismark){
            mu = S * (1.f/256.f);
            float var = S2 * (1.f/256.f) - mu*mu;
            float sd = sqrtf(var + 1e-5f);
            inv = 1.f/sd;
            m2 = var / (var + 1e-5f);
            mean[b*NV+gf] = mu; stdv[b*NV+gf] = sd;
        } else { mu = 0.f; inv = 1.f; m2 = S2 * (1.f/256.f); }
        smu[f] = mu; sinv[f] = inv; ssc[f] = rsqrtf(m2 + 1e-5f);
    }
    __syncthreads();
    float wv = nw[tid];
    #pragma unroll 4
    for (int fr = 0; fr < 32; fr++){
        float v = (tile[fr*257 + tid] - smu[fr]) * sinv[fr] * ssc[fr] * wv;
        xn[((ll)b*512 + f0 + fr) * TT + tid] = __float2half(v);
    }
}

__global__ void k_rms(const float* __restrict__ x, const float* __restrict__ w,
                      hf* __restrict__ o)
{
    int r = blockIdx.x, t = threadIdx.x;
    __shared__ float red[256];
    float v = x[(ll)r*TT + t];
    red[t] = v*v; __syncthreads();
    for (int s = 128; s > 0; s >>= 1){ if (t < s) red[t] += red[t+s]; __syncthreads(); }
    float sc = rsqrtf(red[0]*(1.f/256.f) + 1e-5f);
    o[(ll)r*TT+t] = __float2half(v*sc*w[t]);
}

__global__ void k_cb2(const float* __restrict__ cbp, float* __restrict__ cb)
{
    int r = blockIdx.x*256 + threadIdx.x;
    if (r < ROWS)
        cb[r] = (cbp[r*4+0] + cbp[r*4+1]) + (cbp[r*4+2] + cbp[r*4+3]);
}

struct Seg { const float* src; hf* dst; int K, Nsrc, Ndst, colOff, colStride, nbat; };
struct PrepArgs { Seg s[8]; int cum[9]; };
__global__ void k_prep(PrepArgs a, int total)
{
    int i = blockIdx.x*256 + threadIdx.x;
    if (i >= total) return;
    int si = 0;
    #pragma unroll
    for (int q = 0; q < 7; q++) si += (i >= a.cum[q+1]);
    Seg sg = a.s[si];
    int r = i - a.cum[si];
    int per = sg.K * sg.Nsrc;
    int z = r / per, j = r % per;
    int k = j / sg.Nsrc, n = j % sg.Nsrc;
    ll d = (ll)z * sg.K * sg.Ndst + (ll)(sg.colOff + n * sg.colStride) * sg.K + k;
    sg.dst[d] = __float2half(sg.src[(ll)z * per + j]);
}

__global__ void k_cprep(const float* __restrict__ W, hf* __restrict__ dst)
{
    int j = blockIdx.x*256 + threadIdx.x;
    if (j >= 786432) return;
    ll zo = (ll)blockIdx.z * 786432;
    int tap = j % 3, ii = (j/3) % 512, o = j / 1536;
    ll d = zo + (ll)tap*262144 + (ll)o*512 + ii;
    dst[d] = __float2half(W[zo + j]);
}

__global__ void k_bias23(const float* __restrict__ b2, const float* __restrict__ b3,
                         float* __restrict__ b23)
{
    int i = blockIdx.x*256 + threadIdx.x;
    if (i >= 3*T2) return;
    int z = i / T2, n = i % T2;
    b23[i] = (n & 1) ? b3[z*256 + (n>>1)] : b2[z*256 + (n>>1)];
}

__global__ void k_out(const float* __restrict__ dec, const float* __restrict__ mean,
                      const float* __restrict__ stdv, float* __restrict__ out)
{
    int idx = blockIdx.x*256 + threadIdx.x;
    if (idx >= BB*TT*NV) return;
    int n = idx % NV, t = (idx/NV) % TT, b = idx/(NV*TT);
    out[idx] = dec[((ll)b*FF + n)*TT + t] * stdv[b*NV+n] + mean[b*NV+n];
}

// ---------------- launcher ----------------
#define GA(p, s) cudaGetSymbolAddress((void**)&p, s)

template<int ACT, int OUTM, int CONV, int SHIFT>
static void lg(dim3 grid, const hf* A, const hf* B, const float* bias,
               float* C32, hf* Cf, const hf* Xp, const float* Xf,
               const float* cbv, int Kd, int Nc)
{
    cudaFuncSetAttribute(tc_gemm<ACT,OUTM,CONV,SHIFT>, cudaFuncAttributeMaxDynamicSharedMemorySize, SMEMSZ);
    tc_gemm<ACT,OUTM,CONV,SHIFT><<<grid, 128, SMEMSZ>>>(A, B, bias, C32, Cf, Xp, Xf, cbv, Kd, Nc);
}

extern "C" void kernel_launch(void* const* d_in, const int* in_sizes, int n_in,
                              void* d_out, int out_size)
{
    const float* x_enc  = (const float*)d_in[0];
    const float* x_mark = (const float*)d_in[1];
    const float* norm_w = (const float*)d_in[4];
    const float* inp_W  = (const float*)d_in[5];
    const float* inp_b  = (const float*)d_in[6];
    const float* conv_W = (const float*)d_in[7];
    const float* conv_b = (const float*)d_in[8];
    const float* cvl_W  = (const float*)d_in[9];
    const float* cvl_b  = (const float*)d_in[10];
    const float* fc1_W  = (const float*)d_in[11];
    const float* fc1_b  = (const float*)d_in[12];
    const float* fc2_W  = (const float*)d_in[13];
    const float* fc2_b  = (const float*)d_in[14];
    const float* fc3_W  = (const float*)d_in[15];
    const float* fc3_b  = (const float*)d_in[16];
    const float* D_W    = (const float*)d_in[17];
    const float* D_b    = (const float*)d_in[18];
    const float* out_W  = (const float*)d_in[19];
    const float* out_b  = (const float*)d_in[20];
    const float* proj_W = (const float*)d_in[21];
    const float* proj_b = (const float*)d_in[22];

    float *x32,*xr32,*dec,*mean,*stdv,*cb,*cbp,*b23;
    GA(x32,g_x32); GA(xr32,g_xr32); GA(dec,g_dec); GA(mean,g_mean); GA(stdv,g_std);
    GA(cb,g_cb); GA(cbp,g_cbp); GA(b23,g_b23);
    hf *xn,*xpT,*xc,*xco,*gp,*xp;
    GA(xn,g_xn); GA(xpT,g_xpT); GA(xc,g_xc); GA(xco,g_xco); GA(gp,g_g); GA(xp,g_x);
    hf *winp,*wcv,*wcl,*wf1,*wf23,*wD,*wo,*wp;
    GA(winp,w_inp); GA(wcv,w_cv); GA(wcl,w_cl); GA(wf1,w_f1);
    GA(wf23,w_f23); GA(wD,w_D); GA(wo,w_o); GA(wp,w_p);

    PrepArgs pa;
    pa.s[0] = { inp_W,  winp, 256, 512, 512, 0, 1, 3 };
    pa.s[1] = { cvl_W,  wcl,  512, 512, 512, 0, 1, 3 };
    pa.s[2] = { fc1_W,  wf1,  512, 512, 512, 0, 1, 3 };
    pa.s[3] = { fc2_W,  wf23, 512, 256, 512, 0, 2, 3 };   // even cols
    pa.s[4] = { fc3_W,  wf23, 512, 256, 512, 1, 2, 3 };   // odd cols
    pa.s[5] = { D_W,    wD,   256, 512, 512, 0, 1, 3 };
    pa.s[6] = { out_W,  wo,   512, 256, 256, 0, 1, 3 };
    pa.s[7] = { proj_W, wp,   256, 256, 256, 0, 1, 1 };
    pa.cum[0] = 0;
    for (int q = 0; q < 8; q++)
        pa.cum[q+1] = pa.cum[q] + pa.s[q].K * pa.s[q].Nsrc * pa.s[q].nbat;
    int total = pa.cum[8];
    k_prep<<<(total + 255)/256, 256>>>(pa, total);
    k_cprep<<<dim3((786432+255)/256,1,3),256>>>(conv_W, wcv);
    k_bias23<<<(3*T2+255)/256,256>>>(fc2_b, fc3_b, b23);

    cudaFuncSetAttribute(k_norm, cudaFuncAttributeMaxDynamicSharedMemorySize, 32*257*4);
    k_norm<<<dim3(16,BB),256,32*257*4>>>(x_enc, x_mark, norm_w, xn, mean, stdv);

    for (int i = 0; i < 3; i++){
        ll w2 = (ll)i*512*512, w1 = (ll)i*256*512, wc = (ll)i*786432, wo1 = (ll)i*512*256;
        // xpT[(b,l)][f] = W^T @ xn_b^T + b[l]  (batched, no shift)
        lg<0,2,1,0>(dim3(4,4,BB), winp + w1, xn, inp_b + i*T2,
                  nullptr, xpT, nullptr, nullptr, nullptr, 256, 512);
        // xres = silu(xn @ D_W + b) -> fp32
        lg<1,1,0,0>(dim3(4,128), xn, wD + w1, D_b + i*T2,
                  xr32, nullptr, nullptr, nullptr, nullptr, 256, 512);
        // xc = silu(conv1d(xp) + conv_b)  (3-tap shifted batched)
        lg<1,2,1,1>(dim3(4,4,BB), wcv + wc, xpT, conv_b + i*FF,
                  nullptr, xc, nullptr, nullptr, nullptr, 512, 512);
        // xco = xc @ convlin_W + b
        lg<0,2,0,0>(dim3(4,128), xc, wcl + w2, cvl_b + i*T2,
                  nullptr, xco, nullptr, nullptr, nullptr, 512, 512);
        // interleaved [Bm|Cm] GEMM with fused partial row-dot -> cbp
        lg<0,32,0,0>(dim3(4,128), xco, wf23 + w2, b23 + i*T2,
                  cbp, nullptr, nullptr, nullptr, nullptr, 512, 512);
        k_cb2<<<ROWS/256,256>>>(cbp, cb);
        // g = silu(softplus(xco@fc1+b) * xco * cb) * xres (fused)
        lg<2,16,0,0>(dim3(4,128), xco, wf1 + w2, fc1_b + i*T2,
                  nullptr, gp, xco, xr32, cb, 512, 512);
        // x = g @ out_W + b
        if (i < 2){
            lg<0,1,0,0>(dim3(2,128), gp, wo + wo1, out_b + i*TT,
                      x32, nullptr, nullptr, nullptr, nullptr, 512, 256);
            k_rms<<<ROWS,256>>>(x32, norm_w + (i+1)*TT, xn);
        } else {
            lg<0,2,0,0>(dim3(2,128), gp, wo + wo1, out_b + i*TT,
                      nullptr, xp, nullptr, nullptr, nullptr, 512, 256);
        }
    }
    // dec = x @ proj_W + b
    lg<0,1,0,0>(dim3(2,128), xp, wp, proj_b,
              dec, nullptr, nullptr, nullptr, nullptr, 256, 256);
    k_out<<<(BB*TT*NV+255)/256,256>>>(dec, mean, stdv, (float*)d_out);
}

// round 17
// speedup vs baseline: 5.7933x; 1.0634x over previous
#include <cuda_runtime.h>
#include <cuda_fp16.h>
#include <math.h>
#include <stdint.h>

#define BB 32
#define TT 256
#define FF 512
#define MMK 4
#define NV 508
#define T2 512
#define ROWS (BB*FF)
typedef __half hf;
typedef long long ll;

// ---------------- scratch ----------------
__device__ float g_x32[ROWS*TT];
__device__ float g_xr32[ROWS*T2], g_dec[ROWS*TT];
__device__ float g_cb[ROWS], g_cbp[ROWS*4];
__device__ float g_mean[BB*NV], g_std[BB*NV];
__device__ float g_b23[3*T2];
__device__ hf g_xn [ROWS*TT];
__device__ hf g_xpT[ROWS*T2];
__device__ hf g_xc [ROWS*T2];
__device__ hf g_xco[ROWS*T2];
__device__ hf g_g  [ROWS*T2];
__device__ hf g_x  [ROWS*TT];
__device__ hf w_inp[3*512*256];
__device__ hf w_cv [3*3*512*512];
__device__ hf w_cl [3*512*512];
__device__ hf w_f1 [3*512*512];
__device__ hf w_f23[3*512*512];
__device__ hf w_D  [3*512*256];
__device__ hf w_o  [3*256*512];
__device__ hf w_p  [256*256];

// ---------------- helpers ----------------
__device__ __forceinline__ float siluf(float x){ return x/(1.f+__expf(-x)); }
__device__ __forceinline__ float softplusf(float x){ return fmaxf(x,0.f)+log1pf(__expf(-fabsf(x))); }
__device__ __forceinline__ void st_h2(hf* C, ll off, float v0, float v1){
    *(__half2*)(C+off) = __floats2half2_rn(v0, v1);
}
__device__ __forceinline__ uint32_t s2u(const void* p){
    uint32_t a; asm("{.reg .u64 t; cvta.to.shared.u64 t,%1; cvt.u32.u64 %0,t;}":"=r"(a):"l"(p)); return a;
}
__device__ __forceinline__ void cp16(uint32_t s, const void* g, int sz){
    asm volatile("cp.async.cg.shared.global [%0], [%1], 16, %2;"::"r"(s),"l"(g),"r"(sz):"memory");
}
__device__ __forceinline__ void ldsm4(uint32_t* r, uint32_t a){
    asm volatile("ldmatrix.sync.aligned.m8n8.x4.shared.b16 {%0,%1,%2,%3}, [%4];"
        :"=r"(r[0]),"=r"(r[1]),"=r"(r[2]),"=r"(r[3]):"r"(a));
}
__device__ __forceinline__ void mma16816(float* d, const uint32_t* a, const uint32_t* b){
    asm volatile("mma.sync.aligned.m16n8k16.row.col.f32.f16.f16.f32 "
        "{%0,%1,%2,%3}, {%4,%5,%6,%7}, {%8,%9}, {%0,%1,%2,%3};"
        : "+f"(d[0]),"+f"(d[1]),"+f"(d[2]),"+f"(d[3])
        : "r"(a[0]),"r"(a[1]),"r"(a[2]),"r"(a[3]), "r"(b[0]),"r"(b[1]));
}
// 128B-row SW128 swizzle (proven in R6/R8): conflict-free cp.async + ldmatrix.
#define SW(x) ((uint32_t)((x) ^ (((x)>>3)&0x70)))

// smem per stage: A[128][128B] + B[128][128B] = 32KB; 3 stages = 96KB -> 2 CTAs/SM.
#define ST_B  16384
#define ST_SZ 32768
#define SMEMSZ (3*ST_SZ)

// ---------------- 1-term fp16 HMMA GEMM, K-chunk 64, 3-stage pipeline ----------------
// Non-conv: D = A @ W^T. CONV: D = W @ B^T, B batched by z, bias per row;
// SHIFT adds 3-tap shifted accumulation over B rows.
// ACT: 0 none, 1 silu, 2 softplus.
// OUTM: 1 fp32 ; 2 fp16 ; 16 fused s6-combine ; 32 cb partial-dot (interleaved f23).
template<int ACT, int OUTM, int CONV, int SHIFT>
__global__ void __launch_bounds__(128, 2) tc_gemm(
    const hf* __restrict__ A, const hf* __restrict__ B,
    const float* __restrict__ bias,
    float* __restrict__ C32, hf* __restrict__ Cf,
    const hf* __restrict__ Xp, const float* __restrict__ Xf,
    const float* __restrict__ cbv,
    int Kd, int Nc)
{
    extern __shared__ __align__(1024) char sm[];
    uint32_t sb = s2u(sm);
    const int tid = threadIdx.x, lane = tid & 31, wid = tid >> 5;
    const int n0 = blockIdx.x*128, m0 = blockIdx.y*128, z = blockIdx.z;
    const int wm = (wid & 1) * 64, wn = (wid >> 1) * 64;
    const int NC = SHIFT ? 24 : (Kd >> 6);

    float acc[4][8][4];
    #pragma unroll
    for (int a = 0; a < 4; a++)
        #pragma unroll
        for (int b = 0; b < 8; b++)
            #pragma unroll
            for (int c = 0; c < 4; c++) acc[a][b][c] = 0.f;

    auto DO_LOAD = [&](int c){
        int tap = SHIFT ? (c >> 3) : 0;
        int k0  = (SHIFT ? (c & 7) : c) << 6;
        uint32_t st = sb + (c % 3) * ST_SZ;
        const hf* Aw = A + (SHIFT ? (ll)tap * 262144 : 0);
        #pragma unroll
        for (int rep = 0; rep < 8; rep++){
            int idx = rep * 128 + tid;            // 0..1023
            int row = idx >> 3, ck = idx & 7;
            uint32_t so = SW(row * 128 + ck * 16);
            cp16(st + so, Aw + (ll)(m0 + row) * Kd + k0 + ck * 8, 16);
            if (!CONV){
                cp16(st + ST_B + so, B + (ll)(n0 + row) * Kd + k0 + ck * 8, 16);
            } else {
                int lsrc = n0 + row + (SHIFT ? (tap - 1) : 0);
                int ok = (!SHIFT || (unsigned)lsrc < 512u) ? 16 : 0;
                cp16(st + ST_B + so, B + (ll)(z * 512 + lsrc) * Kd + k0 + ck * 8, ok);
            }
        }
        asm volatile("cp.async.commit_group;":::"memory");
    };

    const int arow = (lane & 7) + ((lane >> 3) & 1) * 8;
    const int acolq = ((lane >> 4) & 1) * 16;
    const int brow = (lane & 7) + ((lane >> 4) & 1) * 8;
    const int bcolq = ((lane >> 3) & 1) * 16;

    DO_LOAD(0);
    if (NC > 1) DO_LOAD(1);
    for (int c = 0; c < NC; c++){
        if (c + 1 < NC) asm volatile("cp.async.wait_group 1;":::"memory");
        else            asm volatile("cp.async.wait_group 0;":::"memory");
        __syncthreads();
        if (c + 2 < NC) DO_LOAD(c + 2);
        uint32_t st = sb + (c % 3) * ST_SZ;
        #pragma unroll
        for (int ks = 0; ks < 4; ks++){
            uint32_t a0[4][4];
            #pragma unroll
            for (int mt = 0; mt < 4; mt++)
                ldsm4(a0[mt], st + SW((wm + mt*16 + arow) * 128 + ks*32 + acolq));
            #pragma unroll
            for (int np = 0; np < 4; np++){
                uint32_t b0[4];
                ldsm4(b0, st + ST_B + SW((wn + np*16 + brow) * 128 + ks*32 + bcolq));
                #pragma unroll
                for (int half = 0; half < 2; half++)
                    #pragma unroll
                    for (int mt = 0; mt < 4; mt++)
                        mma16816(acc[mt][np*2 + half], a0[mt], &b0[half*2]);
            }
        }
    }
    __syncthreads();

    // ---------------- epilogue ----------------
    const int g = lane >> 2, qp = (lane & 3) * 2;

    if (OUTM == 32){
        // interleaved f23: (v0,v1) = (Bm_j, Cm_j); deterministic partial dot per CTA.
        float* part = (float*)sm;     // [128][2]
        #pragma unroll
        for (int mt = 0; mt < 4; mt++){
            #pragma unroll
            for (int half = 0; half < 2; half++){
                float s = 0.f;
                #pragma unroll
                for (int nt = 0; nt < 8; nt++){
                    int n = n0 + wn + nt*8 + qp;
                    float v0 = acc[mt][nt][half*2 + 0] + bias[n];
                    float v1 = acc[mt][nt][half*2 + 1] + bias[n+1];
                    s += v0 * v1;
                }
                s += __shfl_xor_sync(0xFFFFFFFFu, s, 1);
                s += __shfl_xor_sync(0xFFFFFFFFu, s, 2);
                if ((lane & 3) == 0)
                    part[(wm + mt*16 + g + half*8)*2 + (wid >> 1)] = s;
            }
        }
        __syncthreads();
        if (tid < 128)
            C32[((ll)m0 + tid)*4 + blockIdx.x] = part[tid*2] + part[tid*2 + 1];
        return;
    }

    #pragma unroll
    for (int mt = 0; mt < 4; mt++){
        #pragma unroll
        for (int half = 0; half < 2; half++){
            int m = m0 + wm + mt*16 + g + half*8;
            ll crow = CONV ? ((ll)z * 512 + m) : (ll)m;
            float bv = CONV ? bias[m] : 0.f;
            float cbrow = (OUTM == 16) ? cbv[crow] : 0.f;
            #pragma unroll
            for (int nt = 0; nt < 8; nt++){
                int n = n0 + wn + nt*8 + qp;
                float v0 = acc[mt][nt][half*2 + 0];
                float v1 = acc[mt][nt][half*2 + 1];
                if (CONV){ v0 += bv; v1 += bv; } else { v0 += bias[n]; v1 += bias[n+1]; }
                if (ACT == 1){ v0 = siluf(v0); v1 = siluf(v1); }
                if (ACT == 2){ v0 = softplusf(v0); v1 = softplusf(v1); }
                ll o = crow * Nc + n;
                if (OUTM == 16){
                    float xc0 = __half2float(Xp[o]);
                    float xc1 = __half2float(Xp[o+1]);
                    v0 = siluf(v0 * xc0 * cbrow) * Xf[o];
                    v1 = siluf(v1 * xc1 * cbrow) * Xf[o+1];
                    st_h2(Cf, o, v0, v1);
                } else if (OUTM == 2){
                    st_h2(Cf, o, v0, v1);
                } else {
                    C32[o] = v0; C32[o+1] = v1;
                }
            }
        }
    }
}

// ---------------- aux kernels ----------------
__global__ void k_norm(const float* __restrict__ xe, const float* __restrict__ xm,
                       const float* __restrict__ nw, hf* __restrict__ xn,
                       float* __restrict__ mean, float* __restrict__ stdv)
{
    extern __shared__ float tile[];                 // [32][257]
    __shared__ float ss[32][8], ss2[32][8];
    __shared__ float smu[32], sinv[32], ssc[32];
    int b = blockIdx.y, f0 = blockIdx.x*32;
    int tid = threadIdx.x, f = tid & 31, tg = tid >> 5;
    int gf = f0 + f;
    bool ismark = (gf >= NV);
    const float* src = ismark ? (xm + (ll)b*TT*MMK + (gf-NV)) : (xe + (ll)b*TT*NV + gf);
    int stride = ismark ? MMK : NV;
    float s = 0.f, s2 = 0.f;
    for (int t = tg; t < TT; t += 8){
        float v = src[(ll)t*stride];
        tile[f*257 + t] = v;
        s += v; s2 += v*v;
    }
    ss[f][tg] = s; ss2[f][tg] = s2;
    __syncthreads();
    if (tg == 0){
        float S = 0.f, S2 = 0.f;
        #pragma unroll
        for (int q = 0; q < 8; q++){ S += ss[f][q]; S2 += ss2[f][q]; }
        float mu, inv, m2;
        if (!ismark){
            mu = S * (1.f/256.f);
            float var = S2 * (1.f/256.f) - mu*mu;
            float sd = sqrtf(var + 1e-5f);
            inv = 1.f/sd;
            m2 = var / (var + 1e-5f);
            mean[b*NV+gf] = mu; stdv[b*NV+gf] = sd;
        } else { mu = 0.f; inv = 1.f; m2 = S2 * (1.f/256.f); }
        smu[f] = mu; sinv[f] = inv; ssc[f] = rsqrtf(m2 + 1e-5f);
    }
    __syncthreads();
    float wv = nw[tid];
    #pragma unroll 4
    for (int fr = 0; fr < 32; fr++){
        float v = (tile[fr*257 + tid] - smu[fr]) * sinv[fr] * ssc[fr] * wv;
        xn[((ll)b*512 + f0 + fr) * TT + tid] = __float2half(v);
    }
}

__global__ void k_rms(const float* __restrict__ x, const float* __restrict__ w,
                      hf* __restrict__ o)
{
    int r = blockIdx.x, t = threadIdx.x;
    __shared__ float red[256];
    float v = x[(ll)r*TT + t];
    red[t] = v*v; __syncthreads();
    for (int s = 128; s > 0; s >>= 1){ if (t < s) red[t] += red[t+s]; __syncthreads(); }
    float sc = rsqrtf(red[0]*(1.f/256.f) + 1e-5f);
    o[(ll)r*TT+t] = __float2half(v*sc*w[t]);
}

__global__ void k_cb2(const float* __restrict__ cbp, float* __restrict__ cb)
{
    int r = blockIdx.x*256 + threadIdx.x;
    if (r < ROWS)
        cb[r] = (cbp[r*4+0] + cbp[r*4+1]) + (cbp[r*4+2] + cbp[r*4+3]);
}

struct Seg { const float* src; hf* dst; int K, Nsrc, Ndst, colOff, colStride, nbat; };
struct PrepArgs { Seg s[8]; int cum[9]; };
__global__ void k_prep(PrepArgs a, int total)
{
    int i = blockIdx.x*256 + threadIdx.x;
    if (i >= total) return;
    int si = 0;
    #pragma unroll
    for (int q = 0; q < 7; q++) si += (i >= a.cum[q+1]);
    Seg sg = a.s[si];
    int r = i - a.cum[si];
    int per = sg.K * sg.Nsrc;
    int z = r / per, j = r % per;
    int k = j / sg.Nsrc, n = j % sg.Nsrc;
    ll d = (ll)z * sg.K * sg.Ndst + (ll)(sg.colOff + n * sg.colStride) * sg.K + k;
    sg.dst[d] = __float2half(sg.src[(ll)z * per + j]);
}

__global__ void k_cprep(const float* __restrict__ W, hf* __restrict__ dst)
{
    int j = blockIdx.x*256 + threadIdx.x;
    if (j >= 786432) return;
    ll zo = (ll)blockIdx.z * 786432;
    int tap = j % 3, ii = (j/3) % 512, o = j / 1536;
    ll d = zo + (ll)tap*262144 + (ll)o*512 + ii;
    dst[d] = __float2half(W[zo + j]);
}

__global__ void k_bias23(const float* __restrict__ b2, const float* __restrict__ b3,
                         float* __restrict__ b23)
{
    int i = blockIdx.x*256 + threadIdx.x;
    if (i >= 3*T2) return;
    int z = i / T2, n = i % T2;
    b23[i] = (n & 1) ? b3[z*256 + (n>>1)] : b2[z*256 + (n>>1)];
}

__global__ void k_out(const float* __restrict__ dec, const float* __restrict__ mean,
                      const float* __restrict__ stdv, float* __restrict__ out)
{
    int idx = blockIdx.x*256 + threadIdx.x;
    if (idx >= BB*TT*NV) return;
    int n = idx % NV, t = (idx/NV) % TT, b = idx/(NV*TT);
    out[idx] = dec[((ll)b*FF + n)*TT + t] * stdv[b*NV+n] + mean[b*NV+n];
}

// ---------------- launcher ----------------
#define GA(p, s) cudaGetSymbolAddress((void**)&p, s)

template<int ACT, int OUTM, int CONV, int SHIFT>
static void lg(dim3 grid, const hf* A, const hf* B, const float* bias,
               float* C32, hf* Cf, const hf* Xp, const float* Xf,
               const float* cbv, int Kd, int Nc)
{
    cudaFuncSetAttribute(tc_gemm<ACT,OUTM,CONV,SHIFT>, cudaFuncAttributeMaxDynamicSharedMemorySize, SMEMSZ);
    tc_gemm<ACT,OUTM,CONV,SHIFT><<<grid, 128, SMEMSZ>>>(A, B, bias, C32, Cf, Xp, Xf, cbv, Kd, Nc);
}

extern "C" void kernel_launch(void* const* d_in, const int* in_sizes, int n_in,
                              void* d_out, int out_size)
{
    const float* x_enc  = (const float*)d_in[0];
    const float* x_mark = (const float*)d_in[1];
    const float* norm_w = (const float*)d_in[4];
    const float* inp_W  = (const float*)d_in[5];
    const float* inp_b  = (const float*)d_in[6];
    const float* conv_W = (const float*)d_in[7];
    const float* conv_b = (const float*)d_in[8];
    const float* cvl_W  = (const float*)d_in[9];
    const float* cvl_b  = (const float*)d_in[10];
    const float* fc1_W  = (const float*)d_in[11];
    const float* fc1_b  = (const float*)d_in[12];
    const float* fc2_W  = (const float*)d_in[13];
    const float* fc2_b  = (const float*)d_in[14];
    const float* fc3_W  = (const float*)d_in[15];
    const float* fc3_b  = (const float*)d_in[16];
    const float* D_W    = (const float*)d_in[17];
    const float* D_b    = (const float*)d_in[18];
    const float* out_W  = (const float*)d_in[19];
    const float* out_b  = (const float*)d_in[20];
    const float* proj_W = (const float*)d_in[21];
    const float* proj_b = (const float*)d_in[22];

    float *x32,*xr32,*dec,*mean,*stdv,*cb,*cbp,*b23;
    GA(x32,g_x32); GA(xr32,g_xr32); GA(dec,g_dec); GA(mean,g_mean); GA(stdv,g_std);
    GA(cb,g_cb); GA(cbp,g_cbp); GA(b23,g_b23);
    hf *xn,*xpT,*xc,*xco,*gp,*xp;
    GA(xn,g_xn); GA(xpT,g_xpT); GA(xc,g_xc); GA(xco,g_xco); GA(gp,g_g); GA(xp,g_x);
    hf *winp,*wcv,*wcl,*wf1,*wf23,*wD,*wo,*wp;
    GA(winp,w_inp); GA(wcv,w_cv); GA(wcl,w_cl); GA(wf1,w_f1);
    GA(wf23,w_f23); GA(wD,w_D); GA(wo,w_o); GA(wp,w_p);

    PrepArgs pa;
    pa.s[0] = { inp_W,  winp, 256, 512, 512, 0, 1, 3 };
    pa.s[1] = { cvl_W,  wcl,  512, 512, 512, 0, 1, 3 };
    pa.s[2] = { fc1_W,  wf1,  512, 512, 512, 0, 1, 3 };
    pa.s[3] = { fc2_W,  wf23, 512, 256, 512, 0, 2, 3 };   // even cols
    pa.s[4] = { fc3_W,  wf23, 512, 256, 512, 1, 2, 3 };   // odd cols
    pa.s[5] = { D_W,    wD,   256, 512, 512, 0, 1, 3 };
    pa.s[6] = { out_W,  wo,   512, 256, 256, 0, 1, 3 };
    pa.s[7] = { proj_W, wp,   256, 256, 256, 0, 1, 1 };
    pa.cum[0] = 0;
    for (int q = 0; q < 8; q++)
        pa.cum[q+1] = pa.cum[q] + pa.s[q].K * pa.s[q].Nsrc * pa.s[q].nbat;
    int total = pa.cum[8];
    k_prep<<<(total + 255)/256, 256>>>(pa, total);
    k_cprep<<<dim3((786432+255)/256,1,3),256>>>(conv_W, wcv);
    k_bias23<<<(3*T2+255)/256,256>>>(fc2_b, fc3_b, b23);

    cudaFuncSetAttribute(k_norm, cudaFuncAttributeMaxDynamicSharedMemorySize, 32*257*4);
    k_norm<<<dim3(16,BB),256,32*257*4>>>(x_enc, x_mark, norm_w, xn, mean, stdv);

    for (int i = 0; i < 3; i++){
        ll w2 = (ll)i*512*512, w1 = (ll)i*256*512, wc = (ll)i*786432, wo1 = (ll)i*512*256;
        // xpT[(b,l)][f] = W^T @ xn_b^T + b[l]  (batched, no shift)
        lg<0,2,1,0>(dim3(4,4,BB), winp + w1, xn, inp_b + i*T2,
                  nullptr, xpT, nullptr, nullptr, nullptr, 256, 512);
        // xres = silu(xn @ D_W + b) -> fp32
        lg<1,1,0,0>(dim3(4,128), xn, wD + w1, D_b + i*T2,
                  xr32, nullptr, nullptr, nullptr, nullptr, 256, 512);
        // xc = silu(conv1d(xp) + conv_b)  (3-tap shifted batched)
        lg<1,2,1,1>(dim3(4,4,BB), wcv + wc, xpT, conv_b + i*FF,
                  nullptr, xc, nullptr, nullptr, nullptr, 512, 512);
        // xco = xc @ convlin_W + b
        lg<0,2,0,0>(dim3(4,128), xc, wcl + w2, cvl_b + i*T2,
                  nullptr, xco, nullptr, nullptr, nullptr, 512, 512);
        // interleaved [Bm|Cm] GEMM with fused partial row-dot -> cbp
        lg<0,32,0,0>(dim3(4,128), xco, wf23 + w2, b23 + i*T2,
                  cbp, nullptr, nullptr, nullptr, nullptr, 512, 512);
        k_cb2<<<ROWS/256,256>>>(cbp, cb);
        // g = silu(softplus(xco@fc1+b) * xco * cb) * xres (fused)
        lg<2,16,0,0>(dim3(4,128), xco, wf1 + w2, fc1_b + i*T2,
                  nullptr, gp, xco, xr32, cb, 512, 512);
        // x = g @ out_W + b
        if (i < 2){
            lg<0,1,0,0>(dim3(2,128), gp, wo + wo1, out_b + i*TT,
                      x32, nullptr, nullptr, nullptr, nullptr, 512, 256);
            k_rms<<<ROWS,256>>>(x32, norm_w + (i+1)*TT, xn);
        } else {
            lg<0,2,0,0>(dim3(2,128), gp, wo + wo1, out_b + i*TT,
                      nullptr, xp, nullptr, nullptr, nullptr, 512, 256);
        }
    }
    // dec = x @ proj_W + b
    lg<0,1,0,0>(dim3(2,128), xp, wp, proj_b,
              dec, nullptr, nullptr, nullptr, nullptr, 256, 256);
    k_out<<<(BB*TT*NV+255)/256,256>>>(dec, mean, stdv, (float*)d_out);
}